// round 6
// baseline (speedup 1.0000x reference)
#include <cuda_runtime.h>
#include <math.h>
#include <stdint.h>

#define BB 4
#define INCH 256
#define NPTS 2048
#define NP1 2049
#define DIM 256
#define KNN 16
#define PHID 64
#define HID 1024
#define NCOL (BB*NP1*KNN)   /* 131136 */
#define NK   (BB*NPTS*KNN)  /* 131072 */
#define NCH  8
#define EPSV 1e-5f
#define GSMEM128 61440      /* 3 stages * (128+128)*20 floats * 4B */
#define GSMEM256 92160      /* 3 stages * (128+256)*20 floats * 4B */

// ---------------- scratch ----------------------------------------------------
__device__ float g_xT[BB*NPTS*INCH];
__device__ float g_hx[BB*NP1*DIM];
__device__ float g_q [BB*NP1*DIM];
__device__ float g_k [BB*NP1*DIM];
__device__ float g_v [BB*NP1*DIM];
__device__ int   g_idx[BB*NPTS*KNN];
__device__ float g_pd[BB*NPTS*NCH*KNN];
__device__ int   g_pi[BB*NPTS*NCH*KNN];
__device__ float g_ph [NK*PHID];
__device__ float g_pe [(long)NK*DIM];
__device__ float g_hid[(long)NCOL*HID];
__device__ float g_agg[BB*NP1*DIM];
__device__ float g_y  [BB*NP1*DIM];
__device__ float g_w1q[BB*NP1*HID];
__device__ float g_w1k[BB*NPTS*HID];
__device__ float g_Wc [HID*PHID];
__device__ float g_sA[HID], g_tA[HID], g_w1pb[HID];
__device__ float g_sP[PHID], g_tP[PHID];
// rounded weights
__device__ float g_rWs[DIM*INCH];
__device__ float g_rWq[DIM*DIM];
__device__ float g_rWk[DIM*DIM];
__device__ float g_rWv[DIM*DIM];
__device__ float g_rW1[HID*DIM];
__device__ float g_rP2[DIM*PHID];
__device__ float g_rW2[DIM*HID];
__device__ float g_rWe[INCH*DIM];

// ---------------- helpers ----------------------------------------------------
__device__ __forceinline__ float rtf(float x){
    uint32_t r; asm("cvt.rna.tf32.f32 %0, %1;" : "=r"(r) : "f"(x));
    return __uint_as_float(r);
}
__device__ __forceinline__ void mma_tf32(float&c0,float&c1,float&c2,float&c3,
   uint32_t a0,uint32_t a1,uint32_t a2,uint32_t a3,uint32_t b0,uint32_t b1){
  asm volatile("mma.sync.aligned.m16n8k8.row.col.f32.tf32.tf32.f32 "
    "{%0,%1,%2,%3}, {%4,%5,%6,%7}, {%8,%9}, {%0,%1,%2,%3};\n"
    : "+f"(c0),"+f"(c1),"+f"(c2),"+f"(c3)
    : "r"(a0),"r"(a1),"r"(a2),"r"(a3),"r"(b0),"r"(b1));
}
__device__ __forceinline__ void cp16(uint32_t dst, const void* src){
    asm volatile("cp.async.cg.shared.global [%0], [%1], 16;" :: "r"(dst), "l"(src));
}
__device__ __forceinline__ void cpcommit(){ asm volatile("cp.async.commit_group;"); }
__device__ __forceinline__ void cpwait1(){ asm volatile("cp.async.wait_group 1;"); }

// ---------------- small prep kernels ----------------------------------------
__global__ void roundcpy_kernel(const float* __restrict__ src, float* __restrict__ dst){
    int i = blockIdx.x*256 + threadIdx.x;
    dst[i] = rtf(src[i]);
}

__global__ void transpose_x_kernel(const float* __restrict__ x){
    __shared__ float tile[32][33];
    int b = blockIdx.z;
    int i0 = blockIdx.y*32, n0 = blockIdx.x*32;
    int tx = threadIdx.x, ty = threadIdx.y;
    tile[ty][tx] = x[(b*INCH + (i0+ty))*NPTS + n0+tx];
    __syncthreads();
    g_xT[(b*NPTS + (n0+ty))*INCH + i0+tx] = rtf(tile[tx][ty]);
}

__global__ void prep_kernel(const float* __restrict__ ag, const float* __restrict__ abeta,
                            const float* __restrict__ am, const float* __restrict__ av,
                            const float* __restrict__ ab1,
                            const float* __restrict__ pg, const float* __restrict__ pbeta,
                            const float* __restrict__ pm, const float* __restrict__ pv,
                            const float* __restrict__ pb1,
                            const float* __restrict__ W1, const float* __restrict__ pb2){
    int t = threadIdx.x;
    if (t < HID){
        float s = ag[t] / sqrtf(av[t] + EPSV);
        g_sA[t] = s;
        g_tA[t] = abeta[t] - am[t]*s + ab1[t]*s;
        float acc = 0.f;
        for (int c = 0; c < DIM; c++) acc += W1[t*DIM+c]*pb2[c];
        g_w1pb[t] = acc;
    }
    if (t < PHID){
        float s = pg[t] / sqrtf(pv[t] + EPSV);
        g_sP[t] = s;
        g_tP[t] = pbeta[t] - pm[t]*s + pb1[t]*s;
    }
}

__global__ void wc_kernel(const float* __restrict__ W1, const float* __restrict__ W2p){
    int h = blockIdx.x, p = threadIdx.x;
    float s = 0.f;
    for (int c = 0; c < DIM; c++) s += W1[h*DIM+c]*W2p[c*PHID+p];
    g_Wc[h*PHID+p] = rtf(s);
}

__global__ void init_cls_kernel(const float* __restrict__ cls){
    g_hx[(blockIdx.x*NP1)*DIM + threadIdx.x] = rtf(cls[threadIdx.x]);
}

__global__ void addpos_kernel(const float* __restrict__ pos_emb){
    int b = blockIdx.x, c = threadIdx.x;
    g_q[(b*NP1)*DIM + c] = rtf(g_q[(b*NP1)*DIM + c] + pos_emb[c]);
    g_v[(b*NP1)*DIM + c] += pos_emb[c];
}

// ---------------- KNN (chunked) ---------------------------------------------
__global__ __launch_bounds__(256) void knn_part_kernel(const float* __restrict__ pos){
    __shared__ float sx[256], sy[256], sz[256];
    int b = blockIdx.y, ch = blockIdx.z;
    const float* pb = pos + (size_t)b*3*NPTS;
    int j0 = ch*256;
    int t = threadIdx.x;
    sx[t] = pb[j0+t]; sy[t] = pb[NPTS+j0+t]; sz[t] = pb[2*NPTS+j0+t];
    __syncthreads();
    int qi = blockIdx.x*256 + t;
    float qx = pb[qi], qy = pb[NPTS+qi], qz = pb[2*NPTS+qi];
    float bd[KNN]; int bi[KNN];
#pragma unroll
    for (int i = 0; i < KNN; i++){ bd[i] = 3.4e38f; bi[i] = 0; }
    float maxv = 3.4e38f; int maxp = 0;
    for (int j = 0; j < 256; j++){
        float dx = qx - sx[j], dy = qy - sy[j], dz = qz - sz[j];
        float d = dx*dx + dy*dy + dz*dz;
        if (d < maxv){
            bd[maxp] = d; bi[maxp] = j0 + j;
            maxv = bd[0]; maxp = 0;
#pragma unroll
            for (int i = 1; i < KNN; i++)
                if (bd[i] > maxv){ maxv = bd[i]; maxp = i; }
        }
    }
    long base = ((long)(b*NPTS + qi)*NCH + ch)*KNN;
#pragma unroll
    for (int i = 0; i < KNN; i++){ g_pd[base+i] = bd[i]; g_pi[base+i] = bi[i]; }
}

__global__ __launch_bounds__(256) void knn_merge_kernel(){
    int b = blockIdx.y;
    int qi = blockIdx.x*256 + threadIdx.x;
    long base = (long)(b*NPTS + qi)*NCH*KNN;
    float bd[KNN]; int bi[KNN];
#pragma unroll
    for (int i = 0; i < KNN; i++){ bd[i] = 3.4e38f; bi[i] = 0; }
    float maxv = 3.4e38f; int maxp = 0;
    for (int j = 0; j < NCH*KNN; j++){
        float d = g_pd[base+j];
        if (d < maxv){
            bd[maxp] = d; bi[maxp] = g_pi[base+j];
            maxv = bd[0]; maxp = 0;
#pragma unroll
            for (int i = 1; i < KNN; i++)
                if (bd[i] > maxv){ maxv = bd[i]; maxp = i; }
        }
    }
    int ob = (b*NPTS + qi)*KNN;
#pragma unroll
    for (int i = 0; i < KNN; i++) g_idx[ob+i] = bi[i];
}

// ---------------- pos-MLP hidden --------------------------------------------
__global__ __launch_bounds__(256) void pos_hidden_kernel(const float* __restrict__ pos,
                                                         const float* __restrict__ pw1){
    int b = blockIdx.y, n = blockIdx.x;
    __shared__ float prx[KNN], pry[KNN], prz[KNN];
    int t = threadIdx.x;
    const float* pb = pos + (size_t)b*3*NPTS;
    if (t < KNN){
        int m = g_idx[(b*NPTS+n)*KNN + t];
        prx[t] = pb[n]        - pb[m];
        pry[t] = pb[NPTS+n]   - pb[NPTS+m];
        prz[t] = pb[2*NPTS+n] - pb[2*NPTS+m];
    }
    __syncthreads();
    for (int e = t; e < KNN*PHID; e += 256){
        int k = e >> 6, hh = e & 63;
        float z = pw1[hh*3+0]*prx[k] + pw1[hh*3+1]*pry[k] + pw1[hh*3+2]*prz[k];
        z = z*g_sP[hh] + g_tP[hh];
        g_ph[((b*NPTS+n)*KNN + k)*PHID + hh] = rtf(fmaxf(z, 0.f));
    }
}

// ---------------- tf32 GEMM, cp.async 3-stage, stride-20 smem, NT=128/256 ----
// C[M][N] = A[M][K] * Bw[N][K]^T
// EPI 0: C = acc + bias[n]
// EPI 1: C = rtf(acc + bias[n])
// EPI 2: folded attn-hidden epilogue -> g_hid (rounded)
// EPI 3: C = acc
// EPI 4: fused softmax(k)+aggregate -> g_agg (rounded)
template<int EPI, int NT>
__global__ __launch_bounds__(256, (NT==128)?2:1) void gemm2(const float* __restrict__ A,
        const float* __restrict__ Bw, float* __restrict__ C,
        int M, int N, int K, const float* __restrict__ bias,
        long strideAb, long strideCb){
    constexpr int SROWS = 128 + NT;        // rows per stage (A then B)
    constexpr int SS    = SROWS * 20;      // floats per stage
    constexpr int JN    = NT / 32;         // j tiles per warp
    constexpr int LCNT  = SROWS / 64;      // prefetch iterations per thread
    extern __shared__ __align__(16) float sm[];
    A += (long)blockIdx.z*strideAb;
    C += (long)blockIdx.z*strideCb;
    const int t = threadIdx.x, lane = t&31, w = t>>5;
    const int wm = w>>2, wn = w&3;
    const int m0 = blockIdx.x*128, n0 = blockIdx.y*NT;
    const uint32_t smb = (uint32_t)__cvta_generic_to_shared(sm);
    float acc[4][JN][4];
#pragma unroll
    for (int i=0;i<4;i++)
#pragma unroll
      for (int j=0;j<JN;j++)
#pragma unroll
        for (int c=0;c<4;c++) acc[i][j][c] = 0.f;

    const int nIter = K >> 4;
    auto prefetch = [&](int st, int kt){
#pragma unroll
        for (int l=0;l<LCNT;l++){
            int g = t + (l<<8);
            int row = g>>2, kq = (g&3)<<2;
            if (row < 128){
                int arow = m0 + row; if (arow >= M) arow = M - 1;   // clamp: in-bounds
                uint32_t d = smb + (uint32_t)((st*SS + row*20 + kq)<<2);
                cp16(d, A + (long)arow*K + (kt<<4) + kq);
            } else {
                int brow = row - 128;
                uint32_t d = smb + (uint32_t)((st*SS + 2560 + brow*20 + kq)<<2);
                cp16(d, Bw + (long)(n0+brow)*K + (kt<<4) + kq);
            }
        }
        cpcommit();
    };
    prefetch(0, 0);
    prefetch(1, 1);

    for (int it = 0; it < nIter; ++it){
        cpwait1();
        __syncthreads();
        if (it+2 < nIter) prefetch((it+2)%3, it+2);
        else cpcommit();
        const float* sA = sm + (it%3)*SS;
        const float* sB = sA + 2560;
#pragma unroll
        for (int k8=0;k8<2;k8++){
            int kb = k8*8 + (lane&3);
            uint32_t af[4][4]; uint32_t bf[JN][2];
#pragma unroll
            for (int i=0;i<4;i++){
                const float* p = sA + (wm*64 + i*16 + (lane>>2))*20 + kb;
                af[i][0]=__float_as_uint(p[0]);
                af[i][1]=__float_as_uint(p[160]);
                af[i][2]=__float_as_uint(p[4]);
                af[i][3]=__float_as_uint(p[164]);
            }
#pragma unroll
            for (int j=0;j<JN;j++){
                const float* p = sB + (wn*(NT/4) + j*8 + (lane>>2))*20 + kb;
                bf[j][0]=__float_as_uint(p[0]);
                bf[j][1]=__float_as_uint(p[4]);
            }
#pragma unroll
            for (int i=0;i<4;i++)
#pragma unroll
                for (int j=0;j<JN;j++)
                    mma_tf32(acc[i][j][0],acc[i][j][1],acc[i][j][2],acc[i][j][3],
                             af[i][0],af[i][1],af[i][2],af[i][3], bf[j][0],bf[j][1]);
        }
        __syncthreads();
    }

    const int r0 = lane >> 2, cq = (lane & 3) << 1;
    if (EPI == 4){
#pragma unroll
        for (int i=0;i<4;i++){
            int mrow = m0 + wm*64 + i*16;
            if (mrow >= M) continue;
            int colidx = mrow >> 4;            // b*NP1 + nn
            int b  = colidx / NP1;
            int nn = colidx - b*NP1;
            long pebase = (nn > 0) ? (long)((b*NPTS + nn-1)*KNN)*DIM : 0;
            int kk0 = r0;                      // k for half 0; half 1 = kk0+8
#pragma unroll
            for (int j=0;j<JN;j++){
                int c0 = n0 + wn*(NT/4) + j*8 + cq;
                float outv[2];
#pragma unroll
                for (int q=0;q<2;q++){
                    float l0 = acc[i][j][q], l1 = acc[i][j][2+q];
                    float mx = fmaxf(l0, l1);
                    mx = fmaxf(mx, __shfl_xor_sync(0xffffffffu, mx, 4));
                    mx = fmaxf(mx, __shfl_xor_sync(0xffffffffu, mx, 8));
                    mx = fmaxf(mx, __shfl_xor_sync(0xffffffffu, mx, 16));
                    float e0 = expf(l0 - mx), e1 = expf(l1 - mx);
                    float pv0 = 0.f, pv1 = 0.f;
                    if (nn > 0){
                        pv0 = g_pe[pebase + (long)kk0*DIM + c0 + q];
                        pv1 = g_pe[pebase + (long)(kk0+8)*DIM + c0 + q];
                    }
                    float s  = e0 + e1;
                    float ts = e0*pv0 + e1*pv1;
                    s  += __shfl_xor_sync(0xffffffffu, s, 4);
                    ts += __shfl_xor_sync(0xffffffffu, ts, 4);
                    s  += __shfl_xor_sync(0xffffffffu, s, 8);
                    ts += __shfl_xor_sync(0xffffffffu, ts, 8);
                    s  += __shfl_xor_sync(0xffffffffu, s, 16);
                    ts += __shfl_xor_sync(0xffffffffu, ts, 16);
                    float vv = g_v[(long)colidx*DIM + c0 + q];
                    outv[q] = rtf(vv + ts / s);
                }
                if (r0 == 0){
                    float2 o = make_float2(outv[0], outv[1]);
                    *(float2*)&g_agg[(long)colidx*DIM + c0] = o;
                }
            }
        }
        return;
    }
#pragma unroll
    for (int i=0;i<4;i++){
#pragma unroll
        for (int half=0; half<2; half++){
            int m = m0 + wm*64 + i*16 + r0 + half*8;
            if (m >= M) continue;
            if (EPI == 2){
                int b  = m >> 15;
                int n  = (m >> 4) & (NPTS-1);
                int kk = m & 15;
                int midx = g_idx[((b*NPTS)+n)*KNN + kk];
                const float* wq = g_w1q + (long)(b*NP1 + n + 1)*HID;
                const float* wk = g_w1k + (long)(b*NPTS + midx)*HID;
                float* dst = g_hid + (long)((b*NP1 + n + 1)*KNN + kk)*HID;
#pragma unroll
                for (int j=0;j<JN;j++){
                    int h = n0 + wn*(NT/4) + j*8 + cq;
                    float2 q2 = *(const float2*)&wq[h];
                    float2 k2 = *(const float2*)&wk[h];
                    float2 p2 = *(const float2*)&g_w1pb[h];
                    float2 s2 = *(const float2*)&g_sA[h];
                    float2 t2 = *(const float2*)&g_tA[h];
                    float2 o;
                    o.x = rtf(fmaxf((acc[i][j][half*2+0] + q2.x - k2.x + p2.x)*s2.x + t2.x, 0.f));
                    o.y = rtf(fmaxf((acc[i][j][half*2+1] + q2.y - k2.y + p2.y)*s2.y + t2.y, 0.f));
                    *(float2*)&dst[h] = o;
                }
            } else {
                float* crow = C + (long)m*N;
#pragma unroll
                for (int j=0;j<JN;j++){
                    int n = n0 + wn*(NT/4) + j*8 + cq;
                    float2 o;
                    if (EPI == 0){
                        float2 bv = *(const float2*)&bias[n];
                        o.x = acc[i][j][half*2+0] + bv.x;
                        o.y = acc[i][j][half*2+1] + bv.y;
                    } else if (EPI == 1){
                        float2 bv = *(const float2*)&bias[n];
                        o.x = rtf(acc[i][j][half*2+0] + bv.x);
                        o.y = rtf(acc[i][j][half*2+1] + bv.y);
                    } else {
                        o.x = acc[i][j][half*2+0];
                        o.y = acc[i][j][half*2+1];
                    }
                    *(float2*)&crow[n] = o;
                }
            }
        }
    }
}

// ---------------- cls hidden -------------------------------------------------
__global__ void cls_hidden_kernel(){
    int b = blockIdx.x >> 4, kk = blockIdx.x & 15;
    long col = (long)(b*NP1)*KNN + kk;
    for (int h = threadIdx.x; h < HID; h += 256){
        float v = rtf(fmaxf(g_w1q[(long)(b*NP1)*HID + h]*g_sA[h] + g_tA[h], 0.f));
        g_hid[col*HID + h] = v;
    }
}

// ---------------- finalize outputs ------------------------------------------
__global__ void finalize1_kernel(const float* __restrict__ x, float* __restrict__ out){
    int gid = blockIdx.x*256 + threadIdx.x;
    int n  = gid % NPTS;
    int ch = (gid / NPTS) % DIM;
    int b  = gid / (NPTS*DIM);
    out[gid] = g_y[((b*NP1) + (n+1))*DIM + ch] + x[gid];
}
__global__ void finalize2_kernel(float* __restrict__ out){
    int t = threadIdx.x;
    int b = t / DIM, ch = t % DIM;
    out[BB*DIM*NPTS + t] = g_y[(b*NP1)*DIM + ch];
}

// ---------------- launch -----------------------------------------------------
extern "C" void kernel_launch(void* const* d_in, const int* in_sizes, int n_in,
                              void* d_out, int out_size){
    const float* x        = (const float*)d_in[0];
    const float* pos      = (const float*)d_in[1];
    const float* W_start  = (const float*)d_in[2];
    const float* b_start  = (const float*)d_in[3];
    const float* W_key    = (const float*)d_in[4];
    const float* b_key    = (const float*)d_in[5];
    const float* W_query  = (const float*)d_in[6];
    const float* b_query  = (const float*)d_in[7];
    const float* W_value  = (const float*)d_in[8];
    const float* b_value  = (const float*)d_in[9];
    const float* pos_W1   = (const float*)d_in[10];
    const float* pos_b1   = (const float*)d_in[11];
    const float* pos_g    = (const float*)d_in[12];
    const float* pos_beta = (const float*)d_in[13];
    const float* pos_m    = (const float*)d_in[14];
    const float* pos_v    = (const float*)d_in[15];
    const float* pos_W2   = (const float*)d_in[16];
    const float* pos_b2   = (const float*)d_in[17];
    const float* attn_W1  = (const float*)d_in[18];
    const float* attn_b1  = (const float*)d_in[19];
    const float* attn_g   = (const float*)d_in[20];
    const float* attn_beta= (const float*)d_in[21];
    const float* attn_m   = (const float*)d_in[22];
    const float* attn_v   = (const float*)d_in[23];
    const float* attn_W2  = (const float*)d_in[24];
    const float* attn_b2  = (const float*)d_in[25];
    const float* W_end    = (const float*)d_in[26];
    const float* b_end    = (const float*)d_in[27];
    const float* pos_emb  = (const float*)d_in[28];
    const float* cls_tok  = (const float*)d_in[29];
    float* out = (float*)d_out;
    (void)attn_b2;

    float *pxT,*phx,*pq,*pk,*pv,*pph,*ppe,*phid,*pagg,*py,*pw1q,*pw1k,*pWc;
    float *prWs,*prWq,*prWk,*prWv,*prW1,*prP2,*prW2,*prWe;
    cudaGetSymbolAddress((void**)&pxT,  g_xT);
    cudaGetSymbolAddress((void**)&phx,  g_hx);
    cudaGetSymbolAddress((void**)&pq,   g_q);
    cudaGetSymbolAddress((void**)&pk,   g_k);
    cudaGetSymbolAddress((void**)&pv,   g_v);
    cudaGetSymbolAddress((void**)&pph,  g_ph);
    cudaGetSymbolAddress((void**)&ppe,  g_pe);
    cudaGetSymbolAddress((void**)&phid, g_hid);
    cudaGetSymbolAddress((void**)&pagg, g_agg);
    cudaGetSymbolAddress((void**)&py,   g_y);
    cudaGetSymbolAddress((void**)&pw1q, g_w1q);
    cudaGetSymbolAddress((void**)&pw1k, g_w1k);
    cudaGetSymbolAddress((void**)&pWc,  g_Wc);
    cudaGetSymbolAddress((void**)&prWs, g_rWs);
    cudaGetSymbolAddress((void**)&prWq, g_rWq);
    cudaGetSymbolAddress((void**)&prWk, g_rWk);
    cudaGetSymbolAddress((void**)&prWv, g_rWv);
    cudaGetSymbolAddress((void**)&prW1, g_rW1);
    cudaGetSymbolAddress((void**)&prP2, g_rP2);
    cudaGetSymbolAddress((void**)&prW2, g_rW2);
    cudaGetSymbolAddress((void**)&prWe, g_rWe);

    cudaFuncSetAttribute(gemm2<0,128>, cudaFuncAttributeMaxDynamicSharedMemorySize, GSMEM128);
    cudaFuncSetAttribute(gemm2<1,128>, cudaFuncAttributeMaxDynamicSharedMemorySize, GSMEM128);
    cudaFuncSetAttribute(gemm2<0,256>, cudaFuncAttributeMaxDynamicSharedMemorySize, GSMEM256);
    cudaFuncSetAttribute(gemm2<2,256>, cudaFuncAttributeMaxDynamicSharedMemorySize, GSMEM256);
    cudaFuncSetAttribute(gemm2<3,256>, cudaFuncAttributeMaxDynamicSharedMemorySize, GSMEM256);
    cudaFuncSetAttribute(gemm2<4,256>, cudaFuncAttributeMaxDynamicSharedMemorySize, GSMEM256);

    // prep + weight rounding
    transpose_x_kernel<<<dim3(NPTS/32, INCH/32, BB), dim3(32,32)>>>(x);
    prep_kernel<<<1,1024>>>(attn_g, attn_beta, attn_m, attn_v, attn_b1,
                            pos_g, pos_beta, pos_m, pos_v, pos_b1,
                            attn_W1, pos_b2);
    wc_kernel<<<HID, PHID>>>(attn_W1, pos_W2);
    roundcpy_kernel<<<(DIM*INCH)/256,256>>>(W_start, prWs);
    roundcpy_kernel<<<(DIM*DIM)/256,256>>>(W_query, prWq);
    roundcpy_kernel<<<(DIM*DIM)/256,256>>>(W_key,   prWk);
    roundcpy_kernel<<<(DIM*DIM)/256,256>>>(W_value, prWv);
    roundcpy_kernel<<<(HID*DIM)/256,256>>>(attn_W1, prW1);
    roundcpy_kernel<<<(DIM*PHID)/256,256>>>(pos_W2, prP2);
    roundcpy_kernel<<<(DIM*HID)/256,256>>>(attn_W2, prW2);
    roundcpy_kernel<<<(INCH*DIM)/256,256>>>(W_end,  prWe);
    init_cls_kernel<<<BB, DIM>>>(cls_tok);
    knn_part_kernel<<<dim3(NPTS/256, BB, NCH), 256>>>(pos);
    knn_merge_kernel<<<dim3(NPTS/256, BB), 256>>>();

    // hx[1:] = W_start @ x + b
    gemm2<1,128><<<dim3(NPTS/128, DIM/128, BB), 256, GSMEM128>>>(
        pxT, prWs, phx + DIM, NPTS, DIM, INCH, b_start,
        (long)NPTS*INCH, (long)NP1*DIM);

    // q,k,v
    gemm2<1,128><<<dim3((BB*NP1+127)/128, DIM/128, 1), 256, GSMEM128>>>(
        phx, prWq, pq, BB*NP1, DIM, DIM, b_query, 0, 0);
    gemm2<1,128><<<dim3((BB*NP1+127)/128, DIM/128, 1), 256, GSMEM128>>>(
        phx, prWk, pk, BB*NP1, DIM, DIM, b_key, 0, 0);
    gemm2<0,128><<<dim3((BB*NP1+127)/128, DIM/128, 1), 256, GSMEM128>>>(
        phx, prWv, pv, BB*NP1, DIM, DIM, b_value, 0, 0);

    addpos_kernel<<<BB, DIM>>>(pos_emb);

    // w1q (all rows, cls row includes pos_emb), w1k (rows 1..)
    gemm2<3,256><<<dim3((BB*NP1+127)/128, HID/256, 1), 256, GSMEM256>>>(
        pq, prW1, pw1q, BB*NP1, HID, DIM, nullptr, 0, 0);
    gemm2<3,256><<<dim3(NPTS/128, HID/256, BB), 256, GSMEM256>>>(
        pk + DIM, prW1, pw1k, NPTS, HID, DIM, nullptr,
        (long)NP1*DIM, (long)NPTS*HID);

    // pos-MLP
    pos_hidden_kernel<<<dim3(NPTS, BB), 256>>>(pos, pos_W1);
    gemm2<0,256><<<dim3(NK/128, DIM/256, 1), 256, GSMEM256>>>(
        pph, prP2, ppe, NK, DIM, PHID, pos_b2, 0, 0);

    // folded attn hidden
    gemm2<2,256><<<dim3(NK/128, HID/256, 1), 256, GSMEM256>>>(
        pph, pWc, nullptr, NK, HID, PHID, nullptr, 0, 0);
    cls_hidden_kernel<<<BB*KNN, 256>>>();

    // logits + fused softmax/aggregate -> g_agg
    gemm2<4,256><<<dim3((NCOL+127)/128, DIM/256, 1), 256, GSMEM256>>>(
        phid, prW2, nullptr, NCOL, DIM, HID, nullptr, 0, 0);

    // y = W_end @ agg + b
    gemm2<0,128><<<dim3((BB*NP1+127)/128, DIM/128, 1), 256, GSMEM128>>>(
        pagg, prWe, py, BB*NP1, DIM, DIM, b_end, 0, 0);

    finalize1_kernel<<<(BB*DIM*NPTS)/256, 256>>>(x, out);
    finalize2_kernel<<<1, BB*DIM>>>(out);
}

// round 7
// speedup vs baseline: 1.2170x; 1.2170x over previous
#include <cuda_runtime.h>
#include <math.h>
#include <stdint.h>

#define BB 4
#define INCH 256
#define NPTS 2048
#define NP1 2049
#define DIM 256
#define KNN 16
#define PHID 64
#define HID 1024
#define NCOL (BB*NP1*KNN)   /* 131136 */
#define NK   (BB*NPTS*KNN)  /* 131072 */
#define NCH  8
#define EPSV 1e-5f
#define GSMEM 81920         /* 4 stages * (128+128)*20 floats * 4B */

// ---------------- scratch ----------------------------------------------------
__device__ float g_xT[BB*NPTS*INCH];
__device__ float g_hx[BB*NP1*DIM];
__device__ float g_q [BB*NP1*DIM];
__device__ float g_k [BB*NP1*DIM];
__device__ float g_v [BB*NP1*DIM];
__device__ int   g_idx[BB*NPTS*KNN];
__device__ float g_pd[BB*NPTS*NCH*KNN];
__device__ int   g_pi[BB*NPTS*NCH*KNN];
__device__ float g_ph [NK*PHID];
__device__ float g_pe [(long)NK*DIM];
__device__ float g_hid[(long)NCOL*HID];
__device__ float g_agg[BB*NP1*DIM];
__device__ float g_y  [BB*NP1*DIM];
__device__ float g_w1q[BB*NP1*HID];
__device__ float g_w1k[BB*NPTS*HID];
__device__ float g_Wc [HID*PHID];
__device__ float g_sA[HID], g_tA[HID], g_w1pb[HID];
__device__ float g_sP[PHID], g_tP[PHID];
// rounded weights
__device__ float g_rWs[DIM*INCH];
__device__ float g_rWq[DIM*DIM];
__device__ float g_rWk[DIM*DIM];
__device__ float g_rWv[DIM*DIM];
__device__ float g_rW1[HID*DIM];
__device__ float g_rP2[DIM*PHID];
__device__ float g_rW2[DIM*HID];
__device__ float g_rWe[INCH*DIM];

// ---------------- helpers ----------------------------------------------------
__device__ __forceinline__ float rtf(float x){
    uint32_t r; asm("cvt.rna.tf32.f32 %0, %1;" : "=r"(r) : "f"(x));
    return __uint_as_float(r);
}
__device__ __forceinline__ void mma_tf32(float&c0,float&c1,float&c2,float&c3,
   uint32_t a0,uint32_t a1,uint32_t a2,uint32_t a3,uint32_t b0,uint32_t b1){
  asm volatile("mma.sync.aligned.m16n8k8.row.col.f32.tf32.tf32.f32 "
    "{%0,%1,%2,%3}, {%4,%5,%6,%7}, {%8,%9}, {%0,%1,%2,%3};\n"
    : "+f"(c0),"+f"(c1),"+f"(c2),"+f"(c3)
    : "r"(a0),"r"(a1),"r"(a2),"r"(a3),"r"(b0),"r"(b1));
}
__device__ __forceinline__ void cp16(uint32_t dst, const void* src){
    asm volatile("cp.async.cg.shared.global [%0], [%1], 16;" :: "r"(dst), "l"(src));
}
__device__ __forceinline__ void cpcommit(){ asm volatile("cp.async.commit_group;"); }
__device__ __forceinline__ void cpwait2(){ asm volatile("cp.async.wait_group 2;"); }
__device__ __forceinline__ void cpwait0(){ asm volatile("cp.async.wait_group 0;"); }

// ---------------- merged weight rounding ------------------------------------
struct RCArgs {
    const float* s[8];
    float* d[8];
    int end[8];       // cumulative end offsets
};
__global__ void roundcpy_all_kernel(RCArgs a){
    int i = blockIdx.x*256 + threadIdx.x;
    int seg = 0;
#pragma unroll
    for (int k = 0; k < 8; k++) if (i >= a.end[k]) seg = k+1;
    if (seg >= 8) return;
    int base = seg ? a.end[seg-1] : 0;
    a.d[seg][i-base] = rtf(a.s[seg][i-base]);
}

// ---------------- small prep kernels ----------------------------------------
__global__ void transpose_x_kernel(const float* __restrict__ x){
    __shared__ float tile[32][33];
    int b = blockIdx.z;
    int i0 = blockIdx.y*32, n0 = blockIdx.x*32;
    int tx = threadIdx.x, ty = threadIdx.y;
    tile[ty][tx] = x[(b*INCH + (i0+ty))*NPTS + n0+tx];
    __syncthreads();
    g_xT[(b*NPTS + (n0+ty))*INCH + i0+tx] = rtf(tile[tx][ty]);
}

__global__ void prep_kernel(const float* __restrict__ ag, const float* __restrict__ abeta,
                            const float* __restrict__ am, const float* __restrict__ av,
                            const float* __restrict__ ab1,
                            const float* __restrict__ pg, const float* __restrict__ pbeta,
                            const float* __restrict__ pm, const float* __restrict__ pv,
                            const float* __restrict__ pb1,
                            const float* __restrict__ W1, const float* __restrict__ pb2){
    int t = threadIdx.x;
    if (t < HID){
        float s = ag[t] / sqrtf(av[t] + EPSV);
        g_sA[t] = s;
        g_tA[t] = abeta[t] - am[t]*s + ab1[t]*s;
        float acc = 0.f;
        for (int c = 0; c < DIM; c++) acc += W1[t*DIM+c]*pb2[c];
        g_w1pb[t] = acc;
    }
    if (t < PHID){
        float s = pg[t] / sqrtf(pv[t] + EPSV);
        g_sP[t] = s;
        g_tP[t] = pbeta[t] - pm[t]*s + pb1[t]*s;
    }
}

__global__ void wc_kernel(const float* __restrict__ W1, const float* __restrict__ W2p){
    int h = blockIdx.x, p = threadIdx.x;
    float s = 0.f;
    for (int c = 0; c < DIM; c++) s += W1[h*DIM+c]*W2p[c*PHID+p];
    g_Wc[h*PHID+p] = rtf(s);
}

__global__ void init_cls_kernel(const float* __restrict__ cls){
    g_hx[(blockIdx.x*NP1)*DIM + threadIdx.x] = rtf(cls[threadIdx.x]);
}

__global__ void addpos_kernel(const float* __restrict__ pos_emb){
    int b = blockIdx.x, c = threadIdx.x;
    g_q[(b*NP1)*DIM + c] = rtf(g_q[(b*NP1)*DIM + c] + pos_emb[c]);
    g_v[(b*NP1)*DIM + c] += pos_emb[c];
}

// ---------------- KNN (chunked) ---------------------------------------------
__global__ __launch_bounds__(256) void knn_part_kernel(const float* __restrict__ pos){
    __shared__ float sx[256], sy[256], sz[256];
    int b = blockIdx.y, ch = blockIdx.z;
    const float* pb = pos + (size_t)b*3*NPTS;
    int j0 = ch*256;
    int t = threadIdx.x;
    sx[t] = pb[j0+t]; sy[t] = pb[NPTS+j0+t]; sz[t] = pb[2*NPTS+j0+t];
    __syncthreads();
    int qi = blockIdx.x*256 + t;
    float qx = pb[qi], qy = pb[NPTS+qi], qz = pb[2*NPTS+qi];
    float bd[KNN]; int bi[KNN];
#pragma unroll
    for (int i = 0; i < KNN; i++){ bd[i] = 3.4e38f; bi[i] = 0; }
    float maxv = 3.4e38f; int maxp = 0;
    for (int j = 0; j < 256; j++){
        float dx = qx - sx[j], dy = qy - sy[j], dz = qz - sz[j];
        float d = dx*dx + dy*dy + dz*dz;
        if (d < maxv){
            bd[maxp] = d; bi[maxp] = j0 + j;
            maxv = bd[0]; maxp = 0;
#pragma unroll
            for (int i = 1; i < KNN; i++)
                if (bd[i] > maxv){ maxv = bd[i]; maxp = i; }
        }
    }
    long base = ((long)(b*NPTS + qi)*NCH + ch)*KNN;
#pragma unroll
    for (int i = 0; i < KNN; i++){ g_pd[base+i] = bd[i]; g_pi[base+i] = bi[i]; }
}

__global__ __launch_bounds__(256) void knn_merge_kernel(){
    int b = blockIdx.y;
    int qi = blockIdx.x*256 + threadIdx.x;
    long base = (long)(b*NPTS + qi)*NCH*KNN;
    float bd[KNN]; int bi[KNN];
#pragma unroll
    for (int i = 0; i < KNN; i++){ bd[i] = 3.4e38f; bi[i] = 0; }
    float maxv = 3.4e38f; int maxp = 0;
    for (int j = 0; j < NCH*KNN; j++){
        float d = g_pd[base+j];
        if (d < maxv){
            bd[maxp] = d; bi[maxp] = g_pi[base+j];
            maxv = bd[0]; maxp = 0;
#pragma unroll
            for (int i = 1; i < KNN; i++)
                if (bd[i] > maxv){ maxv = bd[i]; maxp = i; }
        }
    }
    int ob = (b*NPTS + qi)*KNN;
#pragma unroll
    for (int i = 0; i < KNN; i++) g_idx[ob+i] = bi[i];
}

// ---------------- pos-MLP hidden --------------------------------------------
__global__ __launch_bounds__(256) void pos_hidden_kernel(const float* __restrict__ pos,
                                                         const float* __restrict__ pw1){
    int b = blockIdx.y, n = blockIdx.x;
    __shared__ float prx[KNN], pry[KNN], prz[KNN];
    int t = threadIdx.x;
    const float* pb = pos + (size_t)b*3*NPTS;
    if (t < KNN){
        int m = g_idx[(b*NPTS+n)*KNN + t];
        prx[t] = pb[n]        - pb[m];
        pry[t] = pb[NPTS+n]   - pb[NPTS+m];
        prz[t] = pb[2*NPTS+n] - pb[2*NPTS+m];
    }
    __syncthreads();
    for (int e = t; e < KNN*PHID; e += 256){
        int k = e >> 6, hh = e & 63;
        float z = pw1[hh*3+0]*prx[k] + pw1[hh*3+1]*pry[k] + pw1[hh*3+2]*prz[k];
        z = z*g_sP[hh] + g_tP[hh];
        g_ph[((b*NPTS+n)*KNN + k)*PHID + hh] = rtf(fmaxf(z, 0.f));
    }
}

// ---------------- tf32 GEMM: cp.async 4-stage, 1 barrier/iter, stride-20 smem
// C[M][N] = A[M][K] * Bw[N][K]^T, 128x128 tile, occupancy 2
// EPI 0: C = acc + bias[n]
// EPI 1: C = rtf(acc + bias[n])
// EPI 2: folded attn-hidden epilogue -> g_hid (rounded)
// EPI 3: C = acc
// EPI 4: fused softmax(k)+aggregate -> g_agg (rounded)
template<int EPI>
__global__ __launch_bounds__(256,2) void gemm2(const float* __restrict__ A,
        const float* __restrict__ Bw, float* __restrict__ C,
        int M, int N, int K, const float* __restrict__ bias,
        long strideAb, long strideCb){
    extern __shared__ __align__(16) float sm[];
    A += (long)blockIdx.z*strideAb;
    C += (long)blockIdx.z*strideCb;
    const int t = threadIdx.x, lane = t&31, w = t>>5;
    const int wm = w>>2, wn = w&3;
    const int m0 = blockIdx.x*128, n0 = blockIdx.y*128;
    const uint32_t smb = (uint32_t)__cvta_generic_to_shared(sm);
    float acc[4][4][4];
#pragma unroll
    for (int i=0;i<4;i++)
#pragma unroll
      for (int j=0;j<4;j++)
#pragma unroll
        for (int c=0;c<4;c++) acc[i][j][c] = 0.f;

    const int nIter = K >> 4;
    auto prefetch = [&](int st, int kt){
#pragma unroll
        for (int l=0;l<2;l++){
            int g = t + (l<<8);
            int row = g>>2, kq = (g&3)<<2;
            int arow = m0 + row; if (arow >= M) arow = M - 1;   // clamp: in-bounds
            uint32_t d = smb + (uint32_t)((st*5120 + row*20 + kq)<<2);
            cp16(d, A + (long)arow*K + (kt<<4) + kq);
            uint32_t d2 = smb + (uint32_t)((st*5120 + 2560 + row*20 + kq)<<2);
            cp16(d2, Bw + (long)(n0+row)*K + (kt<<4) + kq);
        }
        cpcommit();
    };
    prefetch(0, 0);
    prefetch(1, 1);
    prefetch(2, 2);

    for (int it = 0; it < nIter; ++it){
        if (it + 3 < nIter) cpwait2();      // steady state: oldest (=it) done
        else                cpwait0();      // tail: guarantee stage it complete
        __syncthreads();                    // also protects slot (it+3)&3 reuse
        if (it+3 < nIter) prefetch((it+3)&3, it+3); else cpcommit();
        const float* sA = sm + (it&3)*5120;
        const float* sB = sA + 2560;
#pragma unroll
        for (int k8=0;k8<2;k8++){
            int kb = k8*8 + (lane&3);
            uint32_t af[4][4]; uint32_t bf[4][2];
#pragma unroll
            for (int i=0;i<4;i++){
                const float* p = sA + (wm*64 + i*16 + (lane>>2))*20 + kb;
                af[i][0]=__float_as_uint(p[0]);
                af[i][1]=__float_as_uint(p[160]);
                af[i][2]=__float_as_uint(p[4]);
                af[i][3]=__float_as_uint(p[164]);
            }
#pragma unroll
            for (int j=0;j<4;j++){
                const float* p = sB + (wn*32 + j*8 + (lane>>2))*20 + kb;
                bf[j][0]=__float_as_uint(p[0]);
                bf[j][1]=__float_as_uint(p[4]);
            }
#pragma unroll
            for (int i=0;i<4;i++)
#pragma unroll
                for (int j=0;j<4;j++)
                    mma_tf32(acc[i][j][0],acc[i][j][1],acc[i][j][2],acc[i][j][3],
                             af[i][0],af[i][1],af[i][2],af[i][3], bf[j][0],bf[j][1]);
        }
        // no trailing barrier: next iteration's top barrier orders slot reuse
    }

    const int r0 = lane >> 2, cq = (lane & 3) << 1;
    if (EPI == 4){
#pragma unroll
        for (int i=0;i<4;i++){
            int mrow = m0 + wm*64 + i*16;
            if (mrow >= M) continue;
            int colidx = mrow >> 4;            // b*NP1 + nn
            int b  = colidx / NP1;
            int nn = colidx - b*NP1;
            long pebase = (nn > 0) ? (long)((b*NPTS + nn-1)*KNN)*DIM : 0;
            int kk0 = r0;                      // k for half 0; half 1 = kk0+8
#pragma unroll
            for (int j=0;j<4;j++){
                int c0 = n0 + wn*32 + j*8 + cq;
                float outv[2];
#pragma unroll
                for (int q=0;q<2;q++){
                    float l0 = acc[i][j][q], l1 = acc[i][j][2+q];
                    float mx = fmaxf(l0, l1);
                    mx = fmaxf(mx, __shfl_xor_sync(0xffffffffu, mx, 4));
                    mx = fmaxf(mx, __shfl_xor_sync(0xffffffffu, mx, 8));
                    mx = fmaxf(mx, __shfl_xor_sync(0xffffffffu, mx, 16));
                    float e0 = expf(l0 - mx), e1 = expf(l1 - mx);
                    float pv0 = 0.f, pv1 = 0.f;
                    if (nn > 0){
                        pv0 = g_pe[pebase + (long)kk0*DIM + c0 + q];
                        pv1 = g_pe[pebase + (long)(kk0+8)*DIM + c0 + q];
                    }
                    float s  = e0 + e1;
                    float ts = e0*pv0 + e1*pv1;
                    s  += __shfl_xor_sync(0xffffffffu, s, 4);
                    ts += __shfl_xor_sync(0xffffffffu, ts, 4);
                    s  += __shfl_xor_sync(0xffffffffu, s, 8);
                    ts += __shfl_xor_sync(0xffffffffu, ts, 8);
                    s  += __shfl_xor_sync(0xffffffffu, s, 16);
                    ts += __shfl_xor_sync(0xffffffffu, ts, 16);
                    float vv = g_v[(long)colidx*DIM + c0 + q];
                    outv[q] = rtf(vv + ts / s);
                }
                if (r0 == 0){
                    float2 o = make_float2(outv[0], outv[1]);
                    *(float2*)&g_agg[(long)colidx*DIM + c0] = o;
                }
            }
        }
        return;
    }
#pragma unroll
    for (int i=0;i<4;i++){
#pragma unroll
        for (int half=0; half<2; half++){
            int m = m0 + wm*64 + i*16 + r0 + half*8;
            if (m >= M) continue;
            if (EPI == 2){
                int b  = m >> 15;
                int n  = (m >> 4) & (NPTS-1);
                int kk = m & 15;
                int midx = g_idx[((b*NPTS)+n)*KNN + kk];
                const float* wq = g_w1q + (long)(b*NP1 + n + 1)*HID;
                const float* wk = g_w1k + (long)(b*NPTS + midx)*HID;
                float* dst = g_hid + (long)((b*NP1 + n + 1)*KNN + kk)*HID;
#pragma unroll
                for (int j=0;j<4;j++){
                    int h = n0 + wn*32 + j*8 + cq;
                    float2 q2 = *(const float2*)&wq[h];
                    float2 k2 = *(const float2*)&wk[h];
                    float2 p2 = *(const float2*)&g_w1pb[h];
                    float2 s2 = *(const float2*)&g_sA[h];
                    float2 t2 = *(const float2*)&g_tA[h];
                    float2 o;
                    o.x = rtf(fmaxf((acc[i][j][half*2+0] + q2.x - k2.x + p2.x)*s2.x + t2.x, 0.f));
                    o.y = rtf(fmaxf((acc[i][j][half*2+1] + q2.y - k2.y + p2.y)*s2.y + t2.y, 0.f));
                    *(float2*)&dst[h] = o;
                }
            } else {
                float* crow = C + (long)m*N;
#pragma unroll
                for (int j=0;j<4;j++){
                    int n = n0 + wn*32 + j*8 + cq;
                    float2 o;
                    if (EPI == 0){
                        float2 bv = *(const float2*)&bias[n];
                        o.x = acc[i][j][half*2+0] + bv.x;
                        o.y = acc[i][j][half*2+1] + bv.y;
                    } else if (EPI == 1){
                        float2 bv = *(const float2*)&bias[n];
                        o.x = rtf(acc[i][j][half*2+0] + bv.x);
                        o.y = rtf(acc[i][j][half*2+1] + bv.y);
                    } else {
                        o.x = acc[i][j][half*2+0];
                        o.y = acc[i][j][half*2+1];
                    }
                    *(float2*)&crow[n] = o;
                }
            }
        }
    }
}

// ---------------- cls hidden -------------------------------------------------
__global__ void cls_hidden_kernel(){
    int b = blockIdx.x >> 4, kk = blockIdx.x & 15;
    long col = (long)(b*NP1)*KNN + kk;
    for (int h = threadIdx.x; h < HID; h += 256){
        float v = rtf(fmaxf(g_w1q[(long)(b*NP1)*HID + h]*g_sA[h] + g_tA[h], 0.f));
        g_hid[col*HID + h] = v;
    }
}

// ---------------- finalize outputs ------------------------------------------
__global__ void finalize1_kernel(const float* __restrict__ x, float* __restrict__ out){
    int gid = blockIdx.x*256 + threadIdx.x;
    int n  = gid % NPTS;
    int ch = (gid / NPTS) % DIM;
    int b  = gid / (NPTS*DIM);
    out[gid] = g_y[((b*NP1) + (n+1))*DIM + ch] + x[gid];
}
__global__ void finalize2_kernel(float* __restrict__ out){
    int t = threadIdx.x;
    int b = t / DIM, ch = t % DIM;
    out[BB*DIM*NPTS + t] = g_y[(b*NP1)*DIM + ch];
}

// ---------------- launch -----------------------------------------------------
extern "C" void kernel_launch(void* const* d_in, const int* in_sizes, int n_in,
                              void* d_out, int out_size){
    const float* x        = (const float*)d_in[0];
    const float* pos      = (const float*)d_in[1];
    const float* W_start  = (const float*)d_in[2];
    const float* b_start  = (const float*)d_in[3];
    const float* W_key    = (const float*)d_in[4];
    const float* b_key    = (const float*)d_in[5];
    const float* W_query  = (const float*)d_in[6];
    const float* b_query  = (const float*)d_in[7];
    const float* W_value  = (const float*)d_in[8];
    const float* b_value  = (const float*)d_in[9];
    const float* pos_W1   = (const float*)d_in[10];
    const float* pos_b1   = (const float*)d_in[11];
    const float* pos_g    = (const float*)d_in[12];
    const float* pos_beta = (const float*)d_in[13];
    const float* pos_m    = (const float*)d_in[14];
    const float* pos_v    = (const float*)d_in[15];
    const float* pos_W2   = (const float*)d_in[16];
    const float* pos_b2   = (const float*)d_in[17];
    const float* attn_W1  = (const float*)d_in[18];
    const float* attn_b1  = (const float*)d_in[19];
    const float* attn_g   = (const float*)d_in[20];
    const float* attn_beta= (const float*)d_in[21];
    const float* attn_m   = (const float*)d_in[22];
    const float* attn_v   = (const float*)d_in[23];
    const float* attn_W2  = (const float*)d_in[24];
    const float* attn_b2  = (const float*)d_in[25];
    const float* W_end    = (const float*)d_in[26];
    const float* b_end    = (const float*)d_in[27];
    const float* pos_emb  = (const float*)d_in[28];
    const float* cls_tok  = (const float*)d_in[29];
    float* out = (float*)d_out;
    (void)attn_b2;

    float *pxT,*phx,*pq,*pk,*pv,*pph,*ppe,*phid,*pagg,*py,*pw1q,*pw1k,*pWc;
    float *prWs,*prWq,*prWk,*prWv,*prW1,*prP2,*prW2,*prWe;
    cudaGetSymbolAddress((void**)&pxT,  g_xT);
    cudaGetSymbolAddress((void**)&phx,  g_hx);
    cudaGetSymbolAddress((void**)&pq,   g_q);
    cudaGetSymbolAddress((void**)&pk,   g_k);
    cudaGetSymbolAddress((void**)&pv,   g_v);
    cudaGetSymbolAddress((void**)&pph,  g_ph);
    cudaGetSymbolAddress((void**)&ppe,  g_pe);
    cudaGetSymbolAddress((void**)&phid, g_hid);
    cudaGetSymbolAddress((void**)&pagg, g_agg);
    cudaGetSymbolAddress((void**)&py,   g_y);
    cudaGetSymbolAddress((void**)&pw1q, g_w1q);
    cudaGetSymbolAddress((void**)&pw1k, g_w1k);
    cudaGetSymbolAddress((void**)&pWc,  g_Wc);
    cudaGetSymbolAddress((void**)&prWs, g_rWs);
    cudaGetSymbolAddress((void**)&prWq, g_rWq);
    cudaGetSymbolAddress((void**)&prWk, g_rWk);
    cudaGetSymbolAddress((void**)&prWv, g_rWv);
    cudaGetSymbolAddress((void**)&prW1, g_rW1);
    cudaGetSymbolAddress((void**)&prP2, g_rP2);
    cudaGetSymbolAddress((void**)&prW2, g_rW2);
    cudaGetSymbolAddress((void**)&prWe, g_rWe);

    cudaFuncSetAttribute(gemm2<0>, cudaFuncAttributeMaxDynamicSharedMemorySize, GSMEM);
    cudaFuncSetAttribute(gemm2<1>, cudaFuncAttributeMaxDynamicSharedMemorySize, GSMEM);
    cudaFuncSetAttribute(gemm2<2>, cudaFuncAttributeMaxDynamicSharedMemorySize, GSMEM);
    cudaFuncSetAttribute(gemm2<3>, cudaFuncAttributeMaxDynamicSharedMemorySize, GSMEM);
    cudaFuncSetAttribute(gemm2<4>, cudaFuncAttributeMaxDynamicSharedMemorySize, GSMEM);

    // prep + weight rounding (single merged launch)
    transpose_x_kernel<<<dim3(NPTS/32, INCH/32, BB), dim3(32,32)>>>(x);
    prep_kernel<<<1,1024>>>(attn_g, attn_beta, attn_m, attn_v, attn_b1,
                            pos_g, pos_beta, pos_m, pos_v, pos_b1,
                            attn_W1, pos_b2);
    wc_kernel<<<HID, PHID>>>(attn_W1, pos_W2);
    {
        RCArgs rc;
        rc.s[0]=W_start; rc.d[0]=prWs;
        rc.s[1]=W_query; rc.d[1]=prWq;
        rc.s[2]=W_key;   rc.d[2]=prWk;
        rc.s[3]=W_value; rc.d[3]=prWv;
        rc.s[4]=attn_W1; rc.d[4]=prW1;
        rc.s[5]=pos_W2;  rc.d[5]=prP2;
        rc.s[6]=attn_W2; rc.d[6]=prW2;
        rc.s[7]=W_end;   rc.d[7]=prWe;
        int sz[8] = {DIM*INCH, DIM*DIM, DIM*DIM, DIM*DIM, HID*DIM, DIM*PHID, DIM*HID, INCH*DIM};
        int acc = 0;
        for (int k = 0; k < 8; k++){ acc += sz[k]; rc.end[k] = acc; }
        roundcpy_all_kernel<<<(acc + 255)/256, 256>>>(rc);
    }
    init_cls_kernel<<<BB, DIM>>>(cls_tok);
    knn_part_kernel<<<dim3(NPTS/256, BB, NCH), 256>>>(pos);
    knn_merge_kernel<<<dim3(NPTS/256, BB), 256>>>();

    // hx[1:] = W_start @ x + b
    gemm2<1><<<dim3(NPTS/128, DIM/128, BB), 256, GSMEM>>>(
        pxT, prWs, phx + DIM, NPTS, DIM, INCH, b_start,
        (long)NPTS*INCH, (long)NP1*DIM);

    // q,k,v
    gemm2<1><<<dim3((BB*NP1+127)/128, DIM/128, 1), 256, GSMEM>>>(
        phx, prWq, pq, BB*NP1, DIM, DIM, b_query, 0, 0);
    gemm2<1><<<dim3((BB*NP1+127)/128, DIM/128, 1), 256, GSMEM>>>(
        phx, prWk, pk, BB*NP1, DIM, DIM, b_key, 0, 0);
    gemm2<0><<<dim3((BB*NP1+127)/128, DIM/128, 1), 256, GSMEM>>>(
        phx, prWv, pv, BB*NP1, DIM, DIM, b_value, 0, 0);

    addpos_kernel<<<BB, DIM>>>(pos_emb);

    // w1q (all rows, cls row includes pos_emb), w1k (rows 1..)
    gemm2<3><<<dim3((BB*NP1+127)/128, HID/128, 1), 256, GSMEM>>>(
        pq, prW1, pw1q, BB*NP1, HID, DIM, nullptr, 0, 0);
    gemm2<3><<<dim3(NPTS/128, HID/128, BB), 256, GSMEM>>>(
        pk + DIM, prW1, pw1k, NPTS, HID, DIM, nullptr,
        (long)NP1*DIM, (long)NPTS*HID);

    // pos-MLP
    pos_hidden_kernel<<<dim3(NPTS, BB), 256>>>(pos, pos_W1);
    gemm2<0><<<dim3(NK/128, DIM/128, 1), 256, GSMEM>>>(
        pph, prP2, ppe, NK, DIM, PHID, pos_b2, 0, 0);

    // folded attn hidden
    gemm2<2><<<dim3(NK/128, HID/128, 1), 256, GSMEM>>>(
        pph, pWc, nullptr, NK, HID, PHID, nullptr, 0, 0);
    cls_hidden_kernel<<<BB*KNN, 256>>>();

    // logits + fused softmax/aggregate -> g_agg
    gemm2<4><<<dim3((NCOL+127)/128, DIM/128, 1), 256, GSMEM>>>(
        phid, prW2, nullptr, NCOL, DIM, HID, nullptr, 0, 0);

    // y = W_end @ agg + b
    gemm2<0><<<dim3((BB*NP1+127)/128, DIM/128, 1), 256, GSMEM>>>(
        pagg, prWe, py, BB*NP1, DIM, DIM, b_end, 0, 0);

    finalize1_kernel<<<(BB*DIM*NPTS)/256, 256>>>(x, out);
    finalize2_kernel<<<1, BB*DIM>>>(out);
}

// round 9
// speedup vs baseline: 1.4173x; 1.1646x over previous
#include <cuda_runtime.h>
#include <cuda_bf16.h>
#include <math.h>
#include <stdint.h>

#define BB 4
#define INCH 256
#define NPTS 2048
#define NP1 2049
#define DIM 256
#define KNN 16
#define PHID 64
#define HID 1024
#define NCOL (BB*NP1*KNN)   /* 131136 */
#define NK   (BB*NPTS*KNN)  /* 131072 */
#define NCH  8
#define EPSV 1e-5f
#define GSMEM  81920        /* tf32: 4 stages * (128+128)*20 words * 4B */
#define GSMEMB 49152        /* bf16: 4 stages * (128+128)*12 words * 4B */

// ---------------- scratch ----------------------------------------------------
__device__ float g_xT[BB*NPTS*INCH];
__device__ float g_hx[BB*NP1*DIM];
__device__ float g_q [BB*NP1*DIM];
__device__ float g_k [BB*NP1*DIM];
__device__ float g_v [BB*NP1*DIM];
__device__ int   g_idx[BB*NPTS*KNN];
__device__ float g_pd[BB*NPTS*NCH*KNN];
__device__ int   g_pi[BB*NPTS*NCH*KNN];
__device__ float g_ph [NK*PHID];
__device__ __nv_bfloat16 g_phb[NK*PHID];
__device__ float g_pe [(long)NK*DIM];
__device__ __nv_bfloat16 g_hid[(long)NCOL*HID];
__device__ float g_agg[BB*NP1*DIM];
__device__ float g_y  [BB*NP1*DIM];
__device__ float g_w1q[BB*NP1*HID];
__device__ float g_w1k[BB*NPTS*HID];
__device__ __nv_bfloat16 g_bWc[HID*PHID];
__device__ __nv_bfloat16 g_bW2[DIM*HID];
__device__ float g_sA[HID], g_tA[HID], g_w1pb[HID];
__device__ float g_sP[PHID], g_tP[PHID];
// rounded tf32 weights
__device__ float g_rWs[DIM*INCH];
__device__ float g_rWq[DIM*DIM];
__device__ float g_rWk[DIM*DIM];
__device__ float g_rWv[DIM*DIM];
__device__ float g_rW1[HID*DIM];
__device__ float g_rP2[DIM*PHID];
__device__ float g_rWe[INCH*DIM];

// ---------------- helpers ----------------------------------------------------
__device__ __forceinline__ float rtf(float x){
    uint32_t r; asm("cvt.rna.tf32.f32 %0, %1;" : "=r"(r) : "f"(x));
    return __uint_as_float(r);
}
__device__ __forceinline__ void mma_tf32(float&c0,float&c1,float&c2,float&c3,
   uint32_t a0,uint32_t a1,uint32_t a2,uint32_t a3,uint32_t b0,uint32_t b1){
  asm volatile("mma.sync.aligned.m16n8k8.row.col.f32.tf32.tf32.f32 "
    "{%0,%1,%2,%3}, {%4,%5,%6,%7}, {%8,%9}, {%0,%1,%2,%3};\n"
    : "+f"(c0),"+f"(c1),"+f"(c2),"+f"(c3)
    : "r"(a0),"r"(a1),"r"(a2),"r"(a3),"r"(b0),"r"(b1));
}
__device__ __forceinline__ void mma_bf16(float&c0,float&c1,float&c2,float&c3,
   uint32_t a0,uint32_t a1,uint32_t a2,uint32_t a3,uint32_t b0,uint32_t b1){
  asm volatile("mma.sync.aligned.m16n8k16.row.col.f32.bf16.bf16.f32 "
    "{%0,%1,%2,%3}, {%4,%5,%6,%7}, {%8,%9}, {%0,%1,%2,%3};\n"
    : "+f"(c0),"+f"(c1),"+f"(c2),"+f"(c3)
    : "r"(a0),"r"(a1),"r"(a2),"r"(a3),"r"(b0),"r"(b1));
}
__device__ __forceinline__ void cp16(uint32_t dst, const void* src){
    asm volatile("cp.async.cg.shared.global [%0], [%1], 16;" :: "r"(dst), "l"(src));
}
__device__ __forceinline__ void cpcommit(){ asm volatile("cp.async.commit_group;"); }
__device__ __forceinline__ void cpwait2(){ asm volatile("cp.async.wait_group 2;"); }
__device__ __forceinline__ void cpwait0(){ asm volatile("cp.async.wait_group 0;"); }

// ---------------- merged weight rounding ------------------------------------
struct RCArgs {
    const float* s[7];
    float* d[7];
    int end[7];
};
__global__ void roundcpy_all_kernel(RCArgs a){
    int i = blockIdx.x*256 + threadIdx.x;
    int seg = 0;
#pragma unroll
    for (int k = 0; k < 7; k++) if (i >= a.end[k]) seg = k+1;
    if (seg >= 7) return;
    int base = seg ? a.end[seg-1] : 0;
    a.d[seg][i-base] = rtf(a.s[seg][i-base]);
}
__global__ void cvtW2_kernel(const float* __restrict__ W2){
    int i = blockIdx.x*256 + threadIdx.x;
    g_bW2[i] = __float2bfloat16_rn(W2[i]);
}

// ---------------- small prep kernels ----------------------------------------
__global__ void transpose_x_kernel(const float* __restrict__ x){
    __shared__ float tile[32][33];
    int b = blockIdx.z;
    int i0 = blockIdx.y*32, n0 = blockIdx.x*32;
    int tx = threadIdx.x, ty = threadIdx.y;
    tile[ty][tx] = x[(b*INCH + (i0+ty))*NPTS + n0+tx];
    __syncthreads();
    g_xT[(b*NPTS + (n0+ty))*INCH + i0+tx] = rtf(tile[tx][ty]);
}

__global__ void prep_kernel(const float* __restrict__ ag, const float* __restrict__ abeta,
                            const float* __restrict__ am, const float* __restrict__ av,
                            const float* __restrict__ ab1,
                            const float* __restrict__ pg, const float* __restrict__ pbeta,
                            const float* __restrict__ pm, const float* __restrict__ pv,
                            const float* __restrict__ pb1,
                            const float* __restrict__ W1, const float* __restrict__ pb2){
    int t = threadIdx.x;
    if (t < HID){
        float s = ag[t] / sqrtf(av[t] + EPSV);
        g_sA[t] = s;
        g_tA[t] = abeta[t] - am[t]*s + ab1[t]*s;
        float acc = 0.f;
        for (int c = 0; c < DIM; c++) acc += W1[t*DIM+c]*pb2[c];
        g_w1pb[t] = acc;
    }
    if (t < PHID){
        float s = pg[t] / sqrtf(pv[t] + EPSV);
        g_sP[t] = s;
        g_tP[t] = pbeta[t] - pm[t]*s + pb1[t]*s;
    }
}

__global__ void wc_kernel(const float* __restrict__ W1, const float* __restrict__ W2p){
    int h = blockIdx.x, p = threadIdx.x;
    float s = 0.f;
    for (int c = 0; c < DIM; c++) s += W1[h*DIM+c]*W2p[c*PHID+p];
    g_bWc[h*PHID+p] = __float2bfloat16_rn(s);
}

__global__ void init_cls_kernel(const float* __restrict__ cls){
    g_hx[(blockIdx.x*NP1)*DIM + threadIdx.x] = rtf(cls[threadIdx.x]);
}

__global__ void addpos_kernel(const float* __restrict__ pos_emb){
    int b = blockIdx.x, c = threadIdx.x;
    g_q[(b*NP1)*DIM + c] = rtf(g_q[(b*NP1)*DIM + c] + pos_emb[c]);
    g_v[(b*NP1)*DIM + c] += pos_emb[c];
}

// ---------------- KNN (chunked) ---------------------------------------------
__global__ __launch_bounds__(256) void knn_part_kernel(const float* __restrict__ pos){
    __shared__ float sx[256], sy[256], sz[256];
    int b = blockIdx.y, ch = blockIdx.z;
    const float* pb = pos + (size_t)b*3*NPTS;
    int j0 = ch*256;
    int t = threadIdx.x;
    sx[t] = pb[j0+t]; sy[t] = pb[NPTS+j0+t]; sz[t] = pb[2*NPTS+j0+t];
    __syncthreads();
    int qi = blockIdx.x*256 + t;
    float qx = pb[qi], qy = pb[NPTS+qi], qz = pb[2*NPTS+qi];
    float bd[KNN]; int bi[KNN];
#pragma unroll
    for (int i = 0; i < KNN; i++){ bd[i] = 3.4e38f; bi[i] = 0; }
    float maxv = 3.4e38f; int maxp = 0;
    for (int j = 0; j < 256; j++){
        float dx = qx - sx[j], dy = qy - sy[j], dz = qz - sz[j];
        float d = dx*dx + dy*dy + dz*dz;
        if (d < maxv){
            bd[maxp] = d; bi[maxp] = j0 + j;
            maxv = bd[0]; maxp = 0;
#pragma unroll
            for (int i = 1; i < KNN; i++)
                if (bd[i] > maxv){ maxv = bd[i]; maxp = i; }
        }
    }
    long base = ((long)(b*NPTS + qi)*NCH + ch)*KNN;
#pragma unroll
    for (int i = 0; i < KNN; i++){ g_pd[base+i] = bd[i]; g_pi[base+i] = bi[i]; }
}

__global__ __launch_bounds__(256) void knn_merge_kernel(){
    int b = blockIdx.y;
    int qi = blockIdx.x*256 + threadIdx.x;
    long base = (long)(b*NPTS + qi)*NCH*KNN;
    float bd[KNN]; int bi[KNN];
#pragma unroll
    for (int i = 0; i < KNN; i++){ bd[i] = 3.4e38f; bi[i] = 0; }
    float maxv = 3.4e38f; int maxp = 0;
    for (int j = 0; j < NCH*KNN; j++){
        float d = g_pd[base+j];
        if (d < maxv){
            bd[maxp] = d; bi[maxp] = g_pi[base+j];
            maxv = bd[0]; maxp = 0;
#pragma unroll
            for (int i = 1; i < KNN; i++)
                if (bd[i] > maxv){ maxv = bd[i]; maxp = i; }
        }
    }
    int ob = (b*NPTS + qi)*KNN;
#pragma unroll
    for (int i = 0; i < KNN; i++) g_idx[ob+i] = bi[i];
}

// ---------------- pos-MLP hidden --------------------------------------------
__global__ __launch_bounds__(256) void pos_hidden_kernel(const float* __restrict__ pos,
                                                         const float* __restrict__ pw1){
    int b = blockIdx.y, n = blockIdx.x;
    __shared__ float prx[KNN], pry[KNN], prz[KNN];
    int t = threadIdx.x;
    const float* pb = pos + (size_t)b*3*NPTS;
    if (t < KNN){
        int m = g_idx[(b*NPTS+n)*KNN + t];
        prx[t] = pb[n]        - pb[m];
        pry[t] = pb[NPTS+n]   - pb[NPTS+m];
        prz[t] = pb[2*NPTS+n] - pb[2*NPTS+m];
    }
    __syncthreads();
    for (int e = t; e < KNN*PHID; e += 256){
        int k = e >> 6, hh = e & 63;
        float z = pw1[hh*3+0]*prx[k] + pw1[hh*3+1]*pry[k] + pw1[hh*3+2]*prz[k];
        z = z*g_sP[hh] + g_tP[hh];
        z = fmaxf(z, 0.f);
        long o = ((long)(b*NPTS+n)*KNN + k)*PHID + hh;
        g_ph[o]  = rtf(z);
        g_phb[o] = __float2bfloat16_rn(z);
    }
}

// ---------------- tf32 GEMM: cp.async 4-stage, 1 barrier/iter, stride-20 smem
// EPI 0: C = acc + bias[n] ; EPI 1: C = rtf(acc + bias[n]) ; EPI 3: C = acc
template<int EPI>
__global__ __launch_bounds__(256,2) void gemm2(const float* __restrict__ A,
        const float* __restrict__ Bw, float* __restrict__ C,
        int M, int N, int K, const float* __restrict__ bias,
        long strideAb, long strideCb){
    extern __shared__ __align__(16) float sm[];
    A += (long)blockIdx.z*strideAb;
    C += (long)blockIdx.z*strideCb;
    const int t = threadIdx.x, lane = t&31, w = t>>5;
    const int wm = w>>2, wn = w&3;
    const int m0 = blockIdx.x*128, n0 = blockIdx.y*128;
    const uint32_t smb = (uint32_t)__cvta_generic_to_shared(sm);
    float acc[4][4][4];
#pragma unroll
    for (int i=0;i<4;i++)
#pragma unroll
      for (int j=0;j<4;j++)
#pragma unroll
        for (int c=0;c<4;c++) acc[i][j][c] = 0.f;

    const int nIter = K >> 4;
    auto prefetch = [&](int st, int kt){
#pragma unroll
        for (int l=0;l<2;l++){
            int g = t + (l<<8);
            int row = g>>2, kq = (g&3)<<2;
            int arow = m0 + row; if (arow >= M) arow = M - 1;
            uint32_t d = smb + (uint32_t)((st*5120 + row*20 + kq)<<2);
            cp16(d, A + (long)arow*K + (kt<<4) + kq);
            uint32_t d2 = smb + (uint32_t)((st*5120 + 2560 + row*20 + kq)<<2);
            cp16(d2, Bw + (long)(n0+row)*K + (kt<<4) + kq);
        }
        cpcommit();
    };
    prefetch(0, 0);
    prefetch(1, 1);
    prefetch(2, 2);

    for (int it = 0; it < nIter; ++it){
        if (it + 3 < nIter) cpwait2();
        else                cpwait0();
        __syncthreads();
        if (it+3 < nIter) prefetch((it+3)&3, it+3); else cpcommit();
        const float* sA = sm + (it&3)*5120;
        const float* sB = sA + 2560;
#pragma unroll
        for (int k8=0;k8<2;k8++){
            int kb = k8*8 + (lane&3);
            uint32_t af[4][4]; uint32_t bf[4][2];
#pragma unroll
            for (int i=0;i<4;i++){
                const float* p = sA + (wm*64 + i*16 + (lane>>2))*20 + kb;
                af[i][0]=__float_as_uint(p[0]);
                af[i][1]=__float_as_uint(p[160]);
                af[i][2]=__float_as_uint(p[4]);
                af[i][3]=__float_as_uint(p[164]);
            }
#pragma unroll
            for (int j=0;j<4;j++){
                const float* p = sB + (wn*32 + j*8 + (lane>>2))*20 + kb;
                bf[j][0]=__float_as_uint(p[0]);
                bf[j][1]=__float_as_uint(p[4]);
            }
#pragma unroll
            for (int i=0;i<4;i++)
#pragma unroll
                for (int j=0;j<4;j++)
                    mma_tf32(acc[i][j][0],acc[i][j][1],acc[i][j][2],acc[i][j][3],
                             af[i][0],af[i][1],af[i][2],af[i][3], bf[j][0],bf[j][1]);
        }
    }

    const int r0 = lane >> 2, cq = (lane & 3) << 1;
#pragma unroll
    for (int i=0;i<4;i++){
#pragma unroll
        for (int half=0; half<2; half++){
            int m = m0 + wm*64 + i*16 + r0 + half*8;
            if (m >= M) continue;
            float* crow = C + (long)m*N;
#pragma unroll
            for (int j=0;j<4;j++){
                int n = n0 + wn*32 + j*8 + cq;
                float2 o;
                if (EPI == 0){
                    float2 bv = *(const float2*)&bias[n];
                    o.x = acc[i][j][half*2+0] + bv.x;
                    o.y = acc[i][j][half*2+1] + bv.y;
                } else if (EPI == 1){
                    float2 bv = *(const float2*)&bias[n];
                    o.x = rtf(acc[i][j][half*2+0] + bv.x);
                    o.y = rtf(acc[i][j][half*2+1] + bv.y);
                } else {
                    o.x = acc[i][j][half*2+0];
                    o.y = acc[i][j][half*2+1];
                }
                *(float2*)&crow[n] = o;
            }
        }
    }
}

// ---------------- bf16 GEMM: m16n8k16, cp.async 4-stage, stride-12 smem ------
// EPI 2: folded attn-hidden -> g_hid (bf16) ; EPI 4: softmax+agg -> g_agg
template<int EPI>
__global__ __launch_bounds__(256,2) void gemm2b(const __nv_bfloat16* __restrict__ A,
        const __nv_bfloat16* __restrict__ Bw, int M, int N, int K){
    extern __shared__ __align__(16) uint32_t smw[];
    const int t = threadIdx.x, lane = t&31, w = t>>5;
    const int wm = w>>2, wn = w&3;
    const int m0 = blockIdx.x*128, n0 = blockIdx.y*128;
    const uint32_t smb = (uint32_t)__cvta_generic_to_shared(smw);
    float acc[4][4][4];
#pragma unroll
    for (int i=0;i<4;i++)
#pragma unroll
      for (int j=0;j<4;j++)
#pragma unroll
        for (int c=0;c<4;c++) acc[i][j][c] = 0.f;

    const int nIter = K >> 4;                  // k-step = 16 halves
    auto prefetch = [&](int st, int kt){
#pragma unroll
        for (int l=0;l<2;l++){
            int g = t + (l<<8);                // 0..511
            int row = g>>1;                    // 0..255
            int kqw = (g&1)<<2;                // word offset 0 or 4
            int kh  = (kt<<4) + ((g&1)<<3);    // half offset
            if (row < 128){
                int arow = m0 + row; if (arow >= M) arow = M - 1;
                uint32_t d = smb + (uint32_t)((st*3072 + row*12 + kqw)<<2);
                cp16(d, A + (long)arow*K + kh);
            } else {
                int brow = row - 128;
                uint32_t d = smb + (uint32_t)((st*3072 + 1536 + brow*12 + kqw)<<2);
                cp16(d, Bw + (long)(n0+brow)*K + kh);
            }
        }
        cpcommit();
    };
    prefetch(0, 0);
    prefetch(1, 1);
    prefetch(2, 2);

    for (int it = 0; it < nIter; ++it){
        if (it + 3 < nIter) cpwait2();
        else                cpwait0();
        __syncthreads();
        if (it+3 < nIter) prefetch((it+3)&3, it+3); else cpcommit();
        const uint32_t* sA = smw + (it&3)*3072;
        const uint32_t* sB = sA + 1536;
        const int c = lane&3, r4 = lane>>2;
        uint32_t af[4][4]; uint32_t bf[4][2];
#pragma unroll
        for (int i=0;i<4;i++){
            const uint32_t* p = sA + (wm*64 + i*16 + r4)*12 + c;
            af[i][0]=p[0]; af[i][1]=p[96]; af[i][2]=p[4]; af[i][3]=p[100];
        }
#pragma unroll
        for (int j=0;j<4;j++){
            const uint32_t* p = sB + (wn*32 + j*8 + r4)*12 + c;
            bf[j][0]=p[0]; bf[j][1]=p[4];
        }
#pragma unroll
        for (int i=0;i<4;i++)
#pragma unroll
            for (int j=0;j<4;j++)
                mma_bf16(acc[i][j][0],acc[i][j][1],acc[i][j][2],acc[i][j][3],
                         af[i][0],af[i][1],af[i][2],af[i][3], bf[j][0],bf[j][1]);
    }

    const int r0 = lane >> 2, cq = (lane & 3) << 1;
    if (EPI == 4){
#pragma unroll
        for (int i=0;i<4;i++){
            int mrow = m0 + wm*64 + i*16;
            if (mrow >= M) continue;
            int colidx = mrow >> 4;            // b*NP1 + nn
            int b  = colidx / NP1;
            int nn = colidx - b*NP1;
            long pebase = (nn > 0) ? (long)((b*NPTS + nn-1)*KNN)*DIM : 0;
            int kk0 = r0;
#pragma unroll
            for (int j=0;j<4;j++){
                int c0 = n0 + wn*32 + j*8 + cq;
                float outv[2];
#pragma unroll
                for (int q=0;q<2;q++){
                    float l0 = acc[i][j][q], l1 = acc[i][j][2+q];
                    float mx = fmaxf(l0, l1);
                    mx = fmaxf(mx, __shfl_xor_sync(0xffffffffu, mx, 4));
                    mx = fmaxf(mx, __shfl_xor_sync(0xffffffffu, mx, 8));
                    mx = fmaxf(mx, __shfl_xor_sync(0xffffffffu, mx, 16));
                    float e0 = expf(l0 - mx), e1 = expf(l1 - mx);
                    float pv0 = 0.f, pv1 = 0.f;
                    if (nn > 0){
                        pv0 = g_pe[pebase + (long)kk0*DIM + c0 + q];
                        pv1 = g_pe[pebase + (long)(kk0+8)*DIM + c0 + q];
                    }
                    float s  = e0 + e1;
                    float ts = e0*pv0 + e1*pv1;
                    s  += __shfl_xor_sync(0xffffffffu, s, 4);
                    ts += __shfl_xor_sync(0xffffffffu, ts, 4);
                    s  += __shfl_xor_sync(0xffffffffu, s, 8);
                    ts += __shfl_xor_sync(0xffffffffu, ts, 8);
                    s  += __shfl_xor_sync(0xffffffffu, s, 16);
                    ts += __shfl_xor_sync(0xffffffffu, ts, 16);
                    float vv = g_v[(long)colidx*DIM + c0 + q];
                    outv[q] = rtf(vv + ts / s);
                }
                if (r0 == 0){
                    float2 o = make_float2(outv[0], outv[1]);
                    *(float2*)&g_agg[(long)colidx*DIM + c0] = o;
                }
            }
        }
        return;
    }
    // EPI 2
#pragma unroll
    for (int i=0;i<4;i++){
#pragma unroll
        for (int half=0; half<2; half++){
            int m = m0 + wm*64 + i*16 + r0 + half*8;
            if (m >= M) continue;
            int b  = m >> 15;
            int n  = (m >> 4) & (NPTS-1);
            int kk = m & 15;
            int midx = g_idx[((b*NPTS)+n)*KNN + kk];
            const float* wq = g_w1q + (long)(b*NP1 + n + 1)*HID;
            const float* wk = g_w1k + (long)(b*NPTS + midx)*HID;
            __nv_bfloat16* dst = g_hid + (long)((b*NP1 + n + 1)*KNN + kk)*HID;
#pragma unroll
            for (int j=0;j<4;j++){
                int h = n0 + wn*32 + j*8 + cq;
                float2 q2 = *(const float2*)&wq[h];
                float2 k2 = *(const float2*)&wk[h];
                float2 p2 = *(const float2*)&g_w1pb[h];
                float2 s2 = *(const float2*)&g_sA[h];
                float2 t2 = *(const float2*)&g_tA[h];
                float ox = fmaxf((acc[i][j][half*2+0] + q2.x - k2.x + p2.x)*s2.x + t2.x, 0.f);
                float oy = fmaxf((acc[i][j][half*2+1] + q2.y - k2.y + p2.y)*s2.y + t2.y, 0.f);
                __nv_bfloat162 o2 = __floats2bfloat162_rn(ox, oy);
                *(__nv_bfloat162*)&dst[h] = o2;
            }
        }
    }
}

// ---------------- cls hidden -------------------------------------------------
__global__ void cls_hidden_kernel(){
    int b = blockIdx.x >> 4, kk = blockIdx.x & 15;
    long col = (long)(b*NP1)*KNN + kk;
    for (int h = threadIdx.x; h < HID; h += 256){
        float v = fmaxf(g_w1q[(long)(b*NP1)*HID + h]*g_sA[h] + g_tA[h], 0.f);
        g_hid[col*HID + h] = __float2bfloat16_rn(v);
    }
}

// ---------------- finalize outputs ------------------------------------------
__global__ void finalize1_kernel(const float* __restrict__ x, float* __restrict__ out){
    int gid = blockIdx.x*256 + threadIdx.x;
    int n  = gid % NPTS;
    int ch = (gid / NPTS) % DIM;
    int b  = gid / (NPTS*DIM);
    out[gid] = g_y[((b*NP1) + (n+1))*DIM + ch] + x[gid];
}
__global__ void finalize2_kernel(float* __restrict__ out){
    int t = threadIdx.x;
    int b = t / DIM, ch = t % DIM;
    out[BB*DIM*NPTS + t] = g_y[(b*NP1)*DIM + ch];
}

// ---------------- launch -----------------------------------------------------
extern "C" void kernel_launch(void* const* d_in, const int* in_sizes, int n_in,
                              void* d_out, int out_size){
    const float* x        = (const float*)d_in[0];
    const float* pos      = (const float*)d_in[1];
    const float* W_start  = (const float*)d_in[2];
    const float* b_start  = (const float*)d_in[3];
    const float* W_key    = (const float*)d_in[4];
    const float* b_key    = (const float*)d_in[5];
    const float* W_query  = (const float*)d_in[6];
    const float* b_query  = (const float*)d_in[7];
    const float* W_value  = (const float*)d_in[8];
    const float* b_value  = (const float*)d_in[9];
    const float* pos_W1   = (const float*)d_in[10];
    const float* pos_b1   = (const float*)d_in[11];
    const float* pos_g    = (const float*)d_in[12];
    const float* pos_beta = (const float*)d_in[13];
    const float* pos_m    = (const float*)d_in[14];
    const float* pos_v    = (const float*)d_in[15];
    const float* pos_W2   = (const float*)d_in[16];
    const float* pos_b2   = (const float*)d_in[17];
    const float* attn_W1  = (const float*)d_in[18];
    const float* attn_b1  = (const float*)d_in[19];
    const float* attn_g   = (const float*)d_in[20];
    const float* attn_beta= (const float*)d_in[21];
    const float* attn_m   = (const float*)d_in[22];
    const float* attn_v   = (const float*)d_in[23];
    const float* attn_W2  = (const float*)d_in[24];
    const float* attn_b2  = (const float*)d_in[25];
    const float* W_end    = (const float*)d_in[26];
    const float* b_end    = (const float*)d_in[27];
    const float* pos_emb  = (const float*)d_in[28];
    const float* cls_tok  = (const float*)d_in[29];
    float* out = (float*)d_out;
    (void)attn_b2;

    float *pxT,*phx,*pq,*pk,*pv,*pph,*ppe,*pagg,*py,*pw1q,*pw1k;
    float *prWs,*prWq,*prWk,*prWv,*prW1,*prP2,*prWe;
    __nv_bfloat16 *pphb,*phid,*pbWc,*pbW2;
    cudaGetSymbolAddress((void**)&pxT,  g_xT);
    cudaGetSymbolAddress((void**)&phx,  g_hx);
    cudaGetSymbolAddress((void**)&pq,   g_q);
    cudaGetSymbolAddress((void**)&pk,   g_k);
    cudaGetSymbolAddress((void**)&pv,   g_v);
    cudaGetSymbolAddress((void**)&pph,  g_ph);
    cudaGetSymbolAddress((void**)&pphb, g_phb);
    cudaGetSymbolAddress((void**)&ppe,  g_pe);
    cudaGetSymbolAddress((void**)&phid, g_hid);
    cudaGetSymbolAddress((void**)&pagg, g_agg);
    cudaGetSymbolAddress((void**)&py,   g_y);
    cudaGetSymbolAddress((void**)&pw1q, g_w1q);
    cudaGetSymbolAddress((void**)&pw1k, g_w1k);
    cudaGetSymbolAddress((void**)&pbWc, g_bWc);
    cudaGetSymbolAddress((void**)&pbW2, g_bW2);
    cudaGetSymbolAddress((void**)&prWs, g_rWs);
    cudaGetSymbolAddress((void**)&prWq, g_rWq);
    cudaGetSymbolAddress((void**)&prWk, g_rWk);
    cudaGetSymbolAddress((void**)&prWv, g_rWv);
    cudaGetSymbolAddress((void**)&prW1, g_rW1);
    cudaGetSymbolAddress((void**)&prP2, g_rP2);
    cudaGetSymbolAddress((void**)&prWe, g_rWe);

    cudaFuncSetAttribute(gemm2<0>, cudaFuncAttributeMaxDynamicSharedMemorySize, GSMEM);
    cudaFuncSetAttribute(gemm2<1>, cudaFuncAttributeMaxDynamicSharedMemorySize, GSMEM);
    cudaFuncSetAttribute(gemm2<3>, cudaFuncAttributeMaxDynamicSharedMemorySize, GSMEM);
    cudaFuncSetAttribute(gemm2b<2>, cudaFuncAttributeMaxDynamicSharedMemorySize, GSMEMB);
    cudaFuncSetAttribute(gemm2b<4>, cudaFuncAttributeMaxDynamicSharedMemorySize, GSMEMB);

    // prep + weight rounding
    transpose_x_kernel<<<dim3(NPTS/32, INCH/32, BB), dim3(32,32)>>>(x);
    prep_kernel<<<1,1024>>>(attn_g, attn_beta, attn_m, attn_v, attn_b1,
                            pos_g, pos_beta, pos_m, pos_v, pos_b1,
                            attn_W1, pos_b2);
    wc_kernel<<<HID, PHID>>>(attn_W1, pos_W2);
    cvtW2_kernel<<<(DIM*HID)/256, 256>>>(attn_W2);
    {
        RCArgs rc;
        rc.s[0]=W_start; rc.d[0]=prWs;
        rc.s[1]=W_query; rc.d[1]=prWq;
        rc.s[2]=W_key;   rc.d[2]=prWk;
        rc.s[3]=W_value; rc.d[3]=prWv;
        rc.s[4]=attn_W1; rc.d[4]=prW1;
        rc.s[5]=pos_W2;  rc.d[5]=prP2;
        rc.s[6]=W_end;   rc.d[6]=prWe;
        int sz[7] = {DIM*INCH, DIM*DIM, DIM*DIM, DIM*DIM, HID*DIM, DIM*PHID, INCH*DIM};
        int acc = 0;
        for (int k = 0; k < 7; k++){ acc += sz[k]; rc.end[k] = acc; }
        roundcpy_all_kernel<<<(acc + 255)/256, 256>>>(rc);
    }
    init_cls_kernel<<<BB, DIM>>>(cls_tok);
    knn_part_kernel<<<dim3(NPTS/256, BB, NCH), 256>>>(pos);
    knn_merge_kernel<<<dim3(NPTS/256, BB), 256>>>();

    // hx[1:] = W_start @ x + b
    gemm2<1><<<dim3(NPTS/128, DIM/128, BB), 256, GSMEM>>>(
        pxT, prWs, phx + DIM, NPTS, DIM, INCH, b_start,
        (long)NPTS*INCH, (long)NP1*DIM);

    // q,k,v
    gemm2<1><<<dim3((BB*NP1+127)/128, DIM/128, 1), 256, GSMEM>>>(
        phx, prWq, pq, BB*NP1, DIM, DIM, b_query, 0, 0);
    gemm2<1><<<dim3((BB*NP1+127)/128, DIM/128, 1), 256, GSMEM>>>(
        phx, prWk, pk, BB*NP1, DIM, DIM, b_key, 0, 0);
    gemm2<0><<<dim3((BB*NP1+127)/128, DIM/128, 1), 256, GSMEM>>>(
        phx, prWv, pv, BB*NP1, DIM, DIM, b_value, 0, 0);

    addpos_kernel<<<BB, DIM>>>(pos_emb);

    // w1q, w1k
    gemm2<3><<<dim3((BB*NP1+127)/128, HID/128, 1), 256, GSMEM>>>(
        pq, prW1, pw1q, BB*NP1, HID, DIM, nullptr, 0, 0);
    gemm2<3><<<dim3(NPTS/128, HID/128, BB), 256, GSMEM>>>(
        pk + DIM, prW1, pw1k, NPTS, HID, DIM, nullptr,
        (long)NP1*DIM, (long)NPTS*HID);

    // pos-MLP
    pos_hidden_kernel<<<dim3(NPTS, BB), 256>>>(pos, pos_W1);
    gemm2<0><<<dim3(NK/128, DIM/128, 1), 256, GSMEM>>>(
        pph, prP2, ppe, NK, DIM, PHID, pos_b2, 0, 0);

    // folded attn hidden (bf16 core)
    gemm2b<2><<<dim3(NK/128, HID/128, 1), 256, GSMEMB>>>(
        pphb, pbWc, NK, HID, PHID);
    cls_hidden_kernel<<<BB*KNN, 256>>>();

    // logits + fused softmax/aggregate (bf16 core)
    gemm2b<4><<<dim3((NCOL+127)/128, DIM/128, 1), 256, GSMEMB>>>(
        phid, pbW2, NCOL, DIM, HID);

    // y = W_end @ agg + b
    gemm2<0><<<dim3((BB*NP1+127)/128, DIM/128, 1), 256, GSMEM>>>(
        pagg, prWe, py, BB*NP1, DIM, DIM, b_end, 0, 0);

    finalize1_kernel<<<(BB*DIM*NPTS)/256, 256>>>(x, out);
    finalize2_kernel<<<1, BB*DIM>>>(out);
}

// round 10
// speedup vs baseline: 1.4565x; 1.0277x over previous
#include <cuda_runtime.h>
#include <cuda_bf16.h>
#include <math.h>
#include <stdint.h>

#define BB 4
#define INCH 256
#define NPTS 2048
#define NP1 2049
#define DIM 256
#define KNN 16
#define PHID 64
#define HID 1024
#define NCOL (BB*NP1*KNN)   /* 131136 */
#define NK   (BB*NPTS*KNN)  /* 131072 */
#define NCH  8
#define EPSV 1e-5f
#define GSMEM  81920        /* tf32: 4 stages * (128+128)*20 words * 4B */
#define GSMEMB 49152        /* bf16: 4 stages * (128+128)*12 words * 4B */

// ---------------- scratch ----------------------------------------------------
__device__ float g_xT[BB*NPTS*INCH];
__device__ float g_hx[BB*NP1*DIM];
__device__ __nv_bfloat16 g_qb[BB*NP1*DIM];
__device__ __nv_bfloat16 g_kb[BB*NP1*DIM];
__device__ float g_v [BB*NP1*DIM];
__device__ int   g_idx[BB*NPTS*KNN];
__device__ float g_pd[BB*NPTS*NCH*KNN];
__device__ int   g_pi[BB*NPTS*NCH*KNN];
__device__ float g_ph [NK*PHID];
__device__ __nv_bfloat16 g_phb[NK*PHID];
__device__ float g_pe [(long)NK*DIM];
__device__ __nv_bfloat16 g_hid[(long)NCOL*HID];
__device__ float g_agg[BB*NP1*DIM];
__device__ float g_y  [BB*NP1*DIM];
__device__ float g_w1q[BB*NP1*HID];
__device__ float g_w1k[BB*NPTS*HID];
__device__ __nv_bfloat16 g_bWc[HID*PHID];
__device__ __nv_bfloat16 g_bW2[DIM*HID];
__device__ __nv_bfloat16 g_bW1[HID*DIM];
__device__ float g_sA[HID], g_tA[HID], g_w1pb[HID];
__device__ float g_sP[PHID], g_tP[PHID];
// rounded tf32 weights
__device__ float g_rWs[DIM*INCH];
__device__ float g_rWq[DIM*DIM];
__device__ float g_rWk[DIM*DIM];
__device__ float g_rWv[DIM*DIM];
__device__ float g_rP2[DIM*PHID];
__device__ float g_rWe[INCH*DIM];

// ---------------- helpers ----------------------------------------------------
__device__ __forceinline__ float rtf(float x){
    uint32_t r; asm("cvt.rna.tf32.f32 %0, %1;" : "=r"(r) : "f"(x));
    return __uint_as_float(r);
}
__device__ __forceinline__ void mma_tf32(float&c0,float&c1,float&c2,float&c3,
   uint32_t a0,uint32_t a1,uint32_t a2,uint32_t a3,uint32_t b0,uint32_t b1){
  asm volatile("mma.sync.aligned.m16n8k8.row.col.f32.tf32.tf32.f32 "
    "{%0,%1,%2,%3}, {%4,%5,%6,%7}, {%8,%9}, {%0,%1,%2,%3};\n"
    : "+f"(c0),"+f"(c1),"+f"(c2),"+f"(c3)
    : "r"(a0),"r"(a1),"r"(a2),"r"(a3),"r"(b0),"r"(b1));
}
__device__ __forceinline__ void mma_bf16(float&c0,float&c1,float&c2,float&c3,
   uint32_t a0,uint32_t a1,uint32_t a2,uint32_t a3,uint32_t b0,uint32_t b1){
  asm volatile("mma.sync.aligned.m16n8k16.row.col.f32.bf16.bf16.f32 "
    "{%0,%1,%2,%3}, {%4,%5,%6,%7}, {%8,%9}, {%0,%1,%2,%3};\n"
    : "+f"(c0),"+f"(c1),"+f"(c2),"+f"(c3)
    : "r"(a0),"r"(a1),"r"(a2),"r"(a3),"r"(b0),"r"(b1));
}
__device__ __forceinline__ void cp16(uint32_t dst, const void* src){
    asm volatile("cp.async.cg.shared.global [%0], [%1], 16;" :: "r"(dst), "l"(src));
}
__device__ __forceinline__ void cpcommit(){ asm volatile("cp.async.commit_group;"); }
__device__ __forceinline__ void cpwait2(){ asm volatile("cp.async.wait_group 2;"); }
__device__ __forceinline__ void cpwait0(){ asm volatile("cp.async.wait_group 0;"); }

// ---------------- merged weight rounding ------------------------------------
struct RCArgs {
    const float* s[6];
    float* d[6];
    int end[6];
};
__global__ void roundcpy_all_kernel(RCArgs a){
    int i = blockIdx.x*256 + threadIdx.x;
    int seg = 0;
#pragma unroll
    for (int k = 0; k < 6; k++) if (i >= a.end[k]) seg = k+1;
    if (seg >= 6) return;
    int base = seg ? a.end[seg-1] : 0;
    a.d[seg][i-base] = rtf(a.s[seg][i-base]);
}
__global__ void cvtb_kernel(const float* __restrict__ src, __nv_bfloat16* __restrict__ dst){
    int i = blockIdx.x*256 + threadIdx.x;
    dst[i] = __float2bfloat16_rn(src[i]);
}

// ---------------- small prep kernels ----------------------------------------
__global__ void transpose_x_kernel(const float* __restrict__ x){
    __shared__ float tile[32][33];
    int b = blockIdx.z;
    int i0 = blockIdx.y*32, n0 = blockIdx.x*32;
    int tx = threadIdx.x, ty = threadIdx.y;
    tile[ty][tx] = x[(b*INCH + (i0+ty))*NPTS + n0+tx];
    __syncthreads();
    g_xT[(b*NPTS + (n0+ty))*INCH + i0+tx] = rtf(tile[tx][ty]);
}

__global__ void prep_kernel(const float* __restrict__ ag, const float* __restrict__ abeta,
                            const float* __restrict__ am, const float* __restrict__ av,
                            const float* __restrict__ ab1,
                            const float* __restrict__ pg, const float* __restrict__ pbeta,
                            const float* __restrict__ pm, const float* __restrict__ pv,
                            const float* __restrict__ pb1,
                            const float* __restrict__ W1, const float* __restrict__ pb2){
    int t = threadIdx.x;
    if (t < HID){
        float s = ag[t] / sqrtf(av[t] + EPSV);
        g_sA[t] = s;
        g_tA[t] = abeta[t] - am[t]*s + ab1[t]*s;
        float acc = 0.f;
        for (int c = 0; c < DIM; c++) acc += W1[t*DIM+c]*pb2[c];
        g_w1pb[t] = acc;
    }
    if (t < PHID){
        float s = pg[t] / sqrtf(pv[t] + EPSV);
        g_sP[t] = s;
        g_tP[t] = pbeta[t] - pm[t]*s + pb1[t]*s;
    }
}

__global__ void wc_kernel(const float* __restrict__ W1, const float* __restrict__ W2p){
    int h = blockIdx.x, p = threadIdx.x;
    float s = 0.f;
    for (int c = 0; c < DIM; c++) s += W1[h*DIM+c]*W2p[c*PHID+p];
    g_bWc[h*PHID+p] = __float2bfloat16_rn(s);
}

__global__ void init_cls_kernel(const float* __restrict__ cls){
    g_hx[(blockIdx.x*NP1)*DIM + threadIdx.x] = rtf(cls[threadIdx.x]);
}

__global__ void addpos_kernel(const float* __restrict__ pos_emb){
    int b = blockIdx.x, c = threadIdx.x;
    int o = (b*NP1)*DIM + c;
    g_qb[o] = __float2bfloat16_rn(__bfloat162float(g_qb[o]) + pos_emb[c]);
    g_v[o] += pos_emb[c];
}

// ---------------- KNN (chunked) ---------------------------------------------
__global__ __launch_bounds__(256) void knn_part_kernel(const float* __restrict__ pos){
    __shared__ float sx[256], sy[256], sz[256];
    int b = blockIdx.y, ch = blockIdx.z;
    const float* pb = pos + (size_t)b*3*NPTS;
    int j0 = ch*256;
    int t = threadIdx.x;
    sx[t] = pb[j0+t]; sy[t] = pb[NPTS+j0+t]; sz[t] = pb[2*NPTS+j0+t];
    __syncthreads();
    int qi = blockIdx.x*256 + t;
    float qx = pb[qi], qy = pb[NPTS+qi], qz = pb[2*NPTS+qi];
    float bd[KNN]; int bi[KNN];
#pragma unroll
    for (int i = 0; i < KNN; i++){ bd[i] = 3.4e38f; bi[i] = 0; }
    float maxv = 3.4e38f; int maxp = 0;
    for (int j = 0; j < 256; j++){
        float dx = qx - sx[j], dy = qy - sy[j], dz = qz - sz[j];
        float d = dx*dx + dy*dy + dz*dz;
        if (d < maxv){
            bd[maxp] = d; bi[maxp] = j0 + j;
            maxv = bd[0]; maxp = 0;
#pragma unroll
            for (int i = 1; i < KNN; i++)
                if (bd[i] > maxv){ maxv = bd[i]; maxp = i; }
        }
    }
    long base = ((long)(b*NPTS + qi)*NCH + ch)*KNN;
#pragma unroll
    for (int i = 0; i < KNN; i++){ g_pd[base+i] = bd[i]; g_pi[base+i] = bi[i]; }
}

__global__ __launch_bounds__(256) void knn_merge_kernel(){
    int b = blockIdx.y;
    int qi = blockIdx.x*256 + threadIdx.x;
    long base = (long)(b*NPTS + qi)*NCH*KNN;
    float bd[KNN]; int bi[KNN];
#pragma unroll
    for (int i = 0; i < KNN; i++){ bd[i] = 3.4e38f; bi[i] = 0; }
    float maxv = 3.4e38f; int maxp = 0;
    for (int j = 0; j < NCH*KNN; j++){
        float d = g_pd[base+j];
        if (d < maxv){
            bd[maxp] = d; bi[maxp] = g_pi[base+j];
            maxv = bd[0]; maxp = 0;
#pragma unroll
            for (int i = 1; i < KNN; i++)
                if (bd[i] > maxv){ maxv = bd[i]; maxp = i; }
        }
    }
    int ob = (b*NPTS + qi)*KNN;
#pragma unroll
    for (int i = 0; i < KNN; i++) g_idx[ob+i] = bi[i];
}

// ---------------- pos-MLP hidden --------------------------------------------
__global__ __launch_bounds__(256) void pos_hidden_kernel(const float* __restrict__ pos,
                                                         const float* __restrict__ pw1){
    int b = blockIdx.y, n = blockIdx.x;
    __shared__ float prx[KNN], pry[KNN], prz[KNN];
    int t = threadIdx.x;
    const float* pb = pos + (size_t)b*3*NPTS;
    if (t < KNN){
        int m = g_idx[(b*NPTS+n)*KNN + t];
        prx[t] = pb[n]        - pb[m];
        pry[t] = pb[NPTS+n]   - pb[NPTS+m];
        prz[t] = pb[2*NPTS+n] - pb[2*NPTS+m];
    }
    __syncthreads();
    for (int e = t; e < KNN*PHID; e += 256){
        int k = e >> 6, hh = e & 63;
        float z = pw1[hh*3+0]*prx[k] + pw1[hh*3+1]*pry[k] + pw1[hh*3+2]*prz[k];
        z = z*g_sP[hh] + g_tP[hh];
        z = fmaxf(z, 0.f);
        long o = ((long)(b*NPTS+n)*KNN + k)*PHID + hh;
        g_ph[o]  = rtf(z);
        g_phb[o] = __float2bfloat16_rn(z);
    }
}

// ---------------- tf32 GEMM: cp.async 4-stage, 1 barrier/iter, stride-20 smem
// EPI 0: C = acc + bias[n] ; EPI 1: C = rtf(acc + bias[n]) ; EPI 3: C = acc
// EPI 5: bf16 C = acc + bias[n]
template<int EPI>
__global__ __launch_bounds__(256,2) void gemm2(const float* __restrict__ A,
        const float* __restrict__ Bw, float* __restrict__ C,
        int M, int N, int K, const float* __restrict__ bias,
        long strideAb, long strideCb){
    extern __shared__ __align__(16) float sm[];
    A += (long)blockIdx.z*strideAb;
    C += (long)blockIdx.z*strideCb;
    const int t = threadIdx.x, lane = t&31, w = t>>5;
    const int wm = w>>2, wn = w&3;
    const int m0 = blockIdx.x*128, n0 = blockIdx.y*128;
    const uint32_t smb = (uint32_t)__cvta_generic_to_shared(sm);
    float acc[4][4][4];
#pragma unroll
    for (int i=0;i<4;i++)
#pragma unroll
      for (int j=0;j<4;j++)
#pragma unroll
        for (int c=0;c<4;c++) acc[i][j][c] = 0.f;

    const int nIter = K >> 4;
    auto prefetch = [&](int st, int kt){
#pragma unroll
        for (int l=0;l<2;l++){
            int g = t + (l<<8);
            int row = g>>2, kq = (g&3)<<2;
            int arow = m0 + row; if (arow >= M) arow = M - 1;
            uint32_t d = smb + (uint32_t)((st*5120 + row*20 + kq)<<2);
            cp16(d, A + (long)arow*K + (kt<<4) + kq);
            uint32_t d2 = smb + (uint32_t)((st*5120 + 2560 + row*20 + kq)<<2);
            cp16(d2, Bw + (long)(n0+row)*K + (kt<<4) + kq);
        }
        cpcommit();
    };
    prefetch(0, 0);
    prefetch(1, 1);
    prefetch(2, 2);

    for (int it = 0; it < nIter; ++it){
        if (it + 3 < nIter) cpwait2();
        else                cpwait0();
        __syncthreads();
        if (it+3 < nIter) prefetch((it+3)&3, it+3); else cpcommit();
        const float* sA = sm + (it&3)*5120;
        const float* sB = sA + 2560;
#pragma unroll
        for (int k8=0;k8<2;k8++){
            int kb = k8*8 + (lane&3);
            uint32_t af[4][4]; uint32_t bf[4][2];
#pragma unroll
            for (int i=0;i<4;i++){
                const float* p = sA + (wm*64 + i*16 + (lane>>2))*20 + kb;
                af[i][0]=__float_as_uint(p[0]);
                af[i][1]=__float_as_uint(p[160]);
                af[i][2]=__float_as_uint(p[4]);
                af[i][3]=__float_as_uint(p[164]);
            }
#pragma unroll
            for (int j=0;j<4;j++){
                const float* p = sB + (wn*32 + j*8 + (lane>>2))*20 + kb;
                bf[j][0]=__float_as_uint(p[0]);
                bf[j][1]=__float_as_uint(p[4]);
            }
#pragma unroll
            for (int i=0;i<4;i++)
#pragma unroll
                for (int j=0;j<4;j++)
                    mma_tf32(acc[i][j][0],acc[i][j][1],acc[i][j][2],acc[i][j][3],
                             af[i][0],af[i][1],af[i][2],af[i][3], bf[j][0],bf[j][1]);
        }
    }

    const int r0 = lane >> 2, cq = (lane & 3) << 1;
#pragma unroll
    for (int i=0;i<4;i++){
#pragma unroll
        for (int half=0; half<2; half++){
            int m = m0 + wm*64 + i*16 + r0 + half*8;
            if (m >= M) continue;
            if (EPI == 5){
                __nv_bfloat16* cb = (__nv_bfloat16*)C + (long)m*N;
#pragma unroll
                for (int j=0;j<4;j++){
                    int n = n0 + wn*32 + j*8 + cq;
                    float2 bv = *(const float2*)&bias[n];
                    __nv_bfloat162 o2 = __floats2bfloat162_rn(
                        acc[i][j][half*2+0] + bv.x, acc[i][j][half*2+1] + bv.y);
                    *(__nv_bfloat162*)&cb[n] = o2;
                }
            } else {
                float* crow = C + (long)m*N;
#pragma unroll
                for (int j=0;j<4;j++){
                    int n = n0 + wn*32 + j*8 + cq;
                    float2 o;
                    if (EPI == 0){
                        float2 bv = *(const float2*)&bias[n];
                        o.x = acc[i][j][half*2+0] + bv.x;
                        o.y = acc[i][j][half*2+1] + bv.y;
                    } else if (EPI == 1){
                        float2 bv = *(const float2*)&bias[n];
                        o.x = rtf(acc[i][j][half*2+0] + bv.x);
                        o.y = rtf(acc[i][j][half*2+1] + bv.y);
                    } else {
                        o.x = acc[i][j][half*2+0];
                        o.y = acc[i][j][half*2+1];
                    }
                    *(float2*)&crow[n] = o;
                }
            }
        }
    }
}

// ---------------- bf16 GEMM: m16n8k16, cp.async 4-stage, stride-12 smem ------
// EPI 2: folded attn-hidden -> g_hid (bf16) ; EPI 3: fp32 C = acc ;
// EPI 4: softmax+agg -> g_agg
template<int EPI>
__global__ __launch_bounds__(256,2) void gemm2b(const __nv_bfloat16* __restrict__ A,
        const __nv_bfloat16* __restrict__ Bw, float* __restrict__ C,
        int M, int N, int K, long strideAb, long strideCb){
    extern __shared__ __align__(16) uint32_t smw[];
    A += (long)blockIdx.z*strideAb;
    C += (long)blockIdx.z*strideCb;
    const int t = threadIdx.x, lane = t&31, w = t>>5;
    const int wm = w>>2, wn = w&3;
    const int m0 = blockIdx.x*128, n0 = blockIdx.y*128;
    const uint32_t smb = (uint32_t)__cvta_generic_to_shared(smw);
    float acc[4][4][4];
#pragma unroll
    for (int i=0;i<4;i++)
#pragma unroll
      for (int j=0;j<4;j++)
#pragma unroll
        for (int c=0;c<4;c++) acc[i][j][c] = 0.f;

    const int nIter = K >> 4;                  // k-step = 16 halves
    auto prefetch = [&](int st, int kt){
#pragma unroll
        for (int l=0;l<2;l++){
            int g = t + (l<<8);                // 0..511
            int row = g>>1;                    // 0..255
            int kqw = (g&1)<<2;                // word offset 0 or 4
            int kh  = (kt<<4) + ((g&1)<<3);    // half offset
            if (row < 128){
                int arow = m0 + row; if (arow >= M) arow = M - 1;
                uint32_t d = smb + (uint32_t)((st*3072 + row*12 + kqw)<<2);
                cp16(d, A + (long)arow*K + kh);
            } else {
                int brow = row - 128;
                uint32_t d = smb + (uint32_t)((st*3072 + 1536 + brow*12 + kqw)<<2);
                cp16(d, Bw + (long)(n0+brow)*K + kh);
            }
        }
        cpcommit();
    };
    prefetch(0, 0);
    prefetch(1, 1);
    prefetch(2, 2);

    for (int it = 0; it < nIter; ++it){
        if (it + 3 < nIter) cpwait2();
        else                cpwait0();
        __syncthreads();
        if (it+3 < nIter) prefetch((it+3)&3, it+3); else cpcommit();
        const uint32_t* sA = smw + (it&3)*3072;
        const uint32_t* sB = sA + 1536;
        const int c = lane&3, r4 = lane>>2;
        uint32_t af[4][4]; uint32_t bf[4][2];
#pragma unroll
        for (int i=0;i<4;i++){
            const uint32_t* p = sA + (wm*64 + i*16 + r4)*12 + c;
            af[i][0]=p[0]; af[i][1]=p[96]; af[i][2]=p[4]; af[i][3]=p[100];
        }
#pragma unroll
        for (int j=0;j<4;j++){
            const uint32_t* p = sB + (wn*32 + j*8 + r4)*12 + c;
            bf[j][0]=p[0]; bf[j][1]=p[4];
        }
#pragma unroll
        for (int i=0;i<4;i++)
#pragma unroll
            for (int j=0;j<4;j++)
                mma_bf16(acc[i][j][0],acc[i][j][1],acc[i][j][2],acc[i][j][3],
                         af[i][0],af[i][1],af[i][2],af[i][3], bf[j][0],bf[j][1]);
    }

    const int r0 = lane >> 2, cq = (lane & 3) << 1;
    if (EPI == 4){
#pragma unroll
        for (int i=0;i<4;i++){
            int mrow = m0 + wm*64 + i*16;
            if (mrow >= M) continue;
            int colidx = mrow >> 4;            // b*NP1 + nn
            int b  = colidx / NP1;
            int nn = colidx - b*NP1;
            long pebase = (nn > 0) ? (long)((b*NPTS + nn-1)*KNN)*DIM : 0;
            int kk0 = r0;
#pragma unroll
            for (int j=0;j<4;j++){
                int c0 = n0 + wn*32 + j*8 + cq;
                float outv[2];
#pragma unroll
                for (int q=0;q<2;q++){
                    float l0 = acc[i][j][q], l1 = acc[i][j][2+q];
                    float mx = fmaxf(l0, l1);
                    mx = fmaxf(mx, __shfl_xor_sync(0xffffffffu, mx, 4));
                    mx = fmaxf(mx, __shfl_xor_sync(0xffffffffu, mx, 8));
                    mx = fmaxf(mx, __shfl_xor_sync(0xffffffffu, mx, 16));
                    float e0 = expf(l0 - mx), e1 = expf(l1 - mx);
                    float pv0 = 0.f, pv1 = 0.f;
                    if (nn > 0){
                        pv0 = g_pe[pebase + (long)kk0*DIM + c0 + q];
                        pv1 = g_pe[pebase + (long)(kk0+8)*DIM + c0 + q];
                    }
                    float s  = e0 + e1;
                    float ts = e0*pv0 + e1*pv1;
                    s  += __shfl_xor_sync(0xffffffffu, s, 4);
                    ts += __shfl_xor_sync(0xffffffffu, ts, 4);
                    s  += __shfl_xor_sync(0xffffffffu, s, 8);
                    ts += __shfl_xor_sync(0xffffffffu, ts, 8);
                    s  += __shfl_xor_sync(0xffffffffu, s, 16);
                    ts += __shfl_xor_sync(0xffffffffu, ts, 16);
                    float vv = g_v[(long)colidx*DIM + c0 + q];
                    outv[q] = rtf(vv + ts / s);
                }
                if (r0 == 0){
                    float2 o = make_float2(outv[0], outv[1]);
                    *(float2*)&g_agg[(long)colidx*DIM + c0] = o;
                }
            }
        }
        return;
    }
#pragma unroll
    for (int i=0;i<4;i++){
#pragma unroll
        for (int half=0; half<2; half++){
            int m = m0 + wm*64 + i*16 + r0 + half*8;
            if (m >= M) continue;
            if (EPI == 2){
                int b  = m >> 15;
                int n  = (m >> 4) & (NPTS-1);
                int kk = m & 15;
                int midx = g_idx[((b*NPTS)+n)*KNN + kk];
                const float* wq = g_w1q + (long)(b*NP1 + n + 1)*HID;
                const float* wk = g_w1k + (long)(b*NPTS + midx)*HID;
                __nv_bfloat16* dst = g_hid + (long)((b*NP1 + n + 1)*KNN + kk)*HID;
#pragma unroll
                for (int j=0;j<4;j++){
                    int h = n0 + wn*32 + j*8 + cq;
                    float2 q2 = *(const float2*)&wq[h];
                    float2 k2 = *(const float2*)&wk[h];
                    float2 p2 = *(const float2*)&g_w1pb[h];
                    float2 s2 = *(const float2*)&g_sA[h];
                    float2 t2 = *(const float2*)&g_tA[h];
                    float ox = fmaxf((acc[i][j][half*2+0] + q2.x - k2.x + p2.x)*s2.x + t2.x, 0.f);
                    float oy = fmaxf((acc[i][j][half*2+1] + q2.y - k2.y + p2.y)*s2.y + t2.y, 0.f);
                    __nv_bfloat162 o2 = __floats2bfloat162_rn(ox, oy);
                    *(__nv_bfloat162*)&dst[h] = o2;
                }
            } else {                      // EPI 3: fp32 C = acc
                float* crow = C + (long)m*N;
#pragma unroll
                for (int j=0;j<4;j++){
                    int n = n0 + wn*32 + j*8 + cq;
                    float2 o = make_float2(acc[i][j][half*2+0], acc[i][j][half*2+1]);
                    *(float2*)&crow[n] = o;
                }
            }
        }
    }
}

// ---------------- cls hidden -------------------------------------------------
__global__ void cls_hidden_kernel(){
    int b = blockIdx.x >> 4, kk = blockIdx.x & 15;
    long col = (long)(b*NP1)*KNN + kk;
    for (int h = threadIdx.x; h < HID; h += 256){
        float v = fmaxf(g_w1q[(long)(b*NP1)*HID + h]*g_sA[h] + g_tA[h], 0.f);
        g_hid[col*HID + h] = __float2bfloat16_rn(v);
    }
}

// ---------------- finalize outputs ------------------------------------------
__global__ void finalize1_kernel(const float* __restrict__ x, float* __restrict__ out){
    int gid = blockIdx.x*256 + threadIdx.x;
    int n  = gid % NPTS;
    int ch = (gid / NPTS) % DIM;
    int b  = gid / (NPTS*DIM);
    out[gid] = g_y[((b*NP1) + (n+1))*DIM + ch] + x[gid];
}
__global__ void finalize2_kernel(float* __restrict__ out){
    int t = threadIdx.x;
    int b = t / DIM, ch = t % DIM;
    out[BB*DIM*NPTS + t] = g_y[(b*NP1)*DIM + ch];
}

// ---------------- launch -----------------------------------------------------
extern "C" void kernel_launch(void* const* d_in, const int* in_sizes, int n_in,
                              void* d_out, int out_size){
    const float* x        = (const float*)d_in[0];
    const float* pos      = (const float*)d_in[1];
    const float* W_start  = (const float*)d_in[2];
    const float* b_start  = (const float*)d_in[3];
    const float* W_key    = (const float*)d_in[4];
    const float* b_key    = (const float*)d_in[5];
    const float* W_query  = (const float*)d_in[6];
    const float* b_query  = (const float*)d_in[7];
    const float* W_value  = (const float*)d_in[8];
    const float* b_value  = (const float*)d_in[9];
    const float* pos_W1   = (const float*)d_in[10];
    const float* pos_b1   = (const float*)d_in[11];
    const float* pos_g    = (const float*)d_in[12];
    const float* pos_beta = (const float*)d_in[13];
    const float* pos_m    = (const float*)d_in[14];
    const float* pos_v    = (const float*)d_in[15];
    const float* pos_W2   = (const float*)d_in[16];
    const float* pos_b2   = (const float*)d_in[17];
    const float* attn_W1  = (const float*)d_in[18];
    const float* attn_b1  = (const float*)d_in[19];
    const float* attn_g   = (const float*)d_in[20];
    const float* attn_beta= (const float*)d_in[21];
    const float* attn_m   = (const float*)d_in[22];
    const float* attn_v   = (const float*)d_in[23];
    const float* attn_W2  = (const float*)d_in[24];
    const float* attn_b2  = (const float*)d_in[25];
    const float* W_end    = (const float*)d_in[26];
    const float* b_end    = (const float*)d_in[27];
    const float* pos_emb  = (const float*)d_in[28];
    const float* cls_tok  = (const float*)d_in[29];
    float* out = (float*)d_out;
    (void)attn_b2;

    float *pxT,*phx,*pv,*pph,*ppe,*pagg,*py,*pw1q,*pw1k;
    float *prWs,*prWq,*prWk,*prWv,*prP2,*prWe;
    __nv_bfloat16 *pphb,*phid,*pbWc,*pbW2,*pbW1,*pqb,*pkb;
    cudaGetSymbolAddress((void**)&pxT,  g_xT);
    cudaGetSymbolAddress((void**)&phx,  g_hx);
    cudaGetSymbolAddress((void**)&pqb,  g_qb);
    cudaGetSymbolAddress((void**)&pkb,  g_kb);
    cudaGetSymbolAddress((void**)&pv,   g_v);
    cudaGetSymbolAddress((void**)&pph,  g_ph);
    cudaGetSymbolAddress((void**)&pphb, g_phb);
    cudaGetSymbolAddress((void**)&ppe,  g_pe);
    cudaGetSymbolAddress((void**)&phid, g_hid);
    cudaGetSymbolAddress((void**)&pagg, g_agg);
    cudaGetSymbolAddress((void**)&py,   g_y);
    cudaGetSymbolAddress((void**)&pw1q, g_w1q);
    cudaGetSymbolAddress((void**)&pw1k, g_w1k);
    cudaGetSymbolAddress((void**)&pbWc, g_bWc);
    cudaGetSymbolAddress((void**)&pbW2, g_bW2);
    cudaGetSymbolAddress((void**)&pbW1, g_bW1);
    cudaGetSymbolAddress((void**)&prWs, g_rWs);
    cudaGetSymbolAddress((void**)&prWq, g_rWq);
    cudaGetSymbolAddress((void**)&prWk, g_rWk);
    cudaGetSymbolAddress((void**)&prWv, g_rWv);
    cudaGetSymbolAddress((void**)&prP2, g_rP2);
    cudaGetSymbolAddress((void**)&prWe, g_rWe);

    cudaFuncSetAttribute(gemm2<0>, cudaFuncAttributeMaxDynamicSharedMemorySize, GSMEM);
    cudaFuncSetAttribute(gemm2<1>, cudaFuncAttributeMaxDynamicSharedMemorySize, GSMEM);
    cudaFuncSetAttribute(gemm2<5>, cudaFuncAttributeMaxDynamicSharedMemorySize, GSMEM);
    cudaFuncSetAttribute(gemm2b<2>, cudaFuncAttributeMaxDynamicSharedMemorySize, GSMEMB);
    cudaFuncSetAttribute(gemm2b<3>, cudaFuncAttributeMaxDynamicSharedMemorySize, GSMEMB);
    cudaFuncSetAttribute(gemm2b<4>, cudaFuncAttributeMaxDynamicSharedMemorySize, GSMEMB);

    // prep + weight rounding/conversion
    transpose_x_kernel<<<dim3(NPTS/32, INCH/32, BB), dim3(32,32)>>>(x);
    prep_kernel<<<1,1024>>>(attn_g, attn_beta, attn_m, attn_v, attn_b1,
                            pos_g, pos_beta, pos_m, pos_v, pos_b1,
                            attn_W1, pos_b2);
    wc_kernel<<<HID, PHID>>>(attn_W1, pos_W2);
    cvtb_kernel<<<(DIM*HID)/256, 256>>>(attn_W2, pbW2);
    cvtb_kernel<<<(HID*DIM)/256, 256>>>(attn_W1, pbW1);
    {
        RCArgs rc;
        rc.s[0]=W_start; rc.d[0]=prWs;
        rc.s[1]=W_query; rc.d[1]=prWq;
        rc.s[2]=W_key;   rc.d[2]=prWk;
        rc.s[3]=W_value; rc.d[3]=prWv;
        rc.s[4]=pos_W2;  rc.d[4]=prP2;
        rc.s[5]=W_end;   rc.d[5]=prWe;
        int sz[6] = {DIM*INCH, DIM*DIM, DIM*DIM, DIM*DIM, DIM*PHID, INCH*DIM};
        int acc = 0;
        for (int k = 0; k < 6; k++){ acc += sz[k]; rc.end[k] = acc; }
        roundcpy_all_kernel<<<(acc + 255)/256, 256>>>(rc);
    }
    init_cls_kernel<<<BB, DIM>>>(cls_tok);
    knn_part_kernel<<<dim3(NPTS/256, BB, NCH), 256>>>(pos);
    knn_merge_kernel<<<dim3(NPTS/256, BB), 256>>>();

    // hx[1:] = W_start @ x + b
    gemm2<1><<<dim3(NPTS/128, DIM/128, BB), 256, GSMEM>>>(
        pxT, prWs, phx + DIM, NPTS, DIM, INCH, b_start,
        (long)NPTS*INCH, (long)NP1*DIM);

    // q,k (bf16 output; feed only the damped logit path) ; v (fp32, critical)
    gemm2<5><<<dim3((BB*NP1+127)/128, DIM/128, 1), 256, GSMEM>>>(
        phx, prWq, (float*)pqb, BB*NP1, DIM, DIM, b_query, 0, 0);
    gemm2<5><<<dim3((BB*NP1+127)/128, DIM/128, 1), 256, GSMEM>>>(
        phx, prWk, (float*)pkb, BB*NP1, DIM, DIM, b_key, 0, 0);
    gemm2<0><<<dim3((BB*NP1+127)/128, DIM/128, 1), 256, GSMEM>>>(
        phx, prWv, pv, BB*NP1, DIM, DIM, b_value, 0, 0);

    addpos_kernel<<<BB, DIM>>>(pos_emb);

    // w1q, w1k (bf16 cores, fp32 out)
    gemm2b<3><<<dim3((BB*NP1+127)/128, HID/128, 1), 256, GSMEMB>>>(
        pqb, pbW1, pw1q, BB*NP1, HID, DIM, 0, 0);
    gemm2b<3><<<dim3(NPTS/128, HID/128, BB), 256, GSMEMB>>>(
        pkb + DIM, pbW1, pw1k, NPTS, HID, DIM,
        (long)NP1*DIM, (long)NPTS*HID);

    // pos-MLP (tf32 — feeds agg directly, precision-critical)
    pos_hidden_kernel<<<dim3(NPTS, BB), 256>>>(pos, pos_W1);
    gemm2<0><<<dim3(NK/128, DIM/128, 1), 256, GSMEM>>>(
        pph, prP2, ppe, NK, DIM, PHID, pos_b2, 0, 0);

    // folded attn hidden (bf16 core)
    gemm2b<2><<<dim3(NK/128, HID/128, 1), 256, GSMEMB>>>(
        pphb, pbWc, nullptr, NK, HID, PHID, 0, 0);
    cls_hidden_kernel<<<BB*KNN, 256>>>();

    // logits + fused softmax/aggregate (bf16 core)
    gemm2b<4><<<dim3((NCOL+127)/128, DIM/128, 1), 256, GSMEMB>>>(
        phid, pbW2, nullptr, NCOL, DIM, HID, 0, 0);

    // y = W_end @ agg + b (tf32, critical)
    gemm2<0><<<dim3((BB*NP1+127)/128, DIM/128, 1), 256, GSMEM>>>(
        pagg, prWe, py, BB*NP1, DIM, DIM, b_end, 0, 0);

    finalize1_kernel<<<(BB*DIM*NPTS)/256, 256>>>(x, out);
    finalize2_kernel<<<1, BB*DIM>>>(out);
}

// round 11
// speedup vs baseline: 1.5372x; 1.0554x over previous
#include <cuda_runtime.h>
#include <cuda_bf16.h>
#include <math.h>
#include <stdint.h>

#define BB 4
#define INCH 256
#define NPTS 2048
#define NP1 2049
#define DIM 256
#define KNN 16
#define PHID 64
#define HID 1024
#define NCOL (BB*NP1*KNN)   /* 131136 */
#define NK   (BB*NPTS*KNN)  /* 131072 */
#define NCH  8
#define EPSV 1e-5f
#define GSMEM  81920        /* tf32: 4 stages * (128+128)*20 words * 4B */
#define GSMEMB 49152        /* bf16: 4 stages * (128+128)*12 words * 4B */

// ---------------- scratch ----------------------------------------------------
__device__ float g_xT[BB*NPTS*INCH];
__device__ float g_hx[BB*NP1*DIM];
__device__ __nv_bfloat16 g_qb[BB*NP1*DIM];
__device__ __nv_bfloat16 g_kb[BB*NP1*DIM];
__device__ float g_v [BB*NP1*DIM];
__device__ int   g_idx[BB*NPTS*KNN];
__device__ float g_pd[BB*NPTS*NCH*KNN];
__device__ int   g_pi[BB*NPTS*NCH*KNN];
__device__ float g_ph [NK*PHID];
__device__ __nv_bfloat16 g_phb[NK*PHID];
__device__ float g_pe [(long)NK*DIM];
__device__ __nv_bfloat16 g_hid[(long)NCOL*HID];
__device__ float g_agg[BB*NP1*DIM];
__device__ float g_y  [BB*NP1*DIM];
__device__ float g_w1q[BB*NP1*HID];
__device__ float g_w1k[BB*NPTS*HID];
__device__ __nv_bfloat16 g_bWc[HID*PHID];
__device__ __nv_bfloat16 g_bW2[DIM*HID];
__device__ __nv_bfloat16 g_bW1[HID*DIM];
__device__ float g_sA[HID], g_tA[HID], g_w1pb[HID];
__device__ float g_sP[PHID], g_tP[PHID];
// rounded tf32 weights
__device__ float g_rWs[DIM*INCH];
__device__ float g_rWq[DIM*DIM];
__device__ float g_rWk[DIM*DIM];
__device__ float g_rWv[DIM*DIM];
__device__ float g_rP2[DIM*PHID];
__device__ float g_rWe[INCH*DIM];

// ---------------- helpers ----------------------------------------------------
__device__ __forceinline__ float rtf(float x){
    uint32_t r; asm("cvt.rna.tf32.f32 %0, %1;" : "=r"(r) : "f"(x));
    return __uint_as_float(r);
}
__device__ __forceinline__ void mma_tf32(float&c0,float&c1,float&c2,float&c3,
   uint32_t a0,uint32_t a1,uint32_t a2,uint32_t a3,uint32_t b0,uint32_t b1){
  asm volatile("mma.sync.aligned.m16n8k8.row.col.f32.tf32.tf32.f32 "
    "{%0,%1,%2,%3}, {%4,%5,%6,%7}, {%8,%9}, {%0,%1,%2,%3};\n"
    : "+f"(c0),"+f"(c1),"+f"(c2),"+f"(c3)
    : "r"(a0),"r"(a1),"r"(a2),"r"(a3),"r"(b0),"r"(b1));
}
__device__ __forceinline__ void mma_bf16(float&c0,float&c1,float&c2,float&c3,
   uint32_t a0,uint32_t a1,uint32_t a2,uint32_t a3,uint32_t b0,uint32_t b1){
  asm volatile("mma.sync.aligned.m16n8k16.row.col.f32.bf16.bf16.f32 "
    "{%0,%1,%2,%3}, {%4,%5,%6,%7}, {%8,%9}, {%0,%1,%2,%3};\n"
    : "+f"(c0),"+f"(c1),"+f"(c2),"+f"(c3)
    : "r"(a0),"r"(a1),"r"(a2),"r"(a3),"r"(b0),"r"(b1));
}
__device__ __forceinline__ void ldsm4(uint32_t&r0,uint32_t&r1,uint32_t&r2,uint32_t&r3,
                                      uint32_t addr){
  asm volatile("ldmatrix.sync.aligned.m8n8.x4.shared.b16 {%0,%1,%2,%3}, [%4];"
    : "=r"(r0),"=r"(r1),"=r"(r2),"=r"(r3) : "r"(addr));
}
__device__ __forceinline__ void cp16(uint32_t dst, const void* src){
    asm volatile("cp.async.cg.shared.global [%0], [%1], 16;" :: "r"(dst), "l"(src));
}
__device__ __forceinline__ void cpcommit(){ asm volatile("cp.async.commit_group;"); }
__device__ __forceinline__ void cpwait2(){ asm volatile("cp.async.wait_group 2;"); }
__device__ __forceinline__ void cpwait0(){ asm volatile("cp.async.wait_group 0;"); }

// ---------------- merged weight rounding ------------------------------------
struct RCArgs {
    const float* s[6];
    float* d[6];
    int end[6];
};
__global__ void roundcpy_all_kernel(RCArgs a){
    int i = blockIdx.x*256 + threadIdx.x;
    int seg = 0;
#pragma unroll
    for (int k = 0; k < 6; k++) if (i >= a.end[k]) seg = k+1;
    if (seg >= 6) return;
    int base = seg ? a.end[seg-1] : 0;
    a.d[seg][i-base] = rtf(a.s[seg][i-base]);
}
__global__ void cvtb2_kernel(const float* __restrict__ a, __nv_bfloat16* __restrict__ da,
                             const float* __restrict__ b, __nv_bfloat16* __restrict__ db,
                             int n){
    int i = blockIdx.x*256 + threadIdx.x;
    if (i < n) da[i] = __float2bfloat16_rn(a[i]);
    else       db[i-n] = __float2bfloat16_rn(b[i-n]);
}

// ---------------- small prep kernels ----------------------------------------
__global__ void transpose_x_kernel(const float* __restrict__ x){
    __shared__ float tile[32][33];
    int b = blockIdx.z;
    int i0 = blockIdx.y*32, n0 = blockIdx.x*32;
    int tx = threadIdx.x, ty = threadIdx.y;
    tile[ty][tx] = x[(b*INCH + (i0+ty))*NPTS + n0+tx];
    __syncthreads();
    g_xT[(b*NPTS + (n0+ty))*INCH + i0+tx] = rtf(tile[tx][ty]);
}

__global__ void prep_kernel(const float* __restrict__ ag, const float* __restrict__ abeta,
                            const float* __restrict__ am, const float* __restrict__ av,
                            const float* __restrict__ ab1,
                            const float* __restrict__ pg, const float* __restrict__ pbeta,
                            const float* __restrict__ pm, const float* __restrict__ pv,
                            const float* __restrict__ pb1,
                            const float* __restrict__ W1, const float* __restrict__ pb2){
    int t = threadIdx.x;
    if (t < HID){
        float s = ag[t] / sqrtf(av[t] + EPSV);
        g_sA[t] = s;
        g_tA[t] = abeta[t] - am[t]*s + ab1[t]*s;
        float acc = 0.f;
        for (int c = 0; c < DIM; c++) acc += W1[t*DIM+c]*pb2[c];
        g_w1pb[t] = acc;
    }
    if (t < PHID){
        float s = pg[t] / sqrtf(pv[t] + EPSV);
        g_sP[t] = s;
        g_tP[t] = pbeta[t] - pm[t]*s + pb1[t]*s;
    }
}

__global__ void wc_kernel(const float* __restrict__ W1, const float* __restrict__ W2p){
    int h = blockIdx.x, p = threadIdx.x;
    float s = 0.f;
    for (int c = 0; c < DIM; c++) s += W1[h*DIM+c]*W2p[c*PHID+p];
    g_bWc[h*PHID+p] = __float2bfloat16_rn(s);
}

__global__ void init_cls_kernel(const float* __restrict__ cls){
    g_hx[(blockIdx.x*NP1)*DIM + threadIdx.x] = rtf(cls[threadIdx.x]);
}

__global__ void addpos_kernel(const float* __restrict__ pos_emb){
    int b = blockIdx.x, c = threadIdx.x;
    int o = (b*NP1)*DIM + c;
    g_qb[o] = __float2bfloat16_rn(__bfloat162float(g_qb[o]) + pos_emb[c]);
    g_v[o] += pos_emb[c];
}

// ---------------- KNN (chunked) ---------------------------------------------
__global__ __launch_bounds__(256) void knn_part_kernel(const float* __restrict__ pos){
    __shared__ float sx[256], sy[256], sz[256];
    int b = blockIdx.y, ch = blockIdx.z;
    const float* pb = pos + (size_t)b*3*NPTS;
    int j0 = ch*256;
    int t = threadIdx.x;
    sx[t] = pb[j0+t]; sy[t] = pb[NPTS+j0+t]; sz[t] = pb[2*NPTS+j0+t];
    __syncthreads();
    int qi = blockIdx.x*256 + t;
    float qx = pb[qi], qy = pb[NPTS+qi], qz = pb[2*NPTS+qi];
    float bd[KNN]; int bi[KNN];
#pragma unroll
    for (int i = 0; i < KNN; i++){ bd[i] = 3.4e38f; bi[i] = 0; }
    float maxv = 3.4e38f; int maxp = 0;
    for (int j = 0; j < 256; j++){
        float dx = qx - sx[j], dy = qy - sy[j], dz = qz - sz[j];
        float d = dx*dx + dy*dy + dz*dz;
        if (d < maxv){
            bd[maxp] = d; bi[maxp] = j0 + j;
            maxv = bd[0]; maxp = 0;
#pragma unroll
            for (int i = 1; i < KNN; i++)
                if (bd[i] > maxv){ maxv = bd[i]; maxp = i; }
        }
    }
    long base = ((long)(b*NPTS + qi)*NCH + ch)*KNN;
#pragma unroll
    for (int i = 0; i < KNN; i++){ g_pd[base+i] = bd[i]; g_pi[base+i] = bi[i]; }
}

__global__ __launch_bounds__(256) void knn_merge_kernel(){
    int b = blockIdx.y;
    int qi = blockIdx.x*256 + threadIdx.x;
    long base = (long)(b*NPTS + qi)*NCH*KNN;
    float bd[KNN]; int bi[KNN];
#pragma unroll
    for (int i = 0; i < KNN; i++){ bd[i] = 3.4e38f; bi[i] = 0; }
    float maxv = 3.4e38f; int maxp = 0;
    for (int j = 0; j < NCH*KNN; j++){
        float d = g_pd[base+j];
        if (d < maxv){
            bd[maxp] = d; bi[maxp] = g_pi[base+j];
            maxv = bd[0]; maxp = 0;
#pragma unroll
            for (int i = 1; i < KNN; i++)
                if (bd[i] > maxv){ maxv = bd[i]; maxp = i; }
        }
    }
    int ob = (b*NPTS + qi)*KNN;
#pragma unroll
    for (int i = 0; i < KNN; i++) g_idx[ob+i] = bi[i];
}

// ---------------- pos-MLP hidden --------------------------------------------
__global__ __launch_bounds__(256) void pos_hidden_kernel(const float* __restrict__ pos,
                                                         const float* __restrict__ pw1){
    int b = blockIdx.y, n = blockIdx.x;
    __shared__ float prx[KNN], pry[KNN], prz[KNN];
    int t = threadIdx.x;
    const float* pb = pos + (size_t)b*3*NPTS;
    if (t < KNN){
        int m = g_idx[(b*NPTS+n)*KNN + t];
        prx[t] = pb[n]        - pb[m];
        pry[t] = pb[NPTS+n]   - pb[NPTS+m];
        prz[t] = pb[2*NPTS+n] - pb[2*NPTS+m];
    }
    __syncthreads();
    for (int e = t; e < KNN*PHID; e += 256){
        int k = e >> 6, hh = e & 63;
        float z = pw1[hh*3+0]*prx[k] + pw1[hh*3+1]*pry[k] + pw1[hh*3+2]*prz[k];
        z = z*g_sP[hh] + g_tP[hh];
        z = fmaxf(z, 0.f);
        long o = ((long)(b*NPTS+n)*KNN + k)*PHID + hh;
        g_ph[o]  = rtf(z);
        g_phb[o] = __float2bfloat16_rn(z);
    }
}

// ---------------- tf32 GEMM: cp.async 4-stage, 1 barrier/iter, stride-20 smem
// EPI 0: C = acc + bias[n] ; EPI 1: C = rtf(acc + bias[n]) ; EPI 3: C = acc
// EPI 5: bf16 C = acc + bias[n]
template<int EPI>
__global__ __launch_bounds__(256,2) void gemm2(const float* __restrict__ A,
        const float* __restrict__ Bw, float* __restrict__ C,
        int M, int N, int K, const float* __restrict__ bias,
        long strideAb, long strideCb){
    extern __shared__ __align__(16) float sm[];
    A += (long)blockIdx.z*strideAb;
    C += (long)blockIdx.z*strideCb;
    const int t = threadIdx.x, lane = t&31, w = t>>5;
    const int wm = w>>2, wn = w&3;
    const int m0 = blockIdx.x*128, n0 = blockIdx.y*128;
    const uint32_t smb = (uint32_t)__cvta_generic_to_shared(sm);
    float acc[4][4][4];
#pragma unroll
    for (int i=0;i<4;i++)
#pragma unroll
      for (int j=0;j<4;j++)
#pragma unroll
        for (int c=0;c<4;c++) acc[i][j][c] = 0.f;

    const int nIter = K >> 4;
    auto prefetch = [&](int st, int kt){
#pragma unroll
        for (int l=0;l<2;l++){
            int g = t + (l<<8);
            int row = g>>2, kq = (g&3)<<2;
            int arow = m0 + row; if (arow >= M) arow = M - 1;
            uint32_t d = smb + (uint32_t)((st*5120 + row*20 + kq)<<2);
            cp16(d, A + (long)arow*K + (kt<<4) + kq);
            uint32_t d2 = smb + (uint32_t)((st*5120 + 2560 + row*20 + kq)<<2);
            cp16(d2, Bw + (long)(n0+row)*K + (kt<<4) + kq);
        }
        cpcommit();
    };
    prefetch(0, 0);
    prefetch(1, 1);
    prefetch(2, 2);

    for (int it = 0; it < nIter; ++it){
        if (it + 3 < nIter) cpwait2();
        else                cpwait0();
        __syncthreads();
        if (it+3 < nIter) prefetch((it+3)&3, it+3); else cpcommit();
        const float* sA = sm + (it&3)*5120;
        const float* sB = sA + 2560;
#pragma unroll
        for (int k8=0;k8<2;k8++){
            int kb = k8*8 + (lane&3);
            uint32_t af[4][4]; uint32_t bf[4][2];
#pragma unroll
            for (int i=0;i<4;i++){
                const float* p = sA + (wm*64 + i*16 + (lane>>2))*20 + kb;
                af[i][0]=__float_as_uint(p[0]);
                af[i][1]=__float_as_uint(p[160]);
                af[i][2]=__float_as_uint(p[4]);
                af[i][3]=__float_as_uint(p[164]);
            }
#pragma unroll
            for (int j=0;j<4;j++){
                const float* p = sB + (wn*32 + j*8 + (lane>>2))*20 + kb;
                bf[j][0]=__float_as_uint(p[0]);
                bf[j][1]=__float_as_uint(p[4]);
            }
#pragma unroll
            for (int i=0;i<4;i++)
#pragma unroll
                for (int j=0;j<4;j++)
                    mma_tf32(acc[i][j][0],acc[i][j][1],acc[i][j][2],acc[i][j][3],
                             af[i][0],af[i][1],af[i][2],af[i][3], bf[j][0],bf[j][1]);
        }
    }

    const int r0 = lane >> 2, cq = (lane & 3) << 1;
#pragma unroll
    for (int i=0;i<4;i++){
#pragma unroll
        for (int half=0; half<2; half++){
            int m = m0 + wm*64 + i*16 + r0 + half*8;
            if (m >= M) continue;
            if (EPI == 5){
                __nv_bfloat16* cb = (__nv_bfloat16*)C + (long)m*N;
#pragma unroll
                for (int j=0;j<4;j++){
                    int n = n0 + wn*32 + j*8 + cq;
                    float2 bv = *(const float2*)&bias[n];
                    __nv_bfloat162 o2 = __floats2bfloat162_rn(
                        acc[i][j][half*2+0] + bv.x, acc[i][j][half*2+1] + bv.y);
                    *(__nv_bfloat162*)&cb[n] = o2;
                }
            } else {
                float* crow = C + (long)m*N;
#pragma unroll
                for (int j=0;j<4;j++){
                    int n = n0 + wn*32 + j*8 + cq;
                    float2 o;
                    if (EPI == 0){
                        float2 bv = *(const float2*)&bias[n];
                        o.x = acc[i][j][half*2+0] + bv.x;
                        o.y = acc[i][j][half*2+1] + bv.y;
                    } else if (EPI == 1){
                        float2 bv = *(const float2*)&bias[n];
                        o.x = rtf(acc[i][j][half*2+0] + bv.x);
                        o.y = rtf(acc[i][j][half*2+1] + bv.y);
                    } else {
                        o.x = acc[i][j][half*2+0];
                        o.y = acc[i][j][half*2+1];
                    }
                    *(float2*)&crow[n] = o;
                }
            }
        }
    }
}

// ---------------- bf16 GEMM: m16n8k16, ldmatrix fragments, 4-stage cp.async --
// EPI 2: folded attn-hidden -> g_hid (bf16) ; EPI 3: fp32 C = acc ;
// EPI 4: softmax+agg -> g_agg
template<int EPI>
__global__ __launch_bounds__(256,2) void gemm2b(const __nv_bfloat16* __restrict__ A,
        const __nv_bfloat16* __restrict__ Bw, float* __restrict__ C,
        int M, int N, int K, long strideAb, long strideCb){
    extern __shared__ __align__(16) uint32_t smw[];
    A += (long)blockIdx.z*strideAb;
    C += (long)blockIdx.z*strideCb;
    const int t = threadIdx.x, lane = t&31, w = t>>5;
    const int wm = w>>2, wn = w&3;
    const int m0 = blockIdx.x*128, n0 = blockIdx.y*128;
    const uint32_t smb = (uint32_t)__cvta_generic_to_shared(smw);
    float acc[4][4][4];
#pragma unroll
    for (int i=0;i<4;i++)
#pragma unroll
      for (int j=0;j<4;j++)
#pragma unroll
        for (int c=0;c<4;c++) acc[i][j][c] = 0.f;

    // ldmatrix per-lane word offsets (within a stage)
    // A tile i: 4x m8n8 = rows [base..base+15] x k-words {0..3, 4..7}
    uint32_t aoff[4];
#pragma unroll
    for (int i=0;i<4;i++){
        int row = wm*64 + i*16 + (((lane>>3)&1)<<3) + (lane&7);
        aoff[i] = (uint32_t)(row*12 + ((lane>>4)<<2));
    }
    // B pair jj (covers j=2jj, 2jj+1): rows [base..base+15], words {0,4}
    uint32_t boff[2];
#pragma unroll
    for (int jj=0;jj<2;jj++){
        int row = wn*32 + jj*16 + ((lane>>4)<<3) + (lane&7);
        boff[jj] = (uint32_t)(1536 + row*12 + (((lane>>3)&1)<<2));
    }

    const int nIter = K >> 4;                  // k-step = 16 halves
    auto prefetch = [&](int st, int kt){
#pragma unroll
        for (int l=0;l<2;l++){
            int g = t + (l<<8);                // 0..511
            int row = g>>1;                    // 0..255
            int kqw = (g&1)<<2;                // word offset 0 or 4
            int kh  = (kt<<4) + ((g&1)<<3);    // half offset
            if (row < 128){
                int arow = m0 + row; if (arow >= M) arow = M - 1;
                uint32_t d = smb + (uint32_t)((st*3072 + row*12 + kqw)<<2);
                cp16(d, A + (long)arow*K + kh);
            } else {
                int brow = row - 128;
                uint32_t d = smb + (uint32_t)((st*3072 + 1536 + brow*12 + kqw)<<2);
                cp16(d, Bw + (long)(n0+brow)*K + kh);
            }
        }
        cpcommit();
    };
    prefetch(0, 0);
    prefetch(1, 1);
    prefetch(2, 2);

    for (int it = 0; it < nIter; ++it){
        if (it + 3 < nIter) cpwait2();
        else                cpwait0();
        __syncthreads();
        if (it+3 < nIter) prefetch((it+3)&3, it+3); else cpcommit();
        uint32_t sb = smb + (uint32_t)(((it&3)*3072)<<2);
        uint32_t af[4][4]; uint32_t bfr[2][4];
#pragma unroll
        for (int i=0;i<4;i++)
            ldsm4(af[i][0],af[i][1],af[i][2],af[i][3], sb + (aoff[i]<<2));
#pragma unroll
        for (int jj=0;jj<2;jj++)
            ldsm4(bfr[jj][0],bfr[jj][1],bfr[jj][2],bfr[jj][3], sb + (boff[jj]<<2));
#pragma unroll
        for (int i=0;i<4;i++)
#pragma unroll
            for (int j=0;j<4;j++)
                mma_bf16(acc[i][j][0],acc[i][j][1],acc[i][j][2],acc[i][j][3],
                         af[i][0],af[i][1],af[i][2],af[i][3],
                         bfr[j>>1][(j&1)*2], bfr[j>>1][(j&1)*2+1]);
    }

    const int r0 = lane >> 2, cq = (lane & 3) << 1;
    if (EPI == 4){
#pragma unroll
        for (int i=0;i<4;i++){
            int mrow = m0 + wm*64 + i*16;
            if (mrow >= M) continue;
            int colidx = mrow >> 4;            // b*NP1 + nn
            int b  = colidx / NP1;
            int nn = colidx - b*NP1;
            long pebase = (nn > 0) ? (long)((b*NPTS + nn-1)*KNN)*DIM : 0;
            int kk0 = r0;
#pragma unroll
            for (int j=0;j<4;j++){
                int c0 = n0 + wn*32 + j*8 + cq;
                float outv[2];
#pragma unroll
                for (int q=0;q<2;q++){
                    float l0 = acc[i][j][q], l1 = acc[i][j][2+q];
                    float mx = fmaxf(l0, l1);
                    mx = fmaxf(mx, __shfl_xor_sync(0xffffffffu, mx, 4));
                    mx = fmaxf(mx, __shfl_xor_sync(0xffffffffu, mx, 8));
                    mx = fmaxf(mx, __shfl_xor_sync(0xffffffffu, mx, 16));
                    float e0 = expf(l0 - mx), e1 = expf(l1 - mx);
                    float pv0 = 0.f, pv1 = 0.f;
                    if (nn > 0){
                        pv0 = g_pe[pebase + (long)kk0*DIM + c0 + q];
                        pv1 = g_pe[pebase + (long)(kk0+8)*DIM + c0 + q];
                    }
                    float s  = e0 + e1;
                    float ts = e0*pv0 + e1*pv1;
                    s  += __shfl_xor_sync(0xffffffffu, s, 4);
                    ts += __shfl_xor_sync(0xffffffffu, ts, 4);
                    s  += __shfl_xor_sync(0xffffffffu, s, 8);
                    ts += __shfl_xor_sync(0xffffffffu, ts, 8);
                    s  += __shfl_xor_sync(0xffffffffu, s, 16);
                    ts += __shfl_xor_sync(0xffffffffu, ts, 16);
                    float vv = g_v[(long)colidx*DIM + c0 + q];
                    outv[q] = rtf(vv + ts / s);
                }
                if (r0 == 0){
                    float2 o = make_float2(outv[0], outv[1]);
                    *(float2*)&g_agg[(long)colidx*DIM + c0] = o;
                }
            }
        }
        return;
    }
#pragma unroll
    for (int i=0;i<4;i++){
#pragma unroll
        for (int half=0; half<2; half++){
            int m = m0 + wm*64 + i*16 + r0 + half*8;
            if (m >= M) continue;
            if (EPI == 2){
                int b  = m >> 15;
                int n  = (m >> 4) & (NPTS-1);
                int kk = m & 15;
                int midx = g_idx[((b*NPTS)+n)*KNN + kk];
                const float* wq = g_w1q + (long)(b*NP1 + n + 1)*HID;
                const float* wk = g_w1k + (long)(b*NPTS + midx)*HID;
                __nv_bfloat16* dst = g_hid + (long)((b*NP1 + n + 1)*KNN + kk)*HID;
#pragma unroll
                for (int j=0;j<4;j++){
                    int h = n0 + wn*32 + j*8 + cq;
                    float2 q2 = *(const float2*)&wq[h];
                    float2 k2 = *(const float2*)&wk[h];
                    float2 p2 = *(const float2*)&g_w1pb[h];
                    float2 s2 = *(const float2*)&g_sA[h];
                    float2 t2 = *(const float2*)&g_tA[h];
                    float ox = fmaxf((acc[i][j][half*2+0] + q2.x - k2.x + p2.x)*s2.x + t2.x, 0.f);
                    float oy = fmaxf((acc[i][j][half*2+1] + q2.y - k2.y + p2.y)*s2.y + t2.y, 0.f);
                    __nv_bfloat162 o2 = __floats2bfloat162_rn(ox, oy);
                    *(__nv_bfloat162*)&dst[h] = o2;
                }
            } else {                      // EPI 3: fp32 C = acc
                float* crow = C + (long)m*N;
#pragma unroll
                for (int j=0;j<4;j++){
                    int n = n0 + wn*32 + j*8 + cq;
                    float2 o = make_float2(acc[i][j][half*2+0], acc[i][j][half*2+1]);
                    *(float2*)&crow[n] = o;
                }
            }
        }
    }
}

// ---------------- cls hidden -------------------------------------------------
__global__ void cls_hidden_kernel(){
    int b = blockIdx.x >> 4, kk = blockIdx.x & 15;
    long col = (long)(b*NP1)*KNN + kk;
    for (int h = threadIdx.x; h < HID; h += 256){
        float v = fmaxf(g_w1q[(long)(b*NP1)*HID + h]*g_sA[h] + g_tA[h], 0.f);
        g_hid[col*HID + h] = __float2bfloat16_rn(v);
    }
}

// ---------------- finalize outputs ------------------------------------------
__global__ void finalize1_kernel(const float* __restrict__ x, float* __restrict__ out){
    int gid = blockIdx.x*256 + threadIdx.x;
    int n  = gid % NPTS;
    int ch = (gid / NPTS) % DIM;
    int b  = gid / (NPTS*DIM);
    out[gid] = g_y[((b*NP1) + (n+1))*DIM + ch] + x[gid];
}
__global__ void finalize2_kernel(float* __restrict__ out){
    int t = threadIdx.x;
    int b = t / DIM, ch = t % DIM;
    out[BB*DIM*NPTS + t] = g_y[(b*NP1)*DIM + ch];
}

// ---------------- launch -----------------------------------------------------
extern "C" void kernel_launch(void* const* d_in, const int* in_sizes, int n_in,
                              void* d_out, int out_size){
    const float* x        = (const float*)d_in[0];
    const float* pos      = (const float*)d_in[1];
    const float* W_start  = (const float*)d_in[2];
    const float* b_start  = (const float*)d_in[3];
    const float* W_key    = (const float*)d_in[4];
    const float* b_key    = (const float*)d_in[5];
    const float* W_query  = (const float*)d_in[6];
    const float* b_query  = (const float*)d_in[7];
    const float* W_value  = (const float*)d_in[8];
    const float* b_value  = (const float*)d_in[9];
    const float* pos_W1   = (const float*)d_in[10];
    const float* pos_b1   = (const float*)d_in[11];
    const float* pos_g    = (const float*)d_in[12];
    const float* pos_beta = (const float*)d_in[13];
    const float* pos_m    = (const float*)d_in[14];
    const float* pos_v    = (const float*)d_in[15];
    const float* pos_W2   = (const float*)d_in[16];
    const float* pos_b2   = (const float*)d_in[17];
    const float* attn_W1  = (const float*)d_in[18];
    const float* attn_b1  = (const float*)d_in[19];
    const float* attn_g   = (const float*)d_in[20];
    const float* attn_beta= (const float*)d_in[21];
    const float* attn_m   = (const float*)d_in[22];
    const float* attn_v   = (const float*)d_in[23];
    const float* attn_W2  = (const float*)d_in[24];
    const float* attn_b2  = (const float*)d_in[25];
    const float* W_end    = (const float*)d_in[26];
    const float* b_end    = (const float*)d_in[27];
    const float* pos_emb  = (const float*)d_in[28];
    const float* cls_tok  = (const float*)d_in[29];
    float* out = (float*)d_out;
    (void)attn_b2;

    float *pxT,*phx,*pv,*pph,*ppe,*pagg,*py,*pw1q,*pw1k;
    float *prWs,*prWq,*prWk,*prWv,*prP2,*prWe;
    __nv_bfloat16 *pphb,*phid,*pbWc,*pbW2,*pbW1,*pqb,*pkb;
    cudaGetSymbolAddress((void**)&pxT,  g_xT);
    cudaGetSymbolAddress((void**)&phx,  g_hx);
    cudaGetSymbolAddress((void**)&pqb,  g_qb);
    cudaGetSymbolAddress((void**)&pkb,  g_kb);
    cudaGetSymbolAddress((void**)&pv,   g_v);
    cudaGetSymbolAddress((void**)&pph,  g_ph);
    cudaGetSymbolAddress((void**)&pphb, g_phb);
    cudaGetSymbolAddress((void**)&ppe,  g_pe);
    cudaGetSymbolAddress((void**)&phid, g_hid);
    cudaGetSymbolAddress((void**)&pagg, g_agg);
    cudaGetSymbolAddress((void**)&py,   g_y);
    cudaGetSymbolAddress((void**)&pw1q, g_w1q);
    cudaGetSymbolAddress((void**)&pw1k, g_w1k);
    cudaGetSymbolAddress((void**)&pbWc, g_bWc);
    cudaGetSymbolAddress((void**)&pbW2, g_bW2);
    cudaGetSymbolAddress((void**)&pbW1, g_bW1);
    cudaGetSymbolAddress((void**)&prWs, g_rWs);
    cudaGetSymbolAddress((void**)&prWq, g_rWq);
    cudaGetSymbolAddress((void**)&prWk, g_rWk);
    cudaGetSymbolAddress((void**)&prWv, g_rWv);
    cudaGetSymbolAddress((void**)&prP2, g_rP2);
    cudaGetSymbolAddress((void**)&prWe, g_rWe);

    cudaFuncSetAttribute(gemm2<0>, cudaFuncAttributeMaxDynamicSharedMemorySize, GSMEM);
    cudaFuncSetAttribute(gemm2<1>, cudaFuncAttributeMaxDynamicSharedMemorySize, GSMEM);
    cudaFuncSetAttribute(gemm2<5>, cudaFuncAttributeMaxDynamicSharedMemorySize, GSMEM);
    cudaFuncSetAttribute(gemm2b<2>, cudaFuncAttributeMaxDynamicSharedMemorySize, GSMEMB);
    cudaFuncSetAttribute(gemm2b<3>, cudaFuncAttributeMaxDynamicSharedMemorySize, GSMEMB);
    cudaFuncSetAttribute(gemm2b<4>, cudaFuncAttributeMaxDynamicSharedMemorySize, GSMEMB);

    // prep + weight rounding/conversion
    transpose_x_kernel<<<dim3(NPTS/32, INCH/32, BB), dim3(32,32)>>>(x);
    prep_kernel<<<1,1024>>>(attn_g, attn_beta, attn_m, attn_v, attn_b1,
                            pos_g, pos_beta, pos_m, pos_v, pos_b1,
                            attn_W1, pos_b2);
    wc_kernel<<<HID, PHID>>>(attn_W1, pos_W2);
    cvtb2_kernel<<<(2*DIM*HID)/256, 256>>>(attn_W2, pbW2, attn_W1, pbW1, DIM*HID);
    {
        RCArgs rc;
        rc.s[0]=W_start; rc.d[0]=prWs;
        rc.s[1]=W_query; rc.d[1]=prWq;
        rc.s[2]=W_key;   rc.d[2]=prWk;
        rc.s[3]=W_value; rc.d[3]=prWv;
        rc.s[4]=pos_W2;  rc.d[4]=prP2;
        rc.s[5]=W_end;   rc.d[5]=prWe;
        int sz[6] = {DIM*INCH, DIM*DIM, DIM*DIM, DIM*DIM, DIM*PHID, INCH*DIM};
        int acc = 0;
        for (int k = 0; k < 6; k++){ acc += sz[k]; rc.end[k] = acc; }
        roundcpy_all_kernel<<<(acc + 255)/256, 256>>>(rc);
    }
    init_cls_kernel<<<BB, DIM>>>(cls_tok);
    knn_part_kernel<<<dim3(NPTS/256, BB, NCH), 256>>>(pos);
    knn_merge_kernel<<<dim3(NPTS/256, BB), 256>>>();

    // hx[1:] = W_start @ x + b
    gemm2<1><<<dim3(NPTS/128, DIM/128, BB), 256, GSMEM>>>(
        pxT, prWs, phx + DIM, NPTS, DIM, INCH, b_start,
        (long)NPTS*INCH, (long)NP1*DIM);

    // q,k (bf16 output; feed only the damped logit path) ; v (fp32, critical)
    gemm2<5><<<dim3((BB*NP1+127)/128, DIM/128, 1), 256, GSMEM>>>(
        phx, prWq, (float*)pqb, BB*NP1, DIM, DIM, b_query, 0, 0);
    gemm2<5><<<dim3((BB*NP1+127)/128, DIM/128, 1), 256, GSMEM>>>(
        phx, prWk, (float*)pkb, BB*NP1, DIM, DIM, b_key, 0, 0);
    gemm2<0><<<dim3((BB*NP1+127)/128, DIM/128, 1), 256, GSMEM>>>(
        phx, prWv, pv, BB*NP1, DIM, DIM, b_value, 0, 0);

    addpos_kernel<<<BB, DIM>>>(pos_emb);

    // w1q, w1k (bf16 cores, fp32 out)
    gemm2b<3><<<dim3((BB*NP1+127)/128, HID/128, 1), 256, GSMEMB>>>(
        pqb, pbW1, pw1q, BB*NP1, HID, DIM, 0, 0);
    gemm2b<3><<<dim3(NPTS/128, HID/128, BB), 256, GSMEMB>>>(
        pkb + DIM, pbW1, pw1k, NPTS, HID, DIM,
        (long)NP1*DIM, (long)NPTS*HID);

    // pos-MLP (tf32 — feeds agg directly, precision-critical)
    pos_hidden_kernel<<<dim3(NPTS, BB), 256>>>(pos, pos_W1);
    gemm2<0><<<dim3(NK/128, DIM/128, 1), 256, GSMEM>>>(
        pph, prP2, ppe, NK, DIM, PHID, pos_b2, 0, 0);

    // folded attn hidden (bf16 core)
    gemm2b<2><<<dim3(NK/128, HID/128, 1), 256, GSMEMB>>>(
        pphb, pbWc, nullptr, NK, HID, PHID, 0, 0);
    cls_hidden_kernel<<<BB*KNN, 256>>>();

    // logits + fused softmax/aggregate (bf16 core)
    gemm2b<4><<<dim3((NCOL+127)/128, DIM/128, 1), 256, GSMEMB>>>(
        phid, pbW2, nullptr, NCOL, DIM, HID, 0, 0);

    // y = W_end @ agg + b (tf32, critical)
    gemm2<0><<<dim3((BB*NP1+127)/128, DIM/128, 1), 256, GSMEM>>>(
        pagg, prWe, py, BB*NP1, DIM, DIM, b_end, 0, 0);

    finalize1_kernel<<<(BB*DIM*NPTS)/256, 256>>>(x, out);
    finalize2_kernel<<<1, BB*DIM>>>(out);
}

// round 13
// speedup vs baseline: 1.5669x; 1.0194x over previous
#include <cuda_runtime.h>
#include <cuda_bf16.h>
#include <math.h>
#include <stdint.h>

#define BB 4
#define INCH 256
#define NPTS 2048
#define NP1 2049
#define DIM 256
#define KNN 16
#define PHID 64
#define HID 1024
#define NCOL (BB*NP1*KNN)   /* 131136 */
#define NK   (BB*NPTS*KNN)  /* 131072 */
#define NCH  8
#define EPSV 1e-5f
#define GSMEM  81920        /* tf32: 4 stages * (128+128)*20 words * 4B */
#define GSMEMB 81920        /* bf16 k32: 4 stages * (128+128)*20 words * 4B */

// ---------------- scratch ----------------------------------------------------
__device__ float g_xT[BB*NPTS*INCH];
__device__ float g_hx[BB*NP1*DIM];
__device__ __nv_bfloat16 g_qb[BB*NP1*DIM];
__device__ __nv_bfloat16 g_kb[BB*NP1*DIM];
__device__ float g_v [BB*NP1*DIM];
__device__ int   g_idx[BB*NPTS*KNN];
__device__ float g_pd[BB*NPTS*NCH*KNN];
__device__ int   g_pi[BB*NPTS*NCH*KNN];
__device__ float g_ph [NK*PHID];
__device__ __nv_bfloat16 g_phb[NK*PHID];
__device__ float g_pe [(long)NK*DIM];
__device__ __nv_bfloat16 g_hid[(long)NCOL*HID];
__device__ float g_agg[BB*NP1*DIM];
__device__ float g_y  [BB*NP1*DIM];
__device__ float g_w1q[BB*NP1*HID];
__device__ float g_w1k[BB*NPTS*HID];
__device__ __nv_bfloat16 g_bWc[HID*PHID];
__device__ __nv_bfloat16 g_bW2[DIM*HID];
__device__ __nv_bfloat16 g_bW1[HID*DIM];
__device__ float g_sA[HID], g_tA[HID], g_w1pb[HID];
__device__ float g_sP[PHID], g_tP[PHID];
__device__ float g_rWs[DIM*INCH];
__device__ float g_rWq[DIM*DIM];
__device__ float g_rWk[DIM*DIM];
__device__ float g_rWv[DIM*DIM];
__device__ float g_rP2[DIM*PHID];
__device__ float g_rWe[INCH*DIM];

// ---------------- helpers ----------------------------------------------------
__device__ __forceinline__ float rtf(float x){
    uint32_t r; asm("cvt.rna.tf32.f32 %0, %1;" : "=r"(r) : "f"(x));
    return __uint_as_float(r);
}
__device__ __forceinline__ void mma_tf32(float&c0,float&c1,float&c2,float&c3,
   uint32_t a0,uint32_t a1,uint32_t a2,uint32_t a3,uint32_t b0,uint32_t b1){
  asm volatile("mma.sync.aligned.m16n8k8.row.col.f32.tf32.tf32.f32 "
    "{%0,%1,%2,%3}, {%4,%5,%6,%7}, {%8,%9}, {%0,%1,%2,%3};\n"
    : "+f"(c0),"+f"(c1),"+f"(c2),"+f"(c3)
    : "r"(a0),"r"(a1),"r"(a2),"r"(a3),"r"(b0),"r"(b1));
}
__device__ __forceinline__ void mma_bf16(float&c0,float&c1,float&c2,float&c3,
   uint32_t a0,uint32_t a1,uint32_t a2,uint32_t a3,uint32_t b0,uint32_t b1){
  asm volatile("mma.sync.aligned.m16n8k16.row.col.f32.bf16.bf16.f32 "
    "{%0,%1,%2,%3}, {%4,%5,%6,%7}, {%8,%9}, {%0,%1,%2,%3};\n"
    : "+f"(c0),"+f"(c1),"+f"(c2),"+f"(c3)
    : "r"(a0),"r"(a1),"r"(a2),"r"(a3),"r"(b0),"r"(b1));
}
__device__ __forceinline__ void ldsm4(uint32_t&r0,uint32_t&r1,uint32_t&r2,uint32_t&r3,
                                      uint32_t addr){
  asm volatile("ldmatrix.sync.aligned.m8n8.x4.shared.b16 {%0,%1,%2,%3}, [%4];"
    : "=r"(r0),"=r"(r1),"=r"(r2),"=r"(r3) : "r"(addr));
}
__device__ __forceinline__ void cp16(uint32_t dst, const void* src){
    asm volatile("cp.async.cg.shared.global [%0], [%1], 16;" :: "r"(dst), "l"(src));
}
__device__ __forceinline__ void cpcommit(){ asm volatile("cp.async.commit_group;"); }
__device__ __forceinline__ void cpwait2(){ asm volatile("cp.async.wait_group 2;"); }
__device__ __forceinline__ void cpwait0(){ asm volatile("cp.async.wait_group 0;"); }

// ---------------- merged weight rounding ------------------------------------
struct RCArgs {
    const float* s[6];
    float* d[6];
    int end[6];
};
__global__ void roundcpy_all_kernel(RCArgs a){
    int i = blockIdx.x*256 + threadIdx.x;
    int seg = 0;
#pragma unroll
    for (int k = 0; k < 6; k++) if (i >= a.end[k]) seg = k+1;
    if (seg >= 6) return;
    int base = seg ? a.end[seg-1] : 0;
    a.d[seg][i-base] = rtf(a.s[seg][i-base]);
}
__global__ void cvtb2_kernel(const float* __restrict__ a, __nv_bfloat16* __restrict__ da,
                             const float* __restrict__ b, __nv_bfloat16* __restrict__ db,
                             int n){
    int i = blockIdx.x*256 + threadIdx.x;
    if (i < n) da[i] = __float2bfloat16_rn(a[i]);
    else       db[i-n] = __float2bfloat16_rn(b[i-n]);
}

// ---------------- small prep kernels ----------------------------------------
__global__ void transpose_x_kernel(const float* __restrict__ x){
    __shared__ float tile[32][33];
    int b = blockIdx.z;
    int i0 = blockIdx.y*32, n0 = blockIdx.x*32;
    int tx = threadIdx.x, ty = threadIdx.y;
    tile[ty][tx] = x[(b*INCH + (i0+ty))*NPTS + n0+tx];
    __syncthreads();
    g_xT[(b*NPTS + (n0+ty))*INCH + i0+tx] = rtf(tile[tx][ty]);
}

__global__ void prep_kernel(const float* __restrict__ ag, const float* __restrict__ abeta,
                            const float* __restrict__ am, const float* __restrict__ av,
                            const float* __restrict__ ab1,
                            const float* __restrict__ pg, const float* __restrict__ pbeta,
                            const float* __restrict__ pm, const float* __restrict__ pv,
                            const float* __restrict__ pb1,
                            const float* __restrict__ W1, const float* __restrict__ pb2){
    int t = threadIdx.x;
    if (t < HID){
        float s = ag[t] / sqrtf(av[t] + EPSV);
        g_sA[t] = s;
        g_tA[t] = abeta[t] - am[t]*s + ab1[t]*s;
        float acc = 0.f;
        for (int c = 0; c < DIM; c++) acc += W1[t*DIM+c]*pb2[c];
        g_w1pb[t] = acc;
    }
    if (t < PHID){
        float s = pg[t] / sqrtf(pv[t] + EPSV);
        g_sP[t] = s;
        g_tP[t] = pbeta[t] - pm[t]*s + pb1[t]*s;
    }
}

__global__ void wc_kernel(const float* __restrict__ W1, const float* __restrict__ W2p){
    int h = blockIdx.x, p = threadIdx.x;
    float s = 0.f;
    for (int c = 0; c < DIM; c++) s += W1[h*DIM+c]*W2p[c*PHID+p];
    g_bWc[h*PHID+p] = __float2bfloat16_rn(s);
}

__global__ void init_cls_kernel(const float* __restrict__ cls){
    g_hx[(blockIdx.x*NP1)*DIM + threadIdx.x] = rtf(cls[threadIdx.x]);
}

__global__ void addpos_kernel(const float* __restrict__ pos_emb){
    int b = blockIdx.x, c = threadIdx.x;
    int o = (b*NP1)*DIM + c;
    g_qb[o] = __float2bfloat16_rn(__bfloat162float(g_qb[o]) + pos_emb[c]);
    g_v[o] += pos_emb[c];
}

// ---------------- KNN (chunked) ---------------------------------------------
__global__ __launch_bounds__(256) void knn_part_kernel(const float* __restrict__ pos){
    __shared__ float sx[256], sy[256], sz[256];
    int b = blockIdx.y, ch = blockIdx.z;
    const float* pb = pos + (size_t)b*3*NPTS;
    int j0 = ch*256;
    int t = threadIdx.x;
    sx[t] = pb[j0+t]; sy[t] = pb[NPTS+j0+t]; sz[t] = pb[2*NPTS+j0+t];
    __syncthreads();
    int qi = blockIdx.x*256 + t;
    float qx = pb[qi], qy = pb[NPTS+qi], qz = pb[2*NPTS+qi];
    float bd[KNN]; int bi[KNN];
#pragma unroll
    for (int i = 0; i < KNN; i++){ bd[i] = 3.4e38f; bi[i] = 0; }
    float maxv = 3.4e38f; int maxp = 0;
    for (int j = 0; j < 256; j++){
        float dx = qx - sx[j], dy = qy - sy[j], dz = qz - sz[j];
        float d = dx*dx + dy*dy + dz*dz;
        if (d < maxv){
            bd[maxp] = d; bi[maxp] = j0 + j;
            maxv = bd[0]; maxp = 0;
#pragma unroll
            for (int i = 1; i < KNN; i++)
                if (bd[i] > maxv){ maxv = bd[i]; maxp = i; }
        }
    }
    long base = ((long)(b*NPTS + qi)*NCH + ch)*KNN;
#pragma unroll
    for (int i = 0; i < KNN; i++){ g_pd[base+i] = bd[i]; g_pi[base+i] = bi[i]; }
}

__global__ __launch_bounds__(256) void knn_merge_kernel(){
    int b = blockIdx.y;
    int qi = blockIdx.x*256 + threadIdx.x;
    long base = (long)(b*NPTS + qi)*NCH*KNN;
    float bd[KNN]; int bi[KNN];
#pragma unroll
    for (int i = 0; i < KNN; i++){ bd[i] = 3.4e38f; bi[i] = 0; }
    float maxv = 3.4e38f; int maxp = 0;
    for (int j = 0; j < NCH*KNN; j++){
        float d = g_pd[base+j];
        if (d < maxv){
            bd[maxp] = d; bi[maxp] = g_pi[base+j];
            maxv = bd[0]; maxp = 0;
#pragma unroll
            for (int i = 1; i < KNN; i++)
                if (bd[i] > maxv){ maxv = bd[i]; maxp = i; }
        }
    }
    int ob = (b*NPTS + qi)*KNN;
#pragma unroll
    for (int i = 0; i < KNN; i++) g_idx[ob+i] = bi[i];
}

// ---------------- pos-MLP hidden --------------------------------------------
__global__ __launch_bounds__(256) void pos_hidden_kernel(const float* __restrict__ pos,
                                                         const float* __restrict__ pw1){
    int b = blockIdx.y, n = blockIdx.x;
    __shared__ float prx[KNN], pry[KNN], prz[KNN];
    int t = threadIdx.x;
    const float* pb = pos + (size_t)b*3*NPTS;
    if (t < KNN){
        int m = g_idx[(b*NPTS+n)*KNN + t];
        prx[t] = pb[n]        - pb[m];
        pry[t] = pb[NPTS+n]   - pb[NPTS+m];
        prz[t] = pb[2*NPTS+n] - pb[2*NPTS+m];
    }
    __syncthreads();
    for (int e = t; e < KNN*PHID; e += 256){
        int k = e >> 6, hh = e & 63;
        float z = pw1[hh*3+0]*prx[k] + pw1[hh*3+1]*pry[k] + pw1[hh*3+2]*prz[k];
        z = z*g_sP[hh] + g_tP[hh];
        z = fmaxf(z, 0.f);
        long o = ((long)(b*NPTS+n)*KNN + k)*PHID + hh;
        g_ph[o]  = rtf(z);
        g_phb[o] = __float2bfloat16_rn(z);
    }
}

// ---------------- tf32 GEMM: cp.async 4-stage, 1 barrier/iter, stride-20 smem
// EPI 0: C = acc + bias[n] ; EPI 1: C = rtf(acc + bias[n]) ; EPI 5: bf16 out
template<int EPI>
__global__ __launch_bounds__(256,2) void gemm2(const float* __restrict__ A,
        const float* __restrict__ Bw, float* __restrict__ C,
        int M, int N, int K, const float* __restrict__ bias,
        long strideAb, long strideCb){
    extern __shared__ __align__(16) float sm[];
    A += (long)blockIdx.z*strideAb;
    C += (long)blockIdx.z*strideCb;
    const int t = threadIdx.x, lane = t&31, w = t>>5;
    const int wm = w>>2, wn = w&3;
    const int m0 = blockIdx.x*128, n0 = blockIdx.y*128;
    const uint32_t smb = (uint32_t)__cvta_generic_to_shared(sm);
    float acc[4][4][4];
#pragma unroll
    for (int i=0;i<4;i++)
#pragma unroll
      for (int j=0;j<4;j++)
#pragma unroll
        for (int c=0;c<4;c++) acc[i][j][c] = 0.f;

    const int nIter = K >> 4;
    auto prefetch = [&](int st, int kt){
#pragma unroll
        for (int l=0;l<2;l++){
            int g = t + (l<<8);
            int row = g>>2, kq = (g&3)<<2;
            int arow = m0 + row; if (arow >= M) arow = M - 1;
            uint32_t d = smb + (uint32_t)((st*5120 + row*20 + kq)<<2);
            cp16(d, A + (long)arow*K + (kt<<4) + kq);
            uint32_t d2 = smb + (uint32_t)((st*5120 + 2560 + row*20 + kq)<<2);
            cp16(d2, Bw + (long)(n0+row)*K + (kt<<4) + kq);
        }
        cpcommit();
    };
    prefetch(0, 0);
    prefetch(1, 1);
    prefetch(2, 2);

    for (int it = 0; it < nIter; ++it){
        if (it + 3 < nIter) cpwait2();
        else                cpwait0();
        __syncthreads();
        if (it+3 < nIter) prefetch((it+3)&3, it+3); else cpcommit();
        const float* sA = sm + (it&3)*5120;
        const float* sB = sA + 2560;
#pragma unroll
        for (int k8=0;k8<2;k8++){
            int kb = k8*8 + (lane&3);
            uint32_t af[4][4]; uint32_t bf[4][2];
#pragma unroll
            for (int i=0;i<4;i++){
                const float* p = sA + (wm*64 + i*16 + (lane>>2))*20 + kb;
                af[i][0]=__float_as_uint(p[0]);
                af[i][1]=__float_as_uint(p[160]);
                af[i][2]=__float_as_uint(p[4]);
                af[i][3]=__float_as_uint(p[164]);
            }
#pragma unroll
            for (int j=0;j<4;j++){
                const float* p = sB + (wn*32 + j*8 + (lane>>2))*20 + kb;
                bf[j][0]=__float_as_uint(p[0]);
                bf[j][1]=__float_as_uint(p[4]);
            }
#pragma unroll
            for (int i=0;i<4;i++)
#pragma unroll
                for (int j=0;j<4;j++)
                    mma_tf32(acc[i][j][0],acc[i][j][1],acc[i][j][2],acc[i][j][3],
                             af[i][0],af[i][1],af[i][2],af[i][3], bf[j][0],bf[j][1]);
        }
    }

    const int r0 = lane >> 2, cq = (lane & 3) << 1;
#pragma unroll
    for (int i=0;i<4;i++){
#pragma unroll
        for (int half=0; half<2; half++){
            int m = m0 + wm*64 + i*16 + r0 + half*8;
            if (m >= M) continue;
            if (EPI == 5){
                __nv_bfloat16* cb = (__nv_bfloat16*)C + (long)m*N;
#pragma unroll
                for (int j=0;j<4;j++){
                    int n = n0 + wn*32 + j*8 + cq;
                    float2 bv = *(const float2*)&bias[n];
                    __nv_bfloat162 o2 = __floats2bfloat162_rn(
                        acc[i][j][half*2+0] + bv.x, acc[i][j][half*2+1] + bv.y);
                    *(__nv_bfloat162*)&cb[n] = o2;
                }
            } else {
                float* crow = C + (long)m*N;
#pragma unroll
                for (int j=0;j<4;j++){
                    int n = n0 + wn*32 + j*8 + cq;
                    float2 o;
                    if (EPI == 0){
                        float2 bv = *(const float2*)&bias[n];
                        o.x = acc[i][j][half*2+0] + bv.x;
                        o.y = acc[i][j][half*2+1] + bv.y;
                    } else if (EPI == 1){
                        float2 bv = *(const float2*)&bias[n];
                        o.x = rtf(acc[i][j][half*2+0] + bv.x);
                        o.y = rtf(acc[i][j][half*2+1] + bv.y);
                    } else {
                        o.x = acc[i][j][half*2+0];
                        o.y = acc[i][j][half*2+1];
                    }
                    *(float2*)&crow[n] = o;
                }
            }
        }
    }
}

// ---------------- bf16 GEMM: m16n8k16 x2 per stage (k32), ldmatrix, 4-stage --
// EPI 2: folded attn-hidden -> g_hid (bf16) ; EPI 3: fp32 C = acc ;
// EPI 4: softmax+agg -> g_agg
template<int EPI>
__global__ __launch_bounds__(256,2) void gemm2b(const __nv_bfloat16* __restrict__ A,
        const __nv_bfloat16* __restrict__ Bw, float* __restrict__ C,
        int M, int N, int K, long strideAb, long strideCb){
    extern __shared__ __align__(16) uint32_t smw[];
    A += (long)blockIdx.z*strideAb;
    C += (long)blockIdx.z*strideCb;
    const int t = threadIdx.x, lane = t&31, w = t>>5;
    const int wm = w>>2, wn = w&3;
    const int m0 = blockIdx.x*128, n0 = blockIdx.y*128;
    const uint32_t smb = (uint32_t)__cvta_generic_to_shared(smw);
    float acc[4][4][4];
#pragma unroll
    for (int i=0;i<4;i++)
#pragma unroll
      for (int j=0;j<4;j++)
#pragma unroll
        for (int c=0;c<4;c++) acc[i][j][c] = 0.f;

    // ldmatrix per-lane base word offsets (k-sub 0; add 8 words for k-sub 1)
    uint32_t aoff[4];
#pragma unroll
    for (int i=0;i<4;i++){
        int row = wm*64 + i*16 + (((lane>>3)&1)<<3) + (lane&7);
        aoff[i] = (uint32_t)(row*20 + ((lane>>4)<<2));
    }
    uint32_t boff[2];
#pragma unroll
    for (int jj=0;jj<2;jj++){
        int row = wn*32 + jj*16 + ((lane>>4)<<3) + (lane&7);
        boff[jj] = (uint32_t)(2560 + row*20 + (((lane>>3)&1)<<2));
    }

    const int nIter = K >> 5;                  // k-step = 32 halves
    auto prefetch = [&](int st, int kt){
        if (kt < nIter){
#pragma unroll
            for (int l=0;l<4;l++){
                int g = t + (l<<8);            // 0..1023
                int row = g>>2;                // 0..255
                int kw  = (g&3)<<2;            // word offset 0,4,8,12
                int kh  = (kt<<5) + ((g&3)<<3);// half offset
                if (row < 128){
                    int arow = m0 + row; if (arow >= M) arow = M - 1;
                    uint32_t d = smb + (uint32_t)((st*5120 + row*20 + kw)<<2);
                    cp16(d, A + (long)arow*K + kh);
                } else {
                    int brow = row - 128;
                    uint32_t d = smb + (uint32_t)((st*5120 + 2560 + brow*20 + kw)<<2);
                    cp16(d, Bw + (long)(n0+brow)*K + kh);
                }
            }
        }
        cpcommit();
    };
    prefetch(0, 0);
    prefetch(1, 1);
    prefetch(2, 2);

    for (int it = 0; it < nIter; ++it){
        if (it + 3 < nIter) cpwait2();
        else                cpwait0();
        __syncthreads();
        prefetch((it+3)&3, it+3);
        uint32_t sb = smb + (uint32_t)(((it&3)*5120)<<2);
#pragma unroll
        for (int s=0;s<2;s++){
            uint32_t so = sb + (uint32_t)(s*32);   // +8 words
            uint32_t af[4][4]; uint32_t bfr[2][4];
#pragma unroll
            for (int i=0;i<4;i++)
                ldsm4(af[i][0],af[i][1],af[i][2],af[i][3], so + (aoff[i]<<2));
#pragma unroll
            for (int jj=0;jj<2;jj++)
                ldsm4(bfr[jj][0],bfr[jj][1],bfr[jj][2],bfr[jj][3], so + (boff[jj]<<2));
#pragma unroll
            for (int i=0;i<4;i++)
#pragma unroll
                for (int j=0;j<4;j++)
                    mma_bf16(acc[i][j][0],acc[i][j][1],acc[i][j][2],acc[i][j][3],
                             af[i][0],af[i][1],af[i][2],af[i][3],
                             bfr[j>>1][(j&1)*2], bfr[j>>1][(j&1)*2+1]);
        }
    }

    const int r0 = lane >> 2, cq = (lane & 3) << 1;
    if (EPI == 4){
#pragma unroll
        for (int i=0;i<4;i++){
            int mrow = m0 + wm*64 + i*16;
            if (mrow >= M) continue;
            int colidx = mrow >> 4;            // b*NP1 + nn
            int b  = colidx / NP1;
            int nn = colidx - b*NP1;
            long pebase = (nn > 0) ? (long)((b*NPTS + nn-1)*KNN)*DIM : 0;
            int kk0 = r0;
#pragma unroll
            for (int j=0;j<4;j++){
                int c0 = n0 + wn*32 + j*8 + cq;
                float outv[2];
#pragma unroll
                for (int q=0;q<2;q++){
                    float l0 = acc[i][j][q], l1 = acc[i][j][2+q];
                    float mx = fmaxf(l0, l1);
                    mx = fmaxf(mx, __shfl_xor_sync(0xffffffffu, mx, 4));
                    mx = fmaxf(mx, __shfl_xor_sync(0xffffffffu, mx, 8));
                    mx = fmaxf(mx, __shfl_xor_sync(0xffffffffu, mx, 16));
                    float e0 = expf(l0 - mx), e1 = expf(l1 - mx);
                    float pv0 = 0.f, pv1 = 0.f;
                    if (nn > 0){
                        pv0 = g_pe[pebase + (long)kk0*DIM + c0 + q];
                        pv1 = g_pe[pebase + (long)(kk0+8)*DIM + c0 + q];
                    }
                    float s  = e0 + e1;
                    float ts = e0*pv0 + e1*pv1;
                    s  += __shfl_xor_sync(0xffffffffu, s, 4);
                    ts += __shfl_xor_sync(0xffffffffu, ts, 4);
                    s  += __shfl_xor_sync(0xffffffffu, s, 8);
                    ts += __shfl_xor_sync(0xffffffffu, ts, 8);
                    s  += __shfl_xor_sync(0xffffffffu, s, 16);
                    ts += __shfl_xor_sync(0xffffffffu, ts, 16);
                    float vv = g_v[(long)colidx*DIM + c0 + q];
                    outv[q] = rtf(vv + ts / s);
                }
                if (r0 == 0){
                    float2 o = make_float2(outv[0], outv[1]);
                    *(float2*)&g_agg[(long)colidx*DIM + c0] = o;
                }
            }
        }
        return;
    }
#pragma unroll
    for (int i=0;i<4;i++){
#pragma unroll
        for (int half=0; half<2; half++){
            int m = m0 + wm*64 + i*16 + r0 + half*8;
            if (m >= M) continue;
            if (EPI == 2){
                int b  = m >> 15;
                int n  = (m >> 4) & (NPTS-1);
                int kk = m & 15;
                int midx = g_idx[((b*NPTS)+n)*KNN + kk];
                const float* wq = g_w1q + (long)(b*NP1 + n + 1)*HID;
                const float* wk = g_w1k + (long)(b*NPTS + midx)*HID;
                __nv_bfloat16* dst = g_hid + (long)((b*NP1 + n + 1)*KNN + kk)*HID;
#pragma unroll
                for (int j=0;j<4;j++){
                    int h = n0 + wn*32 + j*8 + cq;
                    float2 q2 = *(const float2*)&wq[h];
                    float2 k2 = *(const float2*)&wk[h];
                    float2 p2 = *(const float2*)&g_w1pb[h];
                    float2 s2 = *(const float2*)&g_sA[h];
                    float2 t2 = *(const float2*)&g_tA[h];
                    float ox = fmaxf((acc[i][j][half*2+0] + q2.x - k2.x + p2.x)*s2.x + t2.x, 0.f);
                    float oy = fmaxf((acc[i][j][half*2+1] + q2.y - k2.y + p2.y)*s2.y + t2.y, 0.f);
                    __nv_bfloat162 o2 = __floats2bfloat162_rn(ox, oy);
                    *(__nv_bfloat162*)&dst[h] = o2;
                }
            } else {                      // EPI 3: fp32 C = acc
                float* crow = C + (long)m*N;
#pragma unroll
                for (int j=0;j<4;j++){
                    int n = n0 + wn*32 + j*8 + cq;
                    float2 o = make_float2(acc[i][j][half*2+0], acc[i][j][half*2+1]);
                    *(float2*)&crow[n] = o;
                }
            }
        }
    }
}

// ---------------- cls hidden -------------------------------------------------
__global__ void cls_hidden_kernel(){
    int b = blockIdx.x >> 4, kk = blockIdx.x & 15;
    long col = (long)(b*NP1)*KNN + kk;
    for (int h = threadIdx.x; h < HID; h += 256){
        float v = fmaxf(g_w1q[(long)(b*NP1)*HID + h]*g_sA[h] + g_tA[h], 0.f);
        g_hid[col*HID + h] = __float2bfloat16_rn(v);
    }
}

// ---------------- finalize outputs ------------------------------------------
__global__ void finalize1_kernel(const float* __restrict__ x, float* __restrict__ out){
    int gid = blockIdx.x*256 + threadIdx.x;
    int n  = gid % NPTS;
    int ch = (gid / NPTS) % DIM;
    int b  = gid / (NPTS*DIM);
    out[gid] = g_y[((b*NP1) + (n+1))*DIM + ch] + x[gid];
}
__global__ void finalize2_kernel(float* __restrict__ out){
    int t = threadIdx.x;
    int b = t / DIM, ch = t % DIM;
    out[BB*DIM*NPTS + t] = g_y[(b*NP1)*DIM + ch];
}

// ---------------- launch -----------------------------------------------------
extern "C" void kernel_launch(void* const* d_in, const int* in_sizes, int n_in,
                              void* d_out, int out_size){
    const float* x        = (const float*)d_in[0];
    const float* pos      = (const float*)d_in[1];
    const float* W_start  = (const float*)d_in[2];
    const float* b_start  = (const float*)d_in[3];
    const float* W_key    = (const float*)d_in[4];
    const float* b_key    = (const float*)d_in[5];
    const float* W_query  = (const float*)d_in[6];
    const float* b_query  = (const float*)d_in[7];
    const float* W_value  = (const float*)d_in[8];
    const float* b_value  = (const float*)d_in[9];
    const float* pos_W1   = (const float*)d_in[10];
    const float* pos_b1   = (const float*)d_in[11];
    const float* pos_g    = (const float*)d_in[12];
    const float* pos_beta = (const float*)d_in[13];
    const float* pos_m    = (const float*)d_in[14];
    const float* pos_v    = (const float*)d_in[15];
    const float* pos_W2   = (const float*)d_in[16];
    const float* pos_b2   = (const float*)d_in[17];
    const float* attn_W1  = (const float*)d_in[18];
    const float* attn_b1  = (const float*)d_in[19];
    const float* attn_g   = (const float*)d_in[20];
    const float* attn_beta= (const float*)d_in[21];
    const float* attn_m   = (const float*)d_in[22];
    const float* attn_v   = (const float*)d_in[23];
    const float* attn_W2  = (const float*)d_in[24];
    const float* attn_b2  = (const float*)d_in[25];
    const float* W_end    = (const float*)d_in[26];
    const float* b_end    = (const float*)d_in[27];
    const float* pos_emb  = (const float*)d_in[28];
    const float* cls_tok  = (const float*)d_in[29];
    float* out = (float*)d_out;
    (void)attn_b2;

    float *pxT,*phx,*pv,*pph,*ppe,*pagg,*py,*pw1q,*pw1k;
    float *prWs,*prWq,*prWk,*prWv,*prP2,*prWe;
    __nv_bfloat16 *pphb,*phid,*pbWc,*pbW2,*pbW1,*pqb,*pkb;
    cudaGetSymbolAddress((void**)&pxT,  g_xT);
    cudaGetSymbolAddress((void**)&phx,  g_hx);
    cudaGetSymbolAddress((void**)&pqb,  g_qb);
    cudaGetSymbolAddress((void**)&pkb,  g_kb);
    cudaGetSymbolAddress((void**)&pv,   g_v);
    cudaGetSymbolAddress((void**)&pph,  g_ph);
    cudaGetSymbolAddress((void**)&pphb, g_phb);
    cudaGetSymbolAddress((void**)&ppe,  g_pe);
    cudaGetSymbolAddress((void**)&phid, g_hid);
    cudaGetSymbolAddress((void**)&pagg, g_agg);
    cudaGetSymbolAddress((void**)&py,   g_y);
    cudaGetSymbolAddress((void**)&pw1q, g_w1q);
    cudaGetSymbolAddress((void**)&pw1k, g_w1k);
    cudaGetSymbolAddress((void**)&pbWc, g_bWc);
    cudaGetSymbolAddress((void**)&pbW2, g_bW2);
    cudaGetSymbolAddress((void**)&pbW1, g_bW1);
    cudaGetSymbolAddress((void**)&prWs, g_rWs);
    cudaGetSymbolAddress((void**)&prWq, g_rWq);
    cudaGetSymbolAddress((void**)&prWk, g_rWk);
    cudaGetSymbolAddress((void**)&prWv, g_rWv);
    cudaGetSymbolAddress((void**)&prP2, g_rP2);
    cudaGetSymbolAddress((void**)&prWe, g_rWe);

    cudaFuncSetAttribute(gemm2<0>, cudaFuncAttributeMaxDynamicSharedMemorySize, GSMEM);
    cudaFuncSetAttribute(gemm2<1>, cudaFuncAttributeMaxDynamicSharedMemorySize, GSMEM);
    cudaFuncSetAttribute(gemm2<5>, cudaFuncAttributeMaxDynamicSharedMemorySize, GSMEM);
    cudaFuncSetAttribute(gemm2b<2>, cudaFuncAttributeMaxDynamicSharedMemorySize, GSMEMB);
    cudaFuncSetAttribute(gemm2b<3>, cudaFuncAttributeMaxDynamicSharedMemorySize, GSMEMB);
    cudaFuncSetAttribute(gemm2b<4>, cudaFuncAttributeMaxDynamicSharedMemorySize, GSMEMB);

    // prep + weight rounding/conversion
    transpose_x_kernel<<<dim3(NPTS/32, INCH/32, BB), dim3(32,32)>>>(x);
    prep_kernel<<<1,1024>>>(attn_g, attn_beta, attn_m, attn_v, attn_b1,
                            pos_g, pos_beta, pos_m, pos_v, pos_b1,
                            attn_W1, pos_b2);
    wc_kernel<<<HID, PHID>>>(attn_W1, pos_W2);
    cvtb2_kernel<<<(2*DIM*HID)/256, 256>>>(attn_W2, pbW2, attn_W1, pbW1, DIM*HID);
    {
        RCArgs rc;
        rc.s[0]=W_start; rc.d[0]=prWs;
        rc.s[1]=W_query; rc.d[1]=prWq;
        rc.s[2]=W_key;   rc.d[2]=prWk;
        rc.s[3]=W_value; rc.d[3]=prWv;
        rc.s[4]=pos_W2;  rc.d[4]=prP2;
        rc.s[5]=W_end;   rc.d[5]=prWe;
        int sz[6] = {DIM*INCH, DIM*DIM, DIM*DIM, DIM*DIM, DIM*PHID, INCH*DIM};
        int acc = 0;
        for (int k = 0; k < 6; k++){ acc += sz[k]; rc.end[k] = acc; }
        roundcpy_all_kernel<<<(acc + 255)/256, 256>>>(rc);
    }
    init_cls_kernel<<<BB, DIM>>>(cls_tok);
    knn_part_kernel<<<dim3(NPTS/256, BB, NCH), 256>>>(pos);
    knn_merge_kernel<<<dim3(NPTS/256, BB), 256>>>();

    // hx[1:] = W_start @ x + b
    gemm2<1><<<dim3(NPTS/128, DIM/128, BB), 256, GSMEM>>>(
        pxT, prWs, phx + DIM, NPTS, DIM, INCH, b_start,
        (long)NPTS*INCH, (long)NP1*DIM);

    // q,k (bf16 out) ; v (fp32, critical)
    gemm2<5><<<dim3((BB*NP1+127)/128, DIM/128, 1), 256, GSMEM>>>(
        phx, prWq, (float*)pqb, BB*NP1, DIM, DIM, b_query, 0, 0);
    gemm2<5><<<dim3((BB*NP1+127)/128, DIM/128, 1), 256, GSMEM>>>(
        phx, prWk, (float*)pkb, BB*NP1, DIM, DIM, b_key, 0, 0);
    gemm2<0><<<dim3((BB*NP1+127)/128, DIM/128, 1), 256, GSMEM>>>(
        phx, prWv, pv, BB*NP1, DIM, DIM, b_value, 0, 0);

    addpos_kernel<<<BB, DIM>>>(pos_emb);

    // w1q, w1k (bf16 cores, fp32 out)
    gemm2b<3><<<dim3((BB*NP1+127)/128, HID/128, 1), 256, GSMEMB>>>(
        pqb, pbW1, pw1q, BB*NP1, HID, DIM, 0, 0);
    gemm2b<3><<<dim3(NPTS/128, HID/128, BB), 256, GSMEMB>>>(
        pkb + DIM, pbW1, pw1k, NPTS, HID, DIM,
        (long)NP1*DIM, (long)NPTS*HID);

    // pos-MLP (tf32 — precision-critical)
    pos_hidden_kernel<<<dim3(NPTS, BB), 256>>>(pos, pos_W1);
    gemm2<0><<<dim3(NK/128, DIM/128, 1), 256, GSMEM>>>(
        pph, prP2, ppe, NK, DIM, PHID, pos_b2, 0, 0);

    // folded attn hidden (bf16 core)
    gemm2b<2><<<dim3(NK/128, HID/128, 1), 256, GSMEMB>>>(
        pphb, pbWc, nullptr, NK, HID, PHID, 0, 0);
    cls_hidden_kernel<<<BB*KNN, 256>>>();

    // logits + fused softmax/aggregate (bf16 core)
    gemm2b<4><<<dim3((NCOL+127)/128, DIM/128, 1), 256, GSMEMB>>>(
        phid, pbW2, nullptr, NCOL, DIM, HID, 0, 0);

    // y = W_end @ agg + b (tf32, critical)
    gemm2<0><<<dim3((BB*NP1+127)/128, DIM/128, 1), 256, GSMEM>>>(
        pagg, prWe, py, BB*NP1, DIM, DIM, b_end, 0, 0);

    finalize1_kernel<<<(BB*DIM*NPTS)/256, 256>>>(x, out);
    finalize2_kernel<<<1, BB*DIM>>>(out);
}

// round 14
// speedup vs baseline: 1.6407x; 1.0471x over previous
#include <cuda_runtime.h>
#include <cuda_bf16.h>
#include <math.h>
#include <stdint.h>

#define BB 4
#define INCH 256
#define NPTS 2048
#define NP1 2049
#define DIM 256
#define KNN 16
#define PHID 64
#define HID 1024
#define NCOL (BB*NP1*KNN)   /* 131136 */
#define NK   (BB*NPTS*KNN)  /* 131072 */
#define NCH  8
#define EPSV 1e-5f
#define GSMEM  81920        /* tf32: 4 stages * (128+128)*20 words * 4B */
#define GSMEMB 81920        /* bf16 k32: 4 stages * (128+128)*20 words * 4B */

// ---------------- scratch ----------------------------------------------------
__device__ float g_xT[BB*NPTS*INCH];
__device__ float g_hx[BB*NP1*DIM];
__device__ __nv_bfloat16 g_qb[BB*NP1*DIM];
__device__ __nv_bfloat16 g_kb[BB*NP1*DIM];
__device__ float g_v [BB*NP1*DIM];
__device__ int   g_idx[BB*NPTS*KNN];
__device__ float g_pd[BB*NPTS*NCH*KNN];
__device__ int   g_pi[BB*NPTS*NCH*KNN];
__device__ __nv_bfloat16 g_phb[NK*PHID];
__device__ float g_pe [(long)NK*DIM];
__device__ __nv_bfloat16 g_hid[(long)NCOL*HID];
__device__ float g_agg[BB*NP1*DIM];
__device__ float g_y  [BB*NP1*DIM];
__device__ __nv_bfloat16 g_w1q[BB*NP1*HID];
__device__ __nv_bfloat16 g_w1k[BB*NPTS*HID];
__device__ __nv_bfloat16 g_bWc[HID*PHID];
__device__ __nv_bfloat16 g_bW2[DIM*HID];
__device__ __nv_bfloat16 g_bW1[HID*DIM];
__device__ __nv_bfloat16 g_bP2[DIM*PHID];
__device__ float g_sA[HID], g_tA[HID], g_w1pb[HID];
__device__ float g_sP[PHID], g_tP[PHID];
__device__ float g_rWs[DIM*INCH];
__device__ float g_rWq[DIM*DIM];
__device__ float g_rWk[DIM*DIM];
__device__ float g_rWv[DIM*DIM];
__device__ float g_rWe[INCH*DIM];

// ---------------- helpers ----------------------------------------------------
__device__ __forceinline__ float rtf(float x){
    uint32_t r; asm("cvt.rna.tf32.f32 %0, %1;" : "=r"(r) : "f"(x));
    return __uint_as_float(r);
}
__device__ __forceinline__ void mma_tf32(float&c0,float&c1,float&c2,float&c3,
   uint32_t a0,uint32_t a1,uint32_t a2,uint32_t a3,uint32_t b0,uint32_t b1){
  asm volatile("mma.sync.aligned.m16n8k8.row.col.f32.tf32.tf32.f32 "
    "{%0,%1,%2,%3}, {%4,%5,%6,%7}, {%8,%9}, {%0,%1,%2,%3};\n"
    : "+f"(c0),"+f"(c1),"+f"(c2),"+f"(c3)
    : "r"(a0),"r"(a1),"r"(a2),"r"(a3),"r"(b0),"r"(b1));
}
__device__ __forceinline__ void mma_bf16(float&c0,float&c1,float&c2,float&c3,
   uint32_t a0,uint32_t a1,uint32_t a2,uint32_t a3,uint32_t b0,uint32_t b1){
  asm volatile("mma.sync.aligned.m16n8k16.row.col.f32.bf16.bf16.f32 "
    "{%0,%1,%2,%3}, {%4,%5,%6,%7}, {%8,%9}, {%0,%1,%2,%3};\n"
    : "+f"(c0),"+f"(c1),"+f"(c2),"+f"(c3)
    : "r"(a0),"r"(a1),"r"(a2),"r"(a3),"r"(b0),"r"(b1));
}
__device__ __forceinline__ void ldsm4(uint32_t&r0,uint32_t&r1,uint32_t&r2,uint32_t&r3,
                                      uint32_t addr){
  asm volatile("ldmatrix.sync.aligned.m8n8.x4.shared.b16 {%0,%1,%2,%3}, [%4];"
    : "=r"(r0),"=r"(r1),"=r"(r2),"=r"(r3) : "r"(addr));
}
__device__ __forceinline__ void cp16(uint32_t dst, const void* src){
    asm volatile("cp.async.cg.shared.global [%0], [%1], 16;" :: "r"(dst), "l"(src));
}
__device__ __forceinline__ void cpcommit(){ asm volatile("cp.async.commit_group;"); }
__device__ __forceinline__ void cpwait2(){ asm volatile("cp.async.wait_group 2;"); }
__device__ __forceinline__ void cpwait0(){ asm volatile("cp.async.wait_group 0;"); }

// ---------------- merged weight rounding ------------------------------------
struct RCArgs {
    const float* s[5];
    float* d[5];
    int end[5];
};
__global__ void roundcpy_all_kernel(RCArgs a){
    int i = blockIdx.x*256 + threadIdx.x;
    int seg = 0;
#pragma unroll
    for (int k = 0; k < 5; k++) if (i >= a.end[k]) seg = k+1;
    if (seg >= 5) return;
    int base = seg ? a.end[seg-1] : 0;
    a.d[seg][i-base] = rtf(a.s[seg][i-base]);
}
__global__ void cvtb3_kernel(const float* __restrict__ a, __nv_bfloat16* __restrict__ da,
                             const float* __restrict__ b, __nv_bfloat16* __restrict__ db,
                             const float* __restrict__ c, __nv_bfloat16* __restrict__ dc,
                             int n1, int n2){
    int i = blockIdx.x*256 + threadIdx.x;
    if (i < n1)            da[i]      = __float2bfloat16_rn(a[i]);
    else if (i < n1+n2)    db[i-n1]   = __float2bfloat16_rn(b[i-n1]);
    else                   dc[i-n1-n2]= __float2bfloat16_rn(c[i-n1-n2]);
}

// ---------------- small prep kernels ----------------------------------------
__global__ void transpose_x_kernel(const float* __restrict__ x){
    __shared__ float tile[32][33];
    int b = blockIdx.z;
    int i0 = blockIdx.y*32, n0 = blockIdx.x*32;
    int tx = threadIdx.x, ty = threadIdx.y;
    tile[ty][tx] = x[(b*INCH + (i0+ty))*NPTS + n0+tx];
    __syncthreads();
    g_xT[(b*NPTS + (n0+ty))*INCH + i0+tx] = rtf(tile[tx][ty]);
}

__global__ void prep_kernel(const float* __restrict__ ag, const float* __restrict__ abeta,
                            const float* __restrict__ am, const float* __restrict__ av,
                            const float* __restrict__ ab1,
                            const float* __restrict__ pg, const float* __restrict__ pbeta,
                            const float* __restrict__ pm, const float* __restrict__ pv,
                            const float* __restrict__ pb1,
                            const float* __restrict__ W1, const float* __restrict__ pb2){
    int t = threadIdx.x;
    if (t < HID){
        float s = ag[t] / sqrtf(av[t] + EPSV);
        g_sA[t] = s;
        g_tA[t] = abeta[t] - am[t]*s + ab1[t]*s;
        float acc = 0.f;
        for (int c = 0; c < DIM; c++) acc += W1[t*DIM+c]*pb2[c];
        g_w1pb[t] = acc;
    }
    if (t < PHID){
        float s = pg[t] / sqrtf(pv[t] + EPSV);
        g_sP[t] = s;
        g_tP[t] = pbeta[t] - pm[t]*s + pb1[t]*s;
    }
}

__global__ void wc_kernel(const float* __restrict__ W1, const float* __restrict__ W2p){
    int h = blockIdx.x, p = threadIdx.x;
    float s = 0.f;
    for (int c = 0; c < DIM; c++) s += W1[h*DIM+c]*W2p[c*PHID+p];
    g_bWc[h*PHID+p] = __float2bfloat16_rn(s);
}

__global__ void init_cls_kernel(const float* __restrict__ cls){
    g_hx[(blockIdx.x*NP1)*DIM + threadIdx.x] = rtf(cls[threadIdx.x]);
}

__global__ void addpos_kernel(const float* __restrict__ pos_emb){
    int b = blockIdx.x, c = threadIdx.x;
    int o = (b*NP1)*DIM + c;
    g_qb[o] = __float2bfloat16_rn(__bfloat162float(g_qb[o]) + pos_emb[c]);
    g_v[o] += pos_emb[c];
}

// ---------------- KNN (chunked) ---------------------------------------------
__global__ __launch_bounds__(256) void knn_part_kernel(const float* __restrict__ pos){
    __shared__ float sx[256], sy[256], sz[256];
    int b = blockIdx.y, ch = blockIdx.z;
    const float* pb = pos + (size_t)b*3*NPTS;
    int j0 = ch*256;
    int t = threadIdx.x;
    sx[t] = pb[j0+t]; sy[t] = pb[NPTS+j0+t]; sz[t] = pb[2*NPTS+j0+t];
    __syncthreads();
    int qi = blockIdx.x*256 + t;
    float qx = pb[qi], qy = pb[NPTS+qi], qz = pb[2*NPTS+qi];
    float bd[KNN]; int bi[KNN];
#pragma unroll
    for (int i = 0; i < KNN; i++){ bd[i] = 3.4e38f; bi[i] = 0; }
    float maxv = 3.4e38f; int maxp = 0;
    for (int j = 0; j < 256; j++){
        float dx = qx - sx[j], dy = qy - sy[j], dz = qz - sz[j];
        float d = dx*dx + dy*dy + dz*dz;
        if (d < maxv){
            bd[maxp] = d; bi[maxp] = j0 + j;
            maxv = bd[0]; maxp = 0;
#pragma unroll
            for (int i = 1; i < KNN; i++)
                if (bd[i] > maxv){ maxv = bd[i]; maxp = i; }
        }
    }
    long base = ((long)(b*NPTS + qi)*NCH + ch)*KNN;
#pragma unroll
    for (int i = 0; i < KNN; i++){ g_pd[base+i] = bd[i]; g_pi[base+i] = bi[i]; }
}

__global__ __launch_bounds__(256) void knn_merge_kernel(){
    int b = blockIdx.y;
    int qi = blockIdx.x*256 + threadIdx.x;
    long base = (long)(b*NPTS + qi)*NCH*KNN;
    float bd[KNN]; int bi[KNN];
#pragma unroll
    for (int i = 0; i < KNN; i++){ bd[i] = 3.4e38f; bi[i] = 0; }
    float maxv = 3.4e38f; int maxp = 0;
    for (int j = 0; j < NCH*KNN; j++){
        float d = g_pd[base+j];
        if (d < maxv){
            bd[maxp] = d; bi[maxp] = g_pi[base+j];
            maxv = bd[0]; maxp = 0;
#pragma unroll
            for (int i = 1; i < KNN; i++)
                if (bd[i] > maxv){ maxv = bd[i]; maxp = i; }
        }
    }
    int ob = (b*NPTS + qi)*KNN;
#pragma unroll
    for (int i = 0; i < KNN; i++) g_idx[ob+i] = bi[i];
}

// ---------------- pos-MLP hidden (bf16 out only) -----------------------------
__global__ __launch_bounds__(256) void pos_hidden_kernel(const float* __restrict__ pos,
                                                         const float* __restrict__ pw1){
    int b = blockIdx.y, n = blockIdx.x;
    __shared__ float prx[KNN], pry[KNN], prz[KNN];
    int t = threadIdx.x;
    const float* pb = pos + (size_t)b*3*NPTS;
    if (t < KNN){
        int m = g_idx[(b*NPTS+n)*KNN + t];
        prx[t] = pb[n]        - pb[m];
        pry[t] = pb[NPTS+n]   - pb[NPTS+m];
        prz[t] = pb[2*NPTS+n] - pb[2*NPTS+m];
    }
    __syncthreads();
    for (int e = t; e < KNN*PHID; e += 256){
        int k = e >> 6, hh = e & 63;
        float z = pw1[hh*3+0]*prx[k] + pw1[hh*3+1]*pry[k] + pw1[hh*3+2]*prz[k];
        z = z*g_sP[hh] + g_tP[hh];
        z = fmaxf(z, 0.f);
        g_phb[((long)(b*NPTS+n)*KNN + k)*PHID + hh] = __float2bfloat16_rn(z);
    }
}

// ---------------- tf32 GEMM: cp.async 4-stage, 1 barrier/iter, stride-20 smem
// EPI 0: C = acc + bias[n] ; EPI 1: C = rtf(acc + bias[n]) ; EPI 5: bf16 out
template<int EPI>
__global__ __launch_bounds__(256,2) void gemm2(const float* __restrict__ A,
        const float* __restrict__ Bw, float* __restrict__ C,
        int M, int N, int K, const float* __restrict__ bias,
        long strideAb, long strideCb){
    extern __shared__ __align__(16) float sm[];
    A += (long)blockIdx.z*strideAb;
    C += (long)blockIdx.z*strideCb;
    const int t = threadIdx.x, lane = t&31, w = t>>5;
    const int wm = w>>2, wn = w&3;
    const int m0 = blockIdx.x*128, n0 = blockIdx.y*128;
    const uint32_t smb = (uint32_t)__cvta_generic_to_shared(sm);
    float acc[4][4][4];
#pragma unroll
    for (int i=0;i<4;i++)
#pragma unroll
      for (int j=0;j<4;j++)
#pragma unroll
        for (int c=0;c<4;c++) acc[i][j][c] = 0.f;

    const int nIter = K >> 4;
    auto prefetch = [&](int st, int kt){
#pragma unroll
        for (int l=0;l<2;l++){
            int g = t + (l<<8);
            int row = g>>2, kq = (g&3)<<2;
            int arow = m0 + row; if (arow >= M) arow = M - 1;
            uint32_t d = smb + (uint32_t)((st*5120 + row*20 + kq)<<2);
            cp16(d, A + (long)arow*K + (kt<<4) + kq);
            uint32_t d2 = smb + (uint32_t)((st*5120 + 2560 + row*20 + kq)<<2);
            cp16(d2, Bw + (long)(n0+row)*K + (kt<<4) + kq);
        }
        cpcommit();
    };
    prefetch(0, 0);
    prefetch(1, 1);
    prefetch(2, 2);

    for (int it = 0; it < nIter; ++it){
        if (it + 3 < nIter) cpwait2();
        else                cpwait0();
        __syncthreads();
        if (it+3 < nIter) prefetch((it+3)&3, it+3); else cpcommit();
        const float* sA = sm + (it&3)*5120;
        const float* sB = sA + 2560;
#pragma unroll
        for (int k8=0;k8<2;k8++){
            int kb = k8*8 + (lane&3);
            uint32_t af[4][4]; uint32_t bf[4][2];
#pragma unroll
            for (int i=0;i<4;i++){
                const float* p = sA + (wm*64 + i*16 + (lane>>2))*20 + kb;
                af[i][0]=__float_as_uint(p[0]);
                af[i][1]=__float_as_uint(p[160]);
                af[i][2]=__float_as_uint(p[4]);
                af[i][3]=__float_as_uint(p[164]);
            }
#pragma unroll
            for (int j=0;j<4;j++){
                const float* p = sB + (wn*32 + j*8 + (lane>>2))*20 + kb;
                bf[j][0]=__float_as_uint(p[0]);
                bf[j][1]=__float_as_uint(p[4]);
            }
#pragma unroll
            for (int i=0;i<4;i++)
#pragma unroll
                for (int j=0;j<4;j++)
                    mma_tf32(acc[i][j][0],acc[i][j][1],acc[i][j][2],acc[i][j][3],
                             af[i][0],af[i][1],af[i][2],af[i][3], bf[j][0],bf[j][1]);
        }
    }

    const int r0 = lane >> 2, cq = (lane & 3) << 1;
#pragma unroll
    for (int i=0;i<4;i++){
#pragma unroll
        for (int half=0; half<2; half++){
            int m = m0 + wm*64 + i*16 + r0 + half*8;
            if (m >= M) continue;
            if (EPI == 5){
                __nv_bfloat16* cb = (__nv_bfloat16*)C + (long)m*N;
#pragma unroll
                for (int j=0;j<4;j++){
                    int n = n0 + wn*32 + j*8 + cq;
                    float2 bv = *(const float2*)&bias[n];
                    __nv_bfloat162 o2 = __floats2bfloat162_rn(
                        acc[i][j][half*2+0] + bv.x, acc[i][j][half*2+1] + bv.y);
                    *(__nv_bfloat162*)&cb[n] = o2;
                }
            } else {
                float* crow = C + (long)m*N;
#pragma unroll
                for (int j=0;j<4;j++){
                    int n = n0 + wn*32 + j*8 + cq;
                    float2 o;
                    if (EPI == 0){
                        float2 bv = *(const float2*)&bias[n];
                        o.x = acc[i][j][half*2+0] + bv.x;
                        o.y = acc[i][j][half*2+1] + bv.y;
                    } else if (EPI == 1){
                        float2 bv = *(const float2*)&bias[n];
                        o.x = rtf(acc[i][j][half*2+0] + bv.x);
                        o.y = rtf(acc[i][j][half*2+1] + bv.y);
                    } else {
                        o.x = acc[i][j][half*2+0];
                        o.y = acc[i][j][half*2+1];
                    }
                    *(float2*)&crow[n] = o;
                }
            }
        }
    }
}

// ---------------- bf16 GEMM: m16n8k16 x2 per stage (k32), ldmatrix, 4-stage --
// EPI 2: folded attn-hidden -> g_hid (bf16)
// EPI 4: softmax+agg -> g_agg
// EPI 6: bf16 C = acc
// EPI 7: fp32 C = acc + bias[n]
template<int EPI>
__global__ __launch_bounds__(256,2) void gemm2b(const __nv_bfloat16* __restrict__ A,
        const __nv_bfloat16* __restrict__ Bw, float* __restrict__ C,
        int M, int N, int K, const float* __restrict__ bias,
        long strideAb, long strideCb){
    extern __shared__ __align__(16) uint32_t smw[];
    A += (long)blockIdx.z*strideAb;
    C += (long)blockIdx.z*strideCb;
    const int t = threadIdx.x, lane = t&31, w = t>>5;
    const int wm = w>>2, wn = w&3;
    const int m0 = blockIdx.x*128, n0 = blockIdx.y*128;
    const uint32_t smb = (uint32_t)__cvta_generic_to_shared(smw);
    float acc[4][4][4];
#pragma unroll
    for (int i=0;i<4;i++)
#pragma unroll
      for (int j=0;j<4;j++)
#pragma unroll
        for (int c=0;c<4;c++) acc[i][j][c] = 0.f;

    uint32_t aoff[4];
#pragma unroll
    for (int i=0;i<4;i++){
        int row = wm*64 + i*16 + (((lane>>3)&1)<<3) + (lane&7);
        aoff[i] = (uint32_t)(row*20 + ((lane>>4)<<2));
    }
    uint32_t boff[2];
#pragma unroll
    for (int jj=0;jj<2;jj++){
        int row = wn*32 + jj*16 + ((lane>>4)<<3) + (lane&7);
        boff[jj] = (uint32_t)(2560 + row*20 + (((lane>>3)&1)<<2));
    }

    const int nIter = K >> 5;                  // k-step = 32 halves
    auto prefetch = [&](int st, int kt){
        if (kt < nIter){
#pragma unroll
            for (int l=0;l<4;l++){
                int g = t + (l<<8);            // 0..1023
                int row = g>>2;                // 0..255
                int kw  = (g&3)<<2;            // word offset 0,4,8,12
                int kh  = (kt<<5) + ((g&3)<<3);// half offset
                if (row < 128){
                    int arow = m0 + row; if (arow >= M) arow = M - 1;
                    uint32_t d = smb + (uint32_t)((st*5120 + row*20 + kw)<<2);
                    cp16(d, A + (long)arow*K + kh);
                } else {
                    int brow = row - 128;
                    uint32_t d = smb + (uint32_t)((st*5120 + 2560 + brow*20 + kw)<<2);
                    cp16(d, Bw + (long)(n0+brow)*K + kh);
                }
            }
        }
        cpcommit();
    };
    prefetch(0, 0);
    prefetch(1, 1);
    prefetch(2, 2);

    for (int it = 0; it < nIter; ++it){
        if (it + 3 < nIter) cpwait2();
        else                cpwait0();
        __syncthreads();
        prefetch((it+3)&3, it+3);
        uint32_t sb = smb + (uint32_t)(((it&3)*5120)<<2);
#pragma unroll
        for (int s=0;s<2;s++){
            uint32_t so = sb + (uint32_t)(s*32);   // +8 words
            uint32_t af[4][4]; uint32_t bfr[2][4];
#pragma unroll
            for (int i=0;i<4;i++)
                ldsm4(af[i][0],af[i][1],af[i][2],af[i][3], so + (aoff[i]<<2));
#pragma unroll
            for (int jj=0;jj<2;jj++)
                ldsm4(bfr[jj][0],bfr[jj][1],bfr[jj][2],bfr[jj][3], so + (boff[jj]<<2));
#pragma unroll
            for (int i=0;i<4;i++)
#pragma unroll
                for (int j=0;j<4;j++)
                    mma_bf16(acc[i][j][0],acc[i][j][1],acc[i][j][2],acc[i][j][3],
                             af[i][0],af[i][1],af[i][2],af[i][3],
                             bfr[j>>1][(j&1)*2], bfr[j>>1][(j&1)*2+1]);
        }
    }

    const int r0 = lane >> 2, cq = (lane & 3) << 1;
    if (EPI == 4){
#pragma unroll
        for (int i=0;i<4;i++){
            int mrow = m0 + wm*64 + i*16;
            if (mrow >= M) continue;
            int colidx = mrow >> 4;            // b*NP1 + nn
            int b  = colidx / NP1;
            int nn = colidx - b*NP1;
            long pebase = (nn > 0) ? (long)((b*NPTS + nn-1)*KNN)*DIM : 0;
            int kk0 = r0;
#pragma unroll
            for (int j=0;j<4;j++){
                int c0 = n0 + wn*32 + j*8 + cq;
                float outv[2];
#pragma unroll
                for (int q=0;q<2;q++){
                    float l0 = acc[i][j][q], l1 = acc[i][j][2+q];
                    float mx = fmaxf(l0, l1);
                    mx = fmaxf(mx, __shfl_xor_sync(0xffffffffu, mx, 4));
                    mx = fmaxf(mx, __shfl_xor_sync(0xffffffffu, mx, 8));
                    mx = fmaxf(mx, __shfl_xor_sync(0xffffffffu, mx, 16));
                    float e0 = expf(l0 - mx), e1 = expf(l1 - mx);
                    float pv0 = 0.f, pv1 = 0.f;
                    if (nn > 0){
                        pv0 = g_pe[pebase + (long)kk0*DIM + c0 + q];
                        pv1 = g_pe[pebase + (long)(kk0+8)*DIM + c0 + q];
                    }
                    float s  = e0 + e1;
                    float ts = e0*pv0 + e1*pv1;
                    s  += __shfl_xor_sync(0xffffffffu, s, 4);
                    ts += __shfl_xor_sync(0xffffffffu, ts, 4);
                    s  += __shfl_xor_sync(0xffffffffu, s, 8);
                    ts += __shfl_xor_sync(0xffffffffu, ts, 8);
                    s  += __shfl_xor_sync(0xffffffffu, s, 16);
                    ts += __shfl_xor_sync(0xffffffffu, ts, 16);
                    float vv = g_v[(long)colidx*DIM + c0 + q];
                    outv[q] = rtf(vv + ts / s);
                }
                if (r0 == 0){
                    float2 o = make_float2(outv[0], outv[1]);
                    *(float2*)&g_agg[(long)colidx*DIM + c0] = o;
                }
            }
        }
        return;
    }
#pragma unroll
    for (int i=0;i<4;i++){
#pragma unroll
        for (int half=0; half<2; half++){
            int m = m0 + wm*64 + i*16 + r0 + half*8;
            if (m >= M) continue;
            if (EPI == 2){
                int b  = m >> 15;
                int n  = (m >> 4) & (NPTS-1);
                int kk = m & 15;
                int midx = g_idx[((b*NPTS)+n)*KNN + kk];
                const __nv_bfloat16* wq = g_w1q + (long)(b*NP1 + n + 1)*HID;
                const __nv_bfloat16* wk = g_w1k + (long)(b*NPTS + midx)*HID;
                __nv_bfloat16* dst = g_hid + (long)((b*NP1 + n + 1)*KNN + kk)*HID;
#pragma unroll
                for (int j=0;j<4;j++){
                    int h = n0 + wn*32 + j*8 + cq;
                    float2 q2 = __bfloat1622float2(*(const __nv_bfloat162*)&wq[h]);
                    float2 k2 = __bfloat1622float2(*(const __nv_bfloat162*)&wk[h]);
                    float2 p2 = *(const float2*)&g_w1pb[h];
                    float2 s2 = *(const float2*)&g_sA[h];
                    float2 t2 = *(const float2*)&g_tA[h];
                    float ox = fmaxf((acc[i][j][half*2+0] + q2.x - k2.x + p2.x)*s2.x + t2.x, 0.f);
                    float oy = fmaxf((acc[i][j][half*2+1] + q2.y - k2.y + p2.y)*s2.y + t2.y, 0.f);
                    __nv_bfloat162 o2 = __floats2bfloat162_rn(ox, oy);
                    *(__nv_bfloat162*)&dst[h] = o2;
                }
            } else if (EPI == 6){          // bf16 C = acc
                __nv_bfloat16* cb = (__nv_bfloat16*)C + (long)m*N;
#pragma unroll
                for (int j=0;j<4;j++){
                    int n = n0 + wn*32 + j*8 + cq;
                    __nv_bfloat162 o2 = __floats2bfloat162_rn(
                        acc[i][j][half*2+0], acc[i][j][half*2+1]);
                    *(__nv_bfloat162*)&cb[n] = o2;
                }
            } else {                      // EPI 7: fp32 C = acc + bias
                float* crow = C + (long)m*N;
#pragma unroll
                for (int j=0;j<4;j++){
                    int n = n0 + wn*32 + j*8 + cq;
                    float2 bv = *(const float2*)&bias[n];
                    float2 o = make_float2(acc[i][j][half*2+0] + bv.x,
                                           acc[i][j][half*2+1] + bv.y);
                    *(float2*)&crow[n] = o;
                }
            }
        }
    }
}

// ---------------- cls hidden -------------------------------------------------
__global__ void cls_hidden_kernel(){
    int b = blockIdx.x >> 4, kk = blockIdx.x & 15;
    long col = (long)(b*NP1)*KNN + kk;
    for (int h = threadIdx.x; h < HID; h += 256){
        float wq = __bfloat162float(g_w1q[(long)(b*NP1)*HID + h]);
        float v = fmaxf(wq*g_sA[h] + g_tA[h], 0.f);
        g_hid[col*HID + h] = __float2bfloat16_rn(v);
    }
}

// ---------------- finalize outputs ------------------------------------------
__global__ void finalize1_kernel(const float* __restrict__ x, float* __restrict__ out){
    int gid = blockIdx.x*256 + threadIdx.x;
    int n  = gid % NPTS;
    int ch = (gid / NPTS) % DIM;
    int b  = gid / (NPTS*DIM);
    out[gid] = g_y[((b*NP1) + (n+1))*DIM + ch] + x[gid];
}
__global__ void finalize2_kernel(float* __restrict__ out){
    int t = threadIdx.x;
    int b = t / DIM, ch = t % DIM;
    out[BB*DIM*NPTS + t] = g_y[(b*NP1)*DIM + ch];
}

// ---------------- launch -----------------------------------------------------
extern "C" void kernel_launch(void* const* d_in, const int* in_sizes, int n_in,
                              void* d_out, int out_size){
    const float* x        = (const float*)d_in[0];
    const float* pos      = (const float*)d_in[1];
    const float* W_start  = (const float*)d_in[2];
    const float* b_start  = (const float*)d_in[3];
    const float* W_key    = (const float*)d_in[4];
    const float* b_key    = (const float*)d_in[5];
    const float* W_query  = (const float*)d_in[6];
    const float* b_query  = (const float*)d_in[7];
    const float* W_value  = (const float*)d_in[8];
    const float* b_value  = (const float*)d_in[9];
    const float* pos_W1   = (const float*)d_in[10];
    const float* pos_b1   = (const float*)d_in[11];
    const float* pos_g    = (const float*)d_in[12];
    const float* pos_beta = (const float*)d_in[13];
    const float* pos_m    = (const float*)d_in[14];
    const float* pos_v    = (const float*)d_in[15];
    const float* pos_W2   = (const float*)d_in[16];
    const float* pos_b2   = (const float*)d_in[17];
    const float* attn_W1  = (const float*)d_in[18];
    const float* attn_b1  = (const float*)d_in[19];
    const float* attn_g   = (const float*)d_in[20];
    const float* attn_beta= (const float*)d_in[21];
    const float* attn_m   = (const float*)d_in[22];
    const float* attn_v   = (const float*)d_in[23];
    const float* attn_W2  = (const float*)d_in[24];
    const float* attn_b2  = (const float*)d_in[25];
    const float* W_end    = (const float*)d_in[26];
    const float* b_end    = (const float*)d_in[27];
    const float* pos_emb  = (const float*)d_in[28];
    const float* cls_tok  = (const float*)d_in[29];
    float* out = (float*)d_out;
    (void)attn_b2;

    float *pxT,*phx,*pv,*ppe,*pagg,*py;
    float *prWs,*prWq,*prWk,*prWv,*prWe;
    __nv_bfloat16 *pphb,*phid,*pbWc,*pbW2,*pbW1,*pbP2,*pqb,*pkb,*pw1q,*pw1k;
    cudaGetSymbolAddress((void**)&pxT,  g_xT);
    cudaGetSymbolAddress((void**)&phx,  g_hx);
    cudaGetSymbolAddress((void**)&pqb,  g_qb);
    cudaGetSymbolAddress((void**)&pkb,  g_kb);
    cudaGetSymbolAddress((void**)&pv,   g_v);
    cudaGetSymbolAddress((void**)&pphb, g_phb);
    cudaGetSymbolAddress((void**)&ppe,  g_pe);
    cudaGetSymbolAddress((void**)&phid, g_hid);
    cudaGetSymbolAddress((void**)&pagg, g_agg);
    cudaGetSymbolAddress((void**)&py,   g_y);
    cudaGetSymbolAddress((void**)&pw1q, g_w1q);
    cudaGetSymbolAddress((void**)&pw1k, g_w1k);
    cudaGetSymbolAddress((void**)&pbWc, g_bWc);
    cudaGetSymbolAddress((void**)&pbW2, g_bW2);
    cudaGetSymbolAddress((void**)&pbW1, g_bW1);
    cudaGetSymbolAddress((void**)&pbP2, g_bP2);
    cudaGetSymbolAddress((void**)&prWs, g_rWs);
    cudaGetSymbolAddress((void**)&prWq, g_rWq);
    cudaGetSymbolAddress((void**)&prWk, g_rWk);
    cudaGetSymbolAddress((void**)&prWv, g_rWv);
    cudaGetSymbolAddress((void**)&prWe, g_rWe);

    cudaFuncSetAttribute(gemm2<0>, cudaFuncAttributeMaxDynamicSharedMemorySize, GSMEM);
    cudaFuncSetAttribute(gemm2<1>, cudaFuncAttributeMaxDynamicSharedMemorySize, GSMEM);
    cudaFuncSetAttribute(gemm2<5>, cudaFuncAttributeMaxDynamicSharedMemorySize, GSMEM);
    cudaFuncSetAttribute(gemm2b<2>, cudaFuncAttributeMaxDynamicSharedMemorySize, GSMEMB);
    cudaFuncSetAttribute(gemm2b<4>, cudaFuncAttributeMaxDynamicSharedMemorySize, GSMEMB);
    cudaFuncSetAttribute(gemm2b<6>, cudaFuncAttributeMaxDynamicSharedMemorySize, GSMEMB);
    cudaFuncSetAttribute(gemm2b<7>, cudaFuncAttributeMaxDynamicSharedMemorySize, GSMEMB);

    // prep + weight rounding/conversion
    transpose_x_kernel<<<dim3(NPTS/32, INCH/32, BB), dim3(32,32)>>>(x);
    prep_kernel<<<1,1024>>>(attn_g, attn_beta, attn_m, attn_v, attn_b1,
                            pos_g, pos_beta, pos_m, pos_v, pos_b1,
                            attn_W1, pos_b2);
    wc_kernel<<<HID, PHID>>>(attn_W1, pos_W2);
    cvtb3_kernel<<<(2*DIM*HID + DIM*PHID + 255)/256, 256>>>(
        attn_W2, pbW2, attn_W1, pbW1, pos_W2, pbP2, DIM*HID, HID*DIM);
    {
        RCArgs rc;
        rc.s[0]=W_start; rc.d[0]=prWs;
        rc.s[1]=W_query; rc.d[1]=prWq;
        rc.s[2]=W_key;   rc.d[2]=prWk;
        rc.s[3]=W_value; rc.d[3]=prWv;
        rc.s[4]=W_end;   rc.d[4]=prWe;
        int sz[5] = {DIM*INCH, DIM*DIM, DIM*DIM, DIM*DIM, INCH*DIM};
        int acc = 0;
        for (int k = 0; k < 5; k++){ acc += sz[k]; rc.end[k] = acc; }
        roundcpy_all_kernel<<<(acc + 255)/256, 256>>>(rc);
    }
    init_cls_kernel<<<BB, DIM>>>(cls_tok);
    knn_part_kernel<<<dim3(NPTS/256, BB, NCH), 256>>>(pos);
    knn_merge_kernel<<<dim3(NPTS/256, BB), 256>>>();

    // hx[1:] = W_start @ x + b
    gemm2<1><<<dim3(NPTS/128, DIM/128, BB), 256, GSMEM>>>(
        pxT, prWs, phx + DIM, NPTS, DIM, INCH, b_start,
        (long)NPTS*INCH, (long)NP1*DIM);

    // q,k (bf16 out) ; v (fp32, critical)
    gemm2<5><<<dim3((BB*NP1+127)/128, DIM/128, 1), 256, GSMEM>>>(
        phx, prWq, (float*)pqb, BB*NP1, DIM, DIM, b_query, 0, 0);
    gemm2<5><<<dim3((BB*NP1+127)/128, DIM/128, 1), 256, GSMEM>>>(
        phx, prWk, (float*)pkb, BB*NP1, DIM, DIM, b_key, 0, 0);
    gemm2<0><<<dim3((BB*NP1+127)/128, DIM/128, 1), 256, GSMEM>>>(
        phx, prWv, pv, BB*NP1, DIM, DIM, b_value, 0, 0);

    addpos_kernel<<<BB, DIM>>>(pos_emb);

    // w1q, w1k (bf16 cores, bf16 out)
    gemm2b<6><<<dim3((BB*NP1+127)/128, HID/128, 1), 256, GSMEMB>>>(
        pqb, pbW1, (float*)pw1q, BB*NP1, HID, DIM, nullptr, 0, 0);
    gemm2b<6><<<dim3(NPTS/128, HID/128, BB), 256, GSMEMB>>>(
        pkb + DIM, pbW1, (float*)pw1k, NPTS, HID, DIM, nullptr,
        (long)NP1*DIM, (long)NPTS*HID/2);

    // pos-MLP (bf16 core, fp32 out + bias)
    pos_hidden_kernel<<<dim3(NPTS, BB), 256>>>(pos, pos_W1);
    gemm2b<7><<<dim3(NK/128, DIM/128, 1), 256, GSMEMB>>>(
        pphb, pbP2, ppe, NK, DIM, PHID, pos_b2, 0, 0);

    // folded attn hidden (bf16 core)
    gemm2b<2><<<dim3(NK/128, HID/128, 1), 256, GSMEMB>>>(
        pphb, pbWc, nullptr, NK, HID, PHID, nullptr, 0, 0);
    cls_hidden_kernel<<<BB*KNN, 256>>>();

    // logits + fused softmax/aggregate (bf16 core)
    gemm2b<4><<<dim3((NCOL+127)/128, DIM/128, 1), 256, GSMEMB>>>(
        phid, pbW2, nullptr, NCOL, DIM, HID, nullptr, 0, 0);

    // y = W_end @ agg + b (tf32, critical)
    gemm2<0><<<dim3((BB*NP1+127)/128, DIM/128, 1), 256, GSMEM>>>(
        pagg, prWe, py, BB*NP1, DIM, DIM, b_end, 0, 0);

    finalize1_kernel<<<(BB*DIM*NPTS)/256, 256>>>(x, out);
    finalize2_kernel<<<1, BB*DIM>>>(out);
}